// round 10
// baseline (speedup 1.0000x reference)
#include <cuda_runtime.h>

// ---------------- problem constants ----------------
#define BATCH  32
#define NTOK   576
#define DIMC   768
#define HEADS  12
#define HD     64
#define LTN    64
#define LSN    256
#define KEEPN  180
#define REMN   76
#define NKEEP  424
#define HID    3072

#define M1     (BATCH*NTOK)   // 18432
#define M2     (BATCH*NKEEP)  // 13568

// output layout (flattened tuple, float32, reference order)
#define GIT_OFF      10420224
#define KEEP_PS_OFF  10422272
#define KEEP_S_OFF   10428032
#define REM_PS_OFF   10433792
#define REM_S_OFF    10436224
#define ATTN_OFF     10438656

// ---------------- device scratch ----------------
__device__ __align__(16) float g_h  [M1*DIMC];
__device__ __align__(16) float g_hlo[M1*DIMC];
__device__ __align__(16) float g_q  [M1*DIMC];
__device__ __align__(16) float g_k  [M1*DIMC];
__device__ __align__(16) float g_v  [M1*DIMC];
__device__ __align__(16) float g_xa [M1*DIMC];
__device__ __align__(16) float g_x1 [M1*DIMC];
__device__ __align__(16) float g_xn [M2*DIMC];
__device__ __align__(16) float g_hn [M2*DIMC];
__device__ __align__(16) float g_act[(size_t)M2*HID];
__device__ __align__(16) float g_kffh[M1*DIMC];
__device__ __align__(16) float g_kffl[M1*DIMC];
__device__ __align__(16) float g_qffh[BATCH*HEADS*LTN*HD];
__device__ __align__(16) float g_qffl[BATCH*HEADS*LTN*HD];
__device__ __align__(16) double g_L[(size_t)BATCH*HEADS*LTN*NTOK];
__device__ __align__(16) double g_spartd [(size_t)BATCH*HEADS*512];
__device__ __align__(16) float  g_spartf2[(size_t)BATCH*HEADS*512];
__device__ __align__(16) float  g_spartf1[(size_t)BATCH*HEADS*512];
__device__ __align__(16) double g_dscore[BATCH*2*LSN];
__device__ __align__(16) float  g_sv1[BATCH*2*LSN];
__device__ __align__(16) float  g_sv2[BATCH*2*LSN];
__device__ __align__(16) int    g_order[64*LSN];
__device__ __align__(16) int    g_top_ps[BATCH*LSN];
__device__ __align__(16) int    g_top_s [BATCH*LSN];

// ---------------- ff (double-single) helpers ----------------
__device__ __forceinline__ void ts2(float a, float b, float& s, float& e) {
    s = a + b;
    float z = s - a;
    e = (a - (s - z)) + (b - z);
}
__device__ __forceinline__ void ffacc_f(float& h, float& l, float v) {
    float s, e; ts2(h, v, s, e); h = s; l += e;
}
__device__ __forceinline__ void ffacc_p(float& h, float& l, float a, float b) {
    float p = a * b;
    float e = fmaf(a, b, -p);
    float s, er; ts2(h, p, s, er);
    h = s; l += er + e;
}
__device__ __forceinline__ void ffadd(float& h, float& l, float bh2, float bl2) {
    float s, e; ts2(h, bh2, s, e);
    e += l + bl2;
    h = s + e;
    l = e - (h - s);
}
__device__ __forceinline__ void ffacc_pp(float& ah, float& al,
                                         float qh, float ql, float kh, float kl) {
    float p = qh * kh;
    float e = fmaf(qh, kh, -p);
    e = fmaf(qh, kl, e);
    e = fmaf(ql, kh, e);
    float s, er; ts2(ah, p, s, er);
    ah = s; al += er + e;
}

__device__ __forceinline__ float gelu_exact(float v) {
    return 0.5f * v * (1.0f + erff(v * 0.70710678118654752f));
}

// ---------------- LN1 in ff: writes h_hi (main path) + h_lo ----------------
__global__ __launch_bounds__(256)
void ln_ff_kernel(const float* __restrict__ X, const float* __restrict__ w,
                  const float* __restrict__ bia, float* __restrict__ Yh,
                  float* __restrict__ Yl)
{
    __shared__ float sh[8], slo[8], sqh[8], sql[8];
    __shared__ double sm_mean, sm_inv;
    int row = blockIdx.x;
    const float* xr = X + (size_t)row * DIMC;
    int t = threadIdx.x;
    float x0 = xr[t], x1 = xr[t+256], x2 = xr[t+512];
    float sH = 0.f, sL = 0.f, qH = 0.f, qL = 0.f;
    ffacc_f(sH, sL, x0); ffacc_f(sH, sL, x1); ffacc_f(sH, sL, x2);
    ffacc_p(qH, qL, x0, x0); ffacc_p(qH, qL, x1, x1); ffacc_p(qH, qL, x2, x2);
    int lane = t & 31, warp = t >> 5;
    #pragma unroll
    for (int o = 16; o; o >>= 1) {
        float oh = __shfl_xor_sync(0xffffffffu, sH, o);
        float ol = __shfl_xor_sync(0xffffffffu, sL, o);
        ffadd(sH, sL, oh, ol);
        oh = __shfl_xor_sync(0xffffffffu, qH, o);
        ol = __shfl_xor_sync(0xffffffffu, qL, o);
        ffadd(qH, qL, oh, ol);
    }
    if (lane == 0) { sh[warp]=sH; slo[warp]=sL; sqh[warp]=qH; sql[warp]=qL; }
    __syncthreads();
    if (t == 0) {
        double ms = 0.0, mq = 0.0;
        #pragma unroll
        for (int i = 0; i < 8; i++) {
            ms += (double)sh[i] + (double)slo[i];
            mq += (double)sqh[i] + (double)sql[i];
        }
        double mean = ms / 768.0;
        double var  = mq / 768.0 - mean*mean;
        sm_mean = mean;
        sm_inv  = 1.0 / sqrt(var + 1e-5);
    }
    __syncthreads();
    double mean = sm_mean, inv = sm_inv;
    float mh = (float)mean, ml = (float)(mean - (double)mh);
    float ih = (float)inv,  il = (float)(inv  - (double)ih);
    #pragma unroll
    for (int rep = 0; rep < 3; rep++) {
        int c = t + rep*256;
        float xv = (rep==0)?x0:((rep==1)?x1:x2);
        float wv = w[c], bv = bia[c];
        float th, tl; ts2(xv, -mh, th, tl); tl -= ml;
        float ph = th * ih;
        float pl = fmaf(th, ih, -ph);
        pl += th*il + tl*ih;
        float uh = ph * wv;
        float ul = fmaf(ph, wv, -uh);
        ul = fmaf(pl, wv, ul);
        float rh, rl; ts2(uh, bv, rh, rl); rl += ul;
        float oh = rh + rl;
        float ol = rl - (oh - rh);
        Yh[(size_t)row*DIMC + c] = oh;
        Yl[(size_t)row*DIMC + c] = ol;
    }
}

// ---------------- ff GEMM ----------------
#define FFM_K 0
#define FFM_Q 1

template<int MODE>
__global__ __launch_bounds__(256)
void ffgemm_kernel(const float* __restrict__ Ah, const float* __restrict__ Al,
                   const float* __restrict__ W, const float* __restrict__ bias,
                   float* __restrict__ Ch, float* __restrict__ Cl)
{
    __shared__ float Ash[16*68], Asl[16*68], Ws[16*68];
    const int tid = threadIdx.x;
    const int tx = tid & 15, ty = tid >> 4;
    const int m0 = blockIdx.y * 64;
    const int n0 = blockIdx.x * 64;
    const int wrow0 = (MODE == FFM_K) ? 768 : 0;
    float aH[4][4], aL[4][4];
    #pragma unroll
    for (int i = 0; i < 4; i++)
        #pragma unroll
        for (int j = 0; j < 4; j++) { aH[i][j] = 0.f; aL[i][j] = 0.f; }

    const int lrow = tid >> 2;
    const int lc4  = (tid & 3) * 4;
    int arow;
    if (MODE == FFM_Q) { int m = m0 + lrow; arow = (m >> 6)*NTOK + (m & 63); }
    else               arow = m0 + lrow;

    for (int k0 = 0; k0 < DIMC; k0 += 16) {
        float4 vh = *(const float4*)(Ah + (size_t)arow*DIMC + k0 + lc4);
        float4 vl = *(const float4*)(Al + (size_t)arow*DIMC + k0 + lc4);
        float4 vw = *(const float4*)(W + (size_t)(wrow0 + n0 + lrow)*DIMC + k0 + lc4);
        Ash[(lc4+0)*68+lrow]=vh.x; Ash[(lc4+1)*68+lrow]=vh.y; Ash[(lc4+2)*68+lrow]=vh.z; Ash[(lc4+3)*68+lrow]=vh.w;
        Asl[(lc4+0)*68+lrow]=vl.x; Asl[(lc4+1)*68+lrow]=vl.y; Asl[(lc4+2)*68+lrow]=vl.z; Asl[(lc4+3)*68+lrow]=vl.w;
        Ws [(lc4+0)*68+lrow]=vw.x; Ws [(lc4+1)*68+lrow]=vw.y; Ws [(lc4+2)*68+lrow]=vw.z; Ws [(lc4+3)*68+lrow]=vw.w;
        __syncthreads();
        #pragma unroll
        for (int kk = 0; kk < 16; kk++) {
            float4 ah4 = *(const float4*)&Ash[kk*68 + ty*4];
            float4 al4 = *(const float4*)&Asl[kk*68 + ty*4];
            float4 w4  = *(const float4*)&Ws [kk*68 + tx*4];
            float ahv[4] = {ah4.x, ah4.y, ah4.z, ah4.w};
            float alv[4] = {al4.x, al4.y, al4.z, al4.w};
            float wv [4] = {w4.x,  w4.y,  w4.z,  w4.w};
            #pragma unroll
            for (int i = 0; i < 4; i++)
                #pragma unroll
                for (int j = 0; j < 4; j++) {
                    float p = ahv[i] * wv[j];
                    float e = fmaf(ahv[i], wv[j], -p);
                    e = fmaf(alv[i], wv[j], e);
                    float s, er; ts2(aH[i][j], p, s, er);
                    aH[i][j] = s; aL[i][j] += er + e;
                }
        }
        __syncthreads();
    }

    #pragma unroll
    for (int i = 0; i < 4; i++) {
        int m = m0 + ty*4 + i;
        float4 rh, rl;
        float* ph = &rh.x; float* pl = &rl.x;
        #pragma unroll
        for (int j = 0; j < 4; j++) {
            int col = n0 + tx*4 + j;
            float hi = aH[i][j], lo = aL[i][j];
            float h2 = hi + lo;
            float l2 = lo - (h2 - hi);
            float bv = bias[wrow0 + col];
            float s, e; ts2(h2, bv, s, e); e += l2;
            float oh = s + e;
            float ol = e - (oh - s);
            ph[j] = oh; pl[j] = ol;
        }
        int col0 = n0 + tx*4;
        int head = col0 >> 6, d = col0 & 63;
        size_t off;
        if (MODE == FFM_Q) {
            int b = m >> 6, q = m & 63;
            off = (((size_t)(b*HEADS + head))*LTN + q)*HD + d;
        } else {
            int b = m / NTOK, n = m - (m/NTOK)*NTOK;
            off = (((size_t)(b*HEADS + head))*NTOK + n)*HD + d;
        }
        *(float4*)&Ch[off] = rh;
        *(float4*)&Cl[off] = rl;
    }
}

// ---------------- ff QK^T -> double logits ----------------
#define SMEM_FFQK (4*64*68*4)

__global__ __launch_bounds__(256)
void ffqk_kernel(const float* __restrict__ Qh, const float* __restrict__ Ql,
                 const float* __restrict__ Kh, const float* __restrict__ Kl,
                 double* __restrict__ Lg)
{
    extern __shared__ float smf[];
    float* sQh = smf;
    float* sQl = smf + 64*68;
    float* sKh = smf + 2*64*68;
    float* sKl = smf + 3*64*68;
    int bh = blockIdx.x, nt = blockIdx.y;
    int tid = threadIdx.x;
    int tx = tid & 15, ty = tid >> 4;
    size_t qbase = (size_t)bh * LTN * HD;
    size_t kbase = ((size_t)bh * NTOK + nt*64) * HD;

    for (int l = tid; l < 1024; l += 256) {
        int row = l >> 4, c4 = (l & 15) * 4;
        float4 a = *(const float4*)&Qh[qbase + (size_t)row*HD + c4];
        float4 b = *(const float4*)&Ql[qbase + (size_t)row*HD + c4];
        float4 c = *(const float4*)&Kh[kbase + (size_t)row*HD + c4];
        float4 d = *(const float4*)&Kl[kbase + (size_t)row*HD + c4];
        sQh[(c4+0)*68+row]=a.x; sQh[(c4+1)*68+row]=a.y; sQh[(c4+2)*68+row]=a.z; sQh[(c4+3)*68+row]=a.w;
        sQl[(c4+0)*68+row]=b.x; sQl[(c4+1)*68+row]=b.y; sQl[(c4+2)*68+row]=b.z; sQl[(c4+3)*68+row]=b.w;
        sKh[(c4+0)*68+row]=c.x; sKh[(c4+1)*68+row]=c.y; sKh[(c4+2)*68+row]=c.z; sKh[(c4+3)*68+row]=c.w;
        sKl[(c4+0)*68+row]=d.x; sKl[(c4+1)*68+row]=d.y; sKl[(c4+2)*68+row]=d.z; sKl[(c4+3)*68+row]=d.w;
    }
    __syncthreads();
    float aH[4][4], aL[4][4];
    #pragma unroll
    for (int i = 0; i < 4; i++)
        #pragma unroll
        for (int j = 0; j < 4; j++) { aH[i][j]=0.f; aL[i][j]=0.f; }
    for (int d = 0; d < 64; d++) {
        float4 qh4 = *(const float4*)&sQh[d*68 + ty*4];
        float4 ql4 = *(const float4*)&sQl[d*68 + ty*4];
        float4 kh4 = *(const float4*)&sKh[d*68 + tx*4];
        float4 kl4 = *(const float4*)&sKl[d*68 + tx*4];
        float qh[4]={qh4.x,qh4.y,qh4.z,qh4.w}, ql[4]={ql4.x,ql4.y,ql4.z,ql4.w};
        float kh[4]={kh4.x,kh4.y,kh4.z,kh4.w}, kl[4]={kl4.x,kl4.y,kl4.z,kl4.w};
        #pragma unroll
        for (int i = 0; i < 4; i++)
            #pragma unroll
            for (int j = 0; j < 4; j++)
                ffacc_pp(aH[i][j], aL[i][j], qh[i], ql[i], kh[j], kl[j]);
    }
    #pragma unroll
    for (int i = 0; i < 4; i++) {
        int q = ty*4 + i;
        #pragma unroll
        for (int j = 0; j < 4; j++) {
            int key = nt*64 + tx*4 + j;
            Lg[((size_t)bh*LTN + q)*NTOK + key] =
                ((double)aH[i][j] + (double)aL[i][j]) * 0.125;
        }
    }
}

// ---------------- exact double softmax + key sums; also V2 fp32-emulated sums ----------------
__global__ __launch_bounds__(256)
void score_soft_kernel(const double* __restrict__ Lg, double* __restrict__ spartd,
                       float* __restrict__ spartf2)
{
    __shared__ double sl[NTOK];
    __shared__ double sred[16];
    int b = blockIdx.x, h = blockIdx.y;
    int bh = b*HEADS + h;
    const double* L = Lg + (size_t)bh * LTN * NTOK;
    int t = threadIdx.x;
    int lane = t & 31, warp = t >> 5;
    double acc0 = 0.0, acc1 = 0.0;
    float  f0 = 0.f,   f1 = 0.f;     // V2: fp32 sequential q-sums of fp32-rounded attn

    for (int q = 0; q < LTN; q++) {
        __syncthreads();
        const double* lq = L + (size_t)q * NTOK;
        double m = lq[t];
        m = fmax(m, lq[t+256]);
        if (t < 64) m = fmax(m, lq[t+512]);
        #pragma unroll
        for (int o = 16; o; o >>= 1) m = fmax(m, __shfl_xor_sync(0xffffffffu, m, o));
        if (lane == 0) sred[warp] = m;
        __syncthreads();
        if (t < 32) {
            double mm = (lane < 8) ? sred[lane] : -1e300;
            #pragma unroll
            for (int o = 4; o; o >>= 1) mm = fmax(mm, __shfl_xor_sync(0xffffffffu, mm, o));
            if (lane == 0) sred[0] = mm;
        }
        __syncthreads();
        m = sred[0];
        double sum = 0.0;
        {
            double p = exp(lq[t] - m);       sl[t] = p;       sum += p;
            p = exp(lq[t+256] - m);          sl[t+256] = p;   sum += p;
            if (t < 64) { p = exp(lq[t+512] - m); sl[t+512] = p; sum += p; }
        }
        #pragma unroll
        for (int o = 16; o; o >>= 1) sum += __shfl_xor_sync(0xffffffffu, sum, o);
        if (lane == 0) sred[8+warp] = sum;
        __syncthreads();
        if (t < 32) {
            double ss = (lane < 8) ? sred[8+lane] : 0.0;
            #pragma unroll
            for (int o = 4; o; o >>= 1) ss += __shfl_xor_sync(0xffffffffu, ss, o);
            if (lane == 0) sred[8] = ss;
        }
        __syncthreads();
        double inv = 1.0 / sred[8];
        double a0 = sl[64  + t] * inv;
        double a1 = sl[320 + t] * inv;
        acc0 += a0;
        acc1 += a1;
        f0 += (float)a0;   // bit-identical to R7's V2 accumulation
        f1 += (float)a1;
    }
    spartd[(size_t)bh*512 + t]        = acc0;
    spartd[(size_t)bh*512 + 256 + t]  = acc1;
    spartf2[(size_t)bh*512 + t]       = f0 / 64.0f;
    spartf2[(size_t)bh*512 + 256 + t] = f1 / 64.0f;
}

// ---------------- V1: R4-style fp32-emulated score from main fp32 q/k ----------------
__global__ __launch_bounds__(256)
void score_emul4_kernel(const float* __restrict__ Q, const float* __restrict__ K,
                        float* __restrict__ spartf1)
{
    __shared__ float sq[64];
    __shared__ float sl[NTOK];
    __shared__ float sred[16];
    int b = blockIdx.x, h = blockIdx.y;
    int bh = b*HEADS + h;
    size_t base = (size_t)bh * NTOK * HD;
    int t = threadIdx.x;
    int lane = t & 31, warp = t >> 5;
    float acc0 = 0.f, acc1 = 0.f;

    for (int q = 0; q < LTN; q++) {
        __syncthreads();
        if (t < 16)
            *(float4*)&sq[t*4] = *(const float4*)&Q[base + (size_t)q*HD + t*4];
        __syncthreads();
        #pragma unroll
        for (int rep = 0; rep < 3; rep++) {
            int j = t + rep*256;
            if (j < NTOK) {
                const float* kr = &K[base + (size_t)j*HD];
                float s0=0.f, s1=0.f, s2=0.f, s3=0.f;
                #pragma unroll
                for (int d = 0; d < 64; d += 4) {
                    s0 = fmaf(sq[d+0], kr[d+0], s0);
                    s1 = fmaf(sq[d+1], kr[d+1], s1);
                    s2 = fmaf(sq[d+2], kr[d+2], s2);
                    s3 = fmaf(sq[d+3], kr[d+3], s3);
                }
                sl[j] = ((s0+s1)+(s2+s3)) * 0.125f;
            }
        }
        __syncthreads();
        float m = -3.4e38f;
        m = fmaxf(m, sl[t]);
        m = fmaxf(m, sl[t+256]);
        if (t < 64) m = fmaxf(m, sl[t+512]);
        #pragma unroll
        for (int o = 16; o; o >>= 1) m = fmaxf(m, __shfl_xor_sync(0xffffffffu, m, o));
        if (lane == 0) sred[warp] = m;
        __syncthreads();
        if (t < 32) {
            float mm = (lane < 8) ? sred[lane] : -3.4e38f;
            #pragma unroll
            for (int o = 4; o; o >>= 1) mm = fmaxf(mm, __shfl_xor_sync(0xffffffffu, mm, o));
            if (lane == 0) sred[0] = mm;
        }
        __syncthreads();
        m = sred[0];
        #pragma unroll
        for (int rep = 0; rep < 3; rep++) {
            int j = t + rep*256;
            if (j < NTOK) {
                float d = sl[j] - m;
                sl[j] = (float)exp((double)d);
            }
        }
        __syncthreads();
        float ls = sl[t] + sl[t+256];
        if (t < 64) ls += sl[t+512];
        #pragma unroll
        for (int o = 16; o; o >>= 1) ls += __shfl_xor_sync(0xffffffffu, ls, o);
        if (lane == 0) sred[8+warp] = ls;
        __syncthreads();
        if (t < 32) {
            float ss = (lane < 8) ? sred[8+lane] : 0.f;
            #pragma unroll
            for (int o = 4; o; o >>= 1) ss += __shfl_xor_sync(0xffffffffu, ss, o);
            if (lane == 0) sred[8] = ss;
        }
        __syncthreads();
        float S = sred[8];
        acc0 += sl[64  + t] / S;
        acc1 += sl[320 + t] / S;
    }
    spartf1[(size_t)bh*512 + t]       = acc0 / 64.0f;
    spartf1[(size_t)bh*512 + 256 + t] = acc1 / 64.0f;
}

// ---------------- reductions: exact(double), V1(fp32 seq), V2(fp32 seq) ----------------
__global__ __launch_bounds__(512)
void score_reduce_kernel(const double* __restrict__ spartd,
                         const float* __restrict__ spartf1,
                         const float* __restrict__ spartf2,
                         double* __restrict__ dscore,
                         float* __restrict__ sv1, float* __restrict__ sv2)
{
    int b = blockIdx.x;
    int j = threadIdx.x;
    double s = 0.0;
    float e1 = 0.f, e2 = 0.f;
    #pragma unroll
    for (int h = 0; h < HEADS; h++) {
        size_t o = (size_t)(b*HEADS + h)*512 + j;
        s  += spartd[o] / 64.0;
        e1 += spartf1[o];
        e2 += spartf2[o];
    }
    dscore[b*2*LSN + j] = s / 12.0;
    sv1[b*2*LSN + j] = e1 / 12.0f;
    sv2[b*2*LSN + j] = e2 / 12.0f;
}

// ---------------- main-path fp32 SGEMM ----------------
#define EPI_QKV  0
#define EPI_PROJ 1
#define EPI_GELU 2
#define EPI_OUT  3

template<int EPI>
__global__ __launch_bounds__(256)
void sgemm_nt(const float* __restrict__ A, const float* __restrict__ Bw,
              const float* __restrict__ bias, const float* __restrict__ res,
              float* __restrict__ Cq, float* __restrict__ Ck, float* __restrict__ Cv,
              float* __restrict__ Cc, int M, int N, int K)
{
    __shared__ float As[16][132];
    __shared__ float Bs[16][132];
    const int tid = threadIdx.x;
    const int tx = tid & 15;
    const int ty = tid >> 4;
    const int m0 = blockIdx.y * 128;
    const int n0 = blockIdx.x * 128;
    float acc[8][8];
    #pragma unroll
    for (int i = 0; i < 8; i++)
        #pragma unroll
        for (int j = 0; j < 8; j++) acc[i][j] = 0.f;

    const int lrow = tid >> 2;
    const int lc4  = (tid & 3) * 4;

    for (int k0 = 0; k0 < K; k0 += 16) {
        #pragma unroll
        for (int half = 0; half < 2; half++) {
            int row = lrow + half*64;
            float4 va = *(const float4*)(A  + (size_t)(m0+row)*K + k0 + lc4);
            As[lc4+0][row]=va.x; As[lc4+1][row]=va.y; As[lc4+2][row]=va.z; As[lc4+3][row]=va.w;
            float4 vb = *(const float4*)(Bw + (size_t)(n0+row)*K + k0 + lc4);
            Bs[lc4+0][row]=vb.x; Bs[lc4+1][row]=vb.y; Bs[lc4+2][row]=vb.z; Bs[lc4+3][row]=vb.w;
        }
        __syncthreads();
        #pragma unroll
        for (int kk = 0; kk < 16; kk++) {
            float4 a0 = *(const float4*)&As[kk][ty*4];
            float4 a1 = *(const float4*)&As[kk][64 + ty*4];
            float4 b0 = *(const float4*)&Bs[kk][tx*4];
            float4 b1 = *(const float4*)&Bs[kk][64 + tx*4];
            float av[8] = {a0.x,a0.y,a0.z,a0.w,a1.x,a1.y,a1.z,a1.w};
            float bv[8] = {b0.x,b0.y,b0.z,b0.w,b1.x,b1.y,b1.z,b1.w};
            #pragma unroll
            for (int i = 0; i < 8; i++)
                #pragma unroll
                for (int j = 0; j < 8; j++)
                    acc[i][j] = fmaf(av[i], bv[j], acc[i][j]);
        }
        __syncthreads();
    }

    #pragma unroll
    for (int i = 0; i < 8; i++) {
        int rloc = (i < 4) ? (ty*4 + i) : (64 + ty*4 + i - 4);
        int row = m0 + rloc;
        #pragma unroll
        for (int jq = 0; jq < 2; jq++) {
            int col = n0 + jq*64 + tx*4;
            float4 r;
            r.x = acc[i][jq*4+0] + bias[col+0];
            r.y = acc[i][jq*4+1] + bias[col+1];
            r.z = acc[i][jq*4+2] + bias[col+2];
            r.w = acc[i][jq*4+3] + bias[col+3];
            if constexpr (EPI == EPI_QKV) {
                int which = col / 768;
                int rem   = col - which*768;
                int head  = rem >> 6;
                int dd    = rem & 63;
                int bb    = row / NTOK;
                int nt    = row - bb*NTOK;
                float* targ = (which == 0) ? Cq : ((which == 1) ? Ck : Cv);
                *(float4*)&targ[(((size_t)(bb*HEADS + head))*NTOK + nt)*HD + dd] = r;
            } else if constexpr (EPI == EPI_PROJ) {
                size_t o = (size_t)row*N + col;
                r.x += res[o+0]; r.y += res[o+1]; r.z += res[o+2]; r.w += res[o+3];
                *(float4*)&Cc[o] = r;
            } else if constexpr (EPI == EPI_GELU) {
                r.x = gelu_exact(r.x); r.y = gelu_exact(r.y);
                r.z = gelu_exact(r.z); r.w = gelu_exact(r.w);
                *(float4*)&Cc[(size_t)row*N + col] = r;
            } else {
                size_t o = (size_t)row*N + col;
                r.x += res[o+0]; r.y += res[o+1]; r.z += res[o+2]; r.w += res[o+3];
                *(float4*)&Cc[o] = r;
            }
        }
    }
}

// ---------------- attention (fp32 main path, 1e-3 tolerance) ----------------
#define SK_PAD 68
#define SMEM_ATTN ((2048 + 64*SK_PAD + 32*577) * 4)

__global__ __launch_bounds__(256)
void attn_softmax_kernel(const float* __restrict__ Q, const float* __restrict__ Km,
                         float* __restrict__ attn_out)
{
    extern __shared__ float sm[];
    float* sQ = sm;
    float* sK = sm + 2048;
    float* sS = sm + 2048 + 64*SK_PAD;
    int bh = blockIdx.x;
    int qt = blockIdx.y;
    int tid = threadIdx.x;
    int tx = tid & 15, ty = tid >> 4;
    int q0 = qt * 32;
    size_t base = (size_t)bh * NTOK * HD;

    for (int l = tid; l < 512; l += 256) {
        int row = l >> 4, c4 = (l & 15) * 4;
        *(float4*)&sQ[row*64 + c4] = *(const float4*)&Q[base + (size_t)(q0+row)*HD + c4];
    }
    for (int kt = 0; kt < 9; kt++) {
        __syncthreads();
        for (int l = tid; l < 1024; l += 256) {
            int row = l >> 4, c4 = (l & 15) * 4;
            float4 v = *(const float4*)&Km[base + (size_t)(kt*64+row)*HD + c4];
            sK[(c4+0)*SK_PAD + row] = v.x;
            sK[(c4+1)*SK_PAD + row] = v.y;
            sK[(c4+2)*SK_PAD + row] = v.z;
            sK[(c4+3)*SK_PAD + row] = v.w;
        }
        __syncthreads();
        float acc[2][4] = {{0.f,0.f,0.f,0.f},{0.f,0.f,0.f,0.f}};
        #pragma unroll
        for (int d = 0; d < 64; d++) {
            float qa = sQ[(2*ty)*64 + d];
            float qb = sQ[(2*ty+1)*64 + d];
            float4 kv = *(const float4*)&sK[d*SK_PAD + tx*4];
            acc[0][0] = fmaf(qa, kv.x, acc[0][0]);
            acc[0][1] = fmaf(qa, kv.y, acc[0][1]);
            acc[0][2] = fmaf(qa, kv.z, acc[0][2]);
            acc[0][3] = fmaf(qa, kv.w, acc[0][3]);
            acc[1][0] = fmaf(qb, kv.x, acc[1][0]);
            acc[1][1] = fmaf(qb, kv.y, acc[1][1]);
            acc[1][2] = fmaf(qb, kv.z, acc[1][2]);
            acc[1][3] = fmaf(qb, kv.w, acc[1][3]);
        }
        #pragma unroll
        for (int i2 = 0; i2 < 2; i2++)
            #pragma unroll
            for (int j = 0; j < 4; j++)
                sS[(2*ty+i2)*577 + kt*64 + tx*4 + j] = acc[i2][j] * 0.125f;
    }
    __syncthreads();
    int warp = tid >> 5, lane = tid & 31;
    for (int r = warp*4; r < warp*4 + 4; r++) {
        float* srow = &sS[r*577];
        float m = -3.4e38f;
        for (int j = lane; j < NTOK; j += 32) m = fmaxf(m, srow[j]);
        #pragma unroll
        for (int o = 16; o; o >>= 1) m = fmaxf(m, __shfl_xor_sync(0xffffffffu, m, o));
        float s = 0.f;
        for (int j = lane; j < NTOK; j += 32) {
            float p = expf(srow[j] - m);
            srow[j] = p;
            s += p;
        }
        #pragma unroll
        for (int o = 16; o; o >>= 1) s += __shfl_xor_sync(0xffffffffu, s, o);
        size_t obase = ((size_t)bh*NTOK + q0 + r) * NTOK;
        for (int j = lane; j < NTOK; j += 32) attn_out[obase + j] = srow[j] / s;
    }
}

// ---------------- PV ----------------
__global__ __launch_bounds__(256)
void attn_pv_kernel(const float* __restrict__ P, const float* __restrict__ V,
                    float* __restrict__ XA)
{
    __shared__ float sP[64*33];
    __shared__ float sV[32*64];
    int bh = blockIdx.x, qt = blockIdx.y;
    int b = bh / HEADS, h = bh % HEADS;
    int tid = threadIdx.x, tx = tid & 15, ty = tid >> 4;
    int q0 = qt * 64;
    float acc[4][4];
    #pragma unroll
    for (int i = 0; i < 4; i++)
        #pragma unroll
        for (int j = 0; j < 4; j++) acc[i][j] = 0.f;
    size_t pbase = ((size_t)bh*NTOK + q0) * NTOK;
    size_t vbase = (size_t)bh * NTOK * HD;

    for (int k0 = 0; k0 < NTOK; k0 += 32) {
        __syncthreads();
        for (int l = tid; l < 512; l += 256) {
            int row = l >> 3, c4 = (l & 7) * 4;
            float4 p = *(const float4*)&P[pbase + (size_t)row*NTOK + k0 + c4];
            sP[row*33 + c4+0] = p.x;
            sP[row*33 + c4+1] = p.y;
            sP[row*33 + c4+2] = p.z;
            sP[row*33 + c4+3] = p.w;
        }
        for (int l = tid; l < 512; l += 256) {
            int row = l >> 4, c4 = (l & 15) * 4;
            *(float4*)&sV[row*64 + c4] = *(const float4*)&V[vbase + (size_t)(k0+row)*HD + c4];
        }
        __syncthreads();
        #pragma unroll
        for (int kk = 0; kk < 32; kk++) {
            float4 vv = *(const float4*)&sV[kk*64 + tx*4];
            float a0 = sP[(ty*4+0)*33 + kk];
            float a1 = sP[(ty*4+1)*33 + kk];
            float a2 = sP[(ty*4+2)*33 + kk];
            float a3 = sP[(ty*4+3)*33 + kk];
            acc[0][0]=fmaf(a0,vv.x,acc[0][0]); acc[0][1]=fmaf(a0,vv.y,acc[0][1]);
            acc[0][2]=fmaf(a0,vv.z,acc[0][2]); acc[0][3]=fmaf(a0,vv.w,acc[0][3]);
            acc[1][0]=fmaf(a1,vv.x,acc[1][0]); acc[1][1]=fmaf(a1,vv.y,acc[1][1]);
            acc[1][2]=fmaf(a1,vv.z,acc[1][2]); acc[1][3]=fmaf(a1,vv.w,acc[1][3]);
            acc[2][0]=fmaf(a2,vv.x,acc[2][0]); acc[2][1]=fmaf(a2,vv.y,acc[2][1]);
            acc[2][2]=fmaf(a2,vv.z,acc[2][2]); acc[2][3]=fmaf(a2,vv.w,acc[2][3]);
            acc[3][0]=fmaf(a3,vv.x,acc[3][0]); acc[3][1]=fmaf(a3,vv.y,acc[3][1]);
            acc[3][2]=fmaf(a3,vv.z,acc[3][2]); acc[3][3]=fmaf(a3,vv.w,acc[3][3]);
        }
    }
    #pragma unroll
    for (int i = 0; i < 4; i++) {
        int q = q0 + ty*4 + i;
        float4 r; r.x = acc[i][0]; r.y = acc[i][1]; r.z = acc[i][2]; r.w = acc[i][3];
        *(float4*)&XA[((size_t)b*NTOK + q)*DIMC + h*HD + tx*4] = r;
    }
}

// ---------------- sort (exact) + intersection-flag swap -> final order ----------------
__global__ __launch_bounds__(256)
void sort_flag_kernel(const double* __restrict__ dscore,
                      const float* __restrict__ sv1, const float* __restrict__ sv2,
                      int* __restrict__ order)
{
    __shared__ double sv[256];
    __shared__ int    si[256];
    __shared__ int    flg[256];
    int b = blockIdx.x, grp = blockIdx.y, tid = threadIdx.x;
    int group = b*2 + grp;
    int gbase = b*2*LSN + grp*LSN;
    sv[tid] = dscore[gbase + tid];
    si[tid] = tid;
    __syncthreads();
    for (int k = 2; k <= 256; k <<= 1) {
        for (int j = k >> 1; j > 0; j >>= 1) {
            int ixj = tid ^ j;
            if (ixj > tid) {
                double va = sv[tid], vb = sv[ixj];
                int    ia = si[tid], ib = si[ixj];
                bool a_first = (va > vb) || (va == vb && ia < ib);
                bool desc = ((tid & k) == 0);
                bool doswap = desc ? (!a_first) : a_first;
                if (doswap) { sv[tid]=vb; sv[ixj]=va; si[tid]=ib; si[ixj]=ia; }
            }
            __syncthreads();
        }
    }
    // flag adjacent pairs inverted by BOTH emulation variants (stable tiebreak)
    int f = 0;
    if (tid < 255) {
        int u = si[tid], v = si[tid+1];
        float a1 = sv1[gbase + u], b1 = sv1[gbase + v];
        float a2 = sv2[gbase + u], b2 = sv2[gbase + v];
        bool inv1 = (b1 > a1) || (b1 == a1 && v < u);
        bool inv2 = (b2 > a2) || (b2 == a2 && v < u);
        f = (inv1 && inv2) ? 1 : 0;
    }
    flg[tid] = f;
    __syncthreads();
    int fprev = (tid > 0) ? flg[tid-1] : 0;
    int src = flg[tid] ? tid+1 : (fprev ? tid-1 : tid);
    order[group*LSN + tid] = si[src];
}

// emit index outputs from final order
__global__ __launch_bounds__(256)
void emit_kernel(const int* __restrict__ order,
                 const int* __restrict__ gi_ps, const int* __restrict__ gi_s,
                 float* __restrict__ out, int* __restrict__ top_ps,
                 int* __restrict__ top_s)
{
    int b = blockIdx.x, grp = blockIdx.y, tid = threadIdx.x;
    int group = b*2 + grp;
    int idx = order[group*LSN + tid];
    const int* gi = grp ? gi_s : gi_ps;
    float gval = (float)gi[b*LSN + idx];
    if (tid < KEEPN) {
        out[(grp ? KEEP_S_OFF : KEEP_PS_OFF) + b*KEEPN + tid] = gval;
        (grp ? top_s : top_ps)[b*LSN + tid] = idx;
    } else {
        out[(grp ? REM_S_OFF : REM_PS_OFF) + b*REMN + (tid - KEEPN)] = gval;
    }
}

__global__ void idx_copy_kernel(const int* __restrict__ git, float* __restrict__ out)
{
    int i = blockIdx.x*256 + threadIdx.x;
    if (i < BATCH*LTN) out[GIT_OFF + i] = (float)git[i];
}

// ---------------- gather kept tokens + LN2 ----------------
__global__ __launch_bounds__(256)
void gather_ln2_kernel(const float* __restrict__ X1, const int* __restrict__ topps,
                       const int* __restrict__ tops, const float* __restrict__ w,
                       const float* __restrict__ bia, float* __restrict__ XN,
                       float* __restrict__ HN)
{
    __shared__ float sb[16];
    int i = blockIdx.x;
    int b = blockIdx.y;
    int src;
    if (i < LTN)              src = i;
    else if (i < LTN + KEEPN) src = LTN + topps[b*LSN + (i - LTN)];
    else                      src = LTN + LSN + tops[b*LSN + (i - LTN - KEEPN)];
    const float* xr = X1 + ((size_t)b*NTOK + src) * DIMC;
    size_t ob = ((size_t)b*NKEEP + i) * DIMC;
    int t = threadIdx.x;
    float v0 = xr[t], v1 = xr[t+256], v2 = xr[t+512];
    XN[ob+t] = v0; XN[ob+t+256] = v1; XN[ob+t+512] = v2;
    float s = v0+v1+v2;
    float q = v0*v0 + v1*v1 + v2*v2;
    int lane = t & 31, warp = t >> 5;
    #pragma unroll
    for (int o = 16; o; o >>= 1) {
        s += __shfl_xor_sync(0xffffffffu, s, o);
        q += __shfl_xor_sync(0xffffffffu, q, o);
    }
    if (lane == 0) { sb[warp] = s; sb[8+warp] = q; }
    __syncthreads();
    if (t < 32) {
        float s2 = (lane < 8) ? sb[lane] : 0.f;
        float q2 = (lane < 8) ? sb[8+lane] : 0.f;
        #pragma unroll
        for (int o = 4; o; o >>= 1) {
            s2 += __shfl_xor_sync(0xffffffffu, s2, o);
            q2 += __shfl_xor_sync(0xffffffffu, q2, o);
        }
        if (lane == 0) { sb[0] = s2; sb[1] = q2; }
    }
    __syncthreads();
    float mean = sb[0] * (1.f/768.f);
    float var  = sb[1] * (1.f/768.f) - mean*mean;
    float inv  = rsqrtf(var + 1e-5f);
    HN[ob+t]     = (v0-mean)*inv*w[t]     + bia[t];
    HN[ob+t+256] = (v1-mean)*inv*w[t+256] + bia[t+256];
    HN[ob+t+512] = (v2-mean)*inv*w[t+512] + bia[t+512];
}

// ---------------- launch ----------------
extern "C" void kernel_launch(void* const* d_in, const int* in_sizes, int n_in,
                              void* d_out, int out_size)
{
    const float* x     = (const float*)d_in[0];
    const int*   git   = (const int*)  d_in[1];
    const int*   gips  = (const int*)  d_in[2];
    const int*   gis   = (const int*)  d_in[3];
    const float* ln1w  = (const float*)d_in[4];
    const float* ln1b  = (const float*)d_in[5];
    const float* qkvw  = (const float*)d_in[6];
    const float* qkvb  = (const float*)d_in[7];
    const float* projw = (const float*)d_in[8];
    const float* projb = (const float*)d_in[9];
    const float* ln2w  = (const float*)d_in[10];
    const float* ln2b  = (const float*)d_in[11];
    const float* fc1w  = (const float*)d_in[12];
    const float* fc1b  = (const float*)d_in[13];
    const float* fc2w  = (const float*)d_in[14];
    const float* fc2b  = (const float*)d_in[15];
    float* out = (float*)d_out;

    float *ph, *phlo, *pq, *pk, *pv, *pxa, *px1, *pxn, *phn, *pact;
    float *pkffh, *pkffl, *pqffh, *pqffl, *pspartf1, *pspartf2, *psv1, *psv2;
    double *pL, *pspartd, *pdscore;
    int *porder, *ptopps, *ptops;
    cudaGetSymbolAddress((void**)&ph,      g_h);
    cudaGetSymbolAddress((void**)&phlo,    g_hlo);
    cudaGetSymbolAddress((void**)&pq,      g_q);
    cudaGetSymbolAddress((void**)&pk,      g_k);
    cudaGetSymbolAddress((void**)&pv,      g_v);
    cudaGetSymbolAddress((void**)&pxa,     g_xa);
    cudaGetSymbolAddress((void**)&px1,     g_x1);
    cudaGetSymbolAddress((void**)&pxn,     g_xn);
    cudaGetSymbolAddress((void**)&phn,     g_hn);
    cudaGetSymbolAddress((void**)&pact,    g_act);
    cudaGetSymbolAddress((void**)&pkffh,   g_kffh);
    cudaGetSymbolAddress((void**)&pkffl,   g_kffl);
    cudaGetSymbolAddress((void**)&pqffh,   g_qffh);
    cudaGetSymbolAddress((void**)&pqffl,   g_qffl);
    cudaGetSymbolAddress((void**)&pL,      g_L);
    cudaGetSymbolAddress((void**)&pspartd, g_spartd);
    cudaGetSymbolAddress((void**)&pspartf1,g_spartf1);
    cudaGetSymbolAddress((void**)&pspartf2,g_spartf2);
    cudaGetSymbolAddress((void**)&pdscore, g_dscore);
    cudaGetSymbolAddress((void**)&psv1,    g_sv1);
    cudaGetSymbolAddress((void**)&psv2,    g_sv2);
    cudaGetSymbolAddress((void**)&porder,  g_order);
    cudaGetSymbolAddress((void**)&ptopps,  g_top_ps);
    cudaGetSymbolAddress((void**)&ptops,   g_top_s);

    float* attn_out = out + ATTN_OFF;

    cudaFuncSetAttribute(attn_softmax_kernel,
                         cudaFuncAttributeMaxDynamicSharedMemorySize, SMEM_ATTN);
    cudaFuncSetAttribute(ffqk_kernel,
                         cudaFuncAttributeMaxDynamicSharedMemorySize, SMEM_FFQK);

    // 1. LN1 in ff (h_hi also feeds main path)
    ln_ff_kernel<<<M1, 256>>>(x, ln1w, ln1b, ph, phlo);
    // 2. main QKV GEMM (fp32)
    sgemm_nt<EPI_QKV><<<dim3(3*DIMC/128, M1/128), 256>>>(
        ph, qkvw, qkvb, nullptr, pq, pk, pv, nullptr, M1, 3*DIMC, DIMC);
    // 3. ff K (all rows) and ff Q (template rows)
    ffgemm_kernel<FFM_K><<<dim3(DIMC/64, M1/64), 256>>>(ph, phlo, qkvw, qkvb, pkffh, pkffl);
    ffgemm_kernel<FFM_Q><<<dim3(DIMC/64, (BATCH*LTN)/64), 256>>>(ph, phlo, qkvw, qkvb, pqffh, pqffl);
    // 4. ff logits -> double
    ffqk_kernel<<<dim3(BATCH*HEADS, NTOK/64), 256, SMEM_FFQK>>>(pqffh, pqffl, pkffh, pkffl, pL);
    // 5. exact scores + V2 emulation (same pass), V1 emulation, reductions
    score_soft_kernel<<<dim3(BATCH, HEADS), 256>>>(pL, pspartd, pspartf2);
    score_emul4_kernel<<<dim3(BATCH, HEADS), 256>>>(pq, pk, pspartf1);
    score_reduce_kernel<<<BATCH, 512>>>(pspartd, pspartf1, pspartf2, pdscore, psv1, psv2);
    // 6. main attention (attn output)
    attn_softmax_kernel<<<dim3(BATCH*HEADS, NTOK/32), 256, SMEM_ATTN>>>(pq, pk, attn_out);
    // 7. PV
    attn_pv_kernel<<<dim3(BATCH*HEADS, NTOK/64), 256>>>(attn_out, pv, pxa);
    // 8. proj + residual
    sgemm_nt<EPI_PROJ><<<dim3(DIMC/128, M1/128), 256>>>(
        pxa, projw, projb, x, nullptr, nullptr, nullptr, px1, M1, DIMC, DIMC);
    // 9. exact sort + intersection-of-emulations swap -> emit
    sort_flag_kernel<<<dim3(BATCH, 2), 256>>>(pdscore, psv1, psv2, porder);
    emit_kernel<<<dim3(BATCH, 2), 256>>>(porder, gips, gis, out, ptopps, ptops);
    idx_copy_kernel<<<(BATCH*LTN + 255)/256, 256>>>(git, out);
    // 10. gather + LN2
    gather_ln2_kernel<<<dim3(NKEEP, BATCH), 256>>>(px1, ptopps, ptops, ln2w, ln2b, pxn, phn);
    // 11. MLP
    sgemm_nt<EPI_GELU><<<dim3(HID/128, M2/128), 256>>>(
        phn, fc1w, fc1b, nullptr, nullptr, nullptr, nullptr, pact, M2, HID, DIMC);
    sgemm_nt<EPI_OUT><<<dim3(DIMC/128, M2/128), 256>>>(
        pact, fc2w, fc2b, pxn, nullptr, nullptr, nullptr, out, M2, DIMC, HID);
}

// round 11
// speedup vs baseline: 1.0677x; 1.0677x over previous
#include <cuda_runtime.h>

// ---------------- problem constants ----------------
#define BATCH  32
#define NTOK   576
#define DIMC   768
#define HEADS  12
#define HD     64
#define LTN    64
#define LSN    256
#define KEEPN  180
#define REMN   76
#define NKEEP  424
#define HID    3072

#define M1     (BATCH*NTOK)   // 18432
#define M2     (BATCH*NKEEP)  // 13568

// output layout (flattened tuple, float32, reference order)
#define GIT_OFF      10420224
#define KEEP_PS_OFF  10422272
#define KEEP_S_OFF   10428032
#define REM_PS_OFF   10433792
#define REM_S_OFF    10436224
#define ATTN_OFF     10438656

// ---------------- device scratch ----------------
__device__ __align__(16) float g_h  [M1*DIMC];
__device__ __align__(16) float g_hlo[M1*DIMC];
__device__ __align__(16) float g_q  [M1*DIMC];
__device__ __align__(16) float g_k  [M1*DIMC];
__device__ __align__(16) float g_v  [M1*DIMC];
__device__ __align__(16) float g_xa [M1*DIMC];
__device__ __align__(16) float g_x1 [M1*DIMC];
__device__ __align__(16) float g_xn [M2*DIMC];
__device__ __align__(16) float g_hn [M2*DIMC];
__device__ __align__(16) float g_act[(size_t)M2*HID];
__device__ __align__(16) float g_kffh[M1*DIMC];
__device__ __align__(16) float g_kffl[M1*DIMC];
__device__ __align__(16) float g_qffh[BATCH*HEADS*LTN*HD];
__device__ __align__(16) float g_qffl[BATCH*HEADS*LTN*HD];
__device__ __align__(16) double g_L[(size_t)BATCH*HEADS*LTN*NTOK];
__device__ __align__(16) double g_spartd [(size_t)BATCH*HEADS*512];
__device__ __align__(16) float  g_spartf2[(size_t)BATCH*HEADS*512];
__device__ __align__(16) float  g_spartf1[(size_t)BATCH*HEADS*512];
__device__ __align__(16) double g_dscore[BATCH*2*LSN];
__device__ __align__(16) float  g_sv1[BATCH*2*LSN];
__device__ __align__(16) float  g_sv2[BATCH*2*LSN];
__device__ __align__(16) int    g_order[64*LSN];
__device__ __align__(16) int    g_top_ps[BATCH*LSN];
__device__ __align__(16) int    g_top_s [BATCH*LSN];

// ---------------- packed f32x2 helpers (per-lane IEEE rn, bit-identical) ----
typedef unsigned long long ull;
__device__ __forceinline__ ull pk2(float lo, float hi) {
    ull r;
    asm("mov.b64 %0, {%1, %2};" : "=l"(r)
        : "r"(__float_as_uint(lo)), "r"(__float_as_uint(hi)));
    return r;
}
__device__ __forceinline__ ull dup2(float v) { return pk2(v, v); }
__device__ __forceinline__ void upk2(ull v, float& lo, float& hi) {
    unsigned a, b;
    asm("mov.b64 {%0, %1}, %2;" : "=r"(a), "=r"(b) : "l"(v));
    lo = __uint_as_float(a); hi = __uint_as_float(b);
}
__device__ __forceinline__ ull fma2(ull a, ull b, ull c) {
    ull d; asm("fma.rn.f32x2 %0, %1, %2, %3;" : "=l"(d) : "l"(a), "l"(b), "l"(c));
    return d;
}
__device__ __forceinline__ ull add2(ull a, ull b) {
    ull d; asm("add.rn.f32x2 %0, %1, %2;" : "=l"(d) : "l"(a), "l"(b));
    return d;
}
__device__ __forceinline__ ull mul2(ull a, ull b) {
    ull d; asm("mul.rn.f32x2 %0, %1, %2;" : "=l"(d) : "l"(a), "l"(b));
    return d;
}
__device__ __forceinline__ ull neg2(ull a) {
    const ull m = 0x8000000080000000ULL;
    ull d; asm("xor.b64 %0, %1, %2;" : "=l"(d) : "l"(a), "l"(m));
    return d;
}

// ---------------- ff (double-single) helpers ----------------
__device__ __forceinline__ void ts2(float a, float b, float& s, float& e) {
    s = a + b;
    float z = s - a;
    e = (a - (s - z)) + (b - z);
}
__device__ __forceinline__ void ffacc_f(float& h, float& l, float v) {
    float s, e; ts2(h, v, s, e); h = s; l += e;
}
__device__ __forceinline__ void ffacc_p(float& h, float& l, float a, float b) {
    float p = a * b;
    float e = fmaf(a, b, -p);
    float s, er; ts2(h, p, s, er);
    h = s; l += er + e;
}
__device__ __forceinline__ void ffadd(float& h, float& l, float bh2, float bl2) {
    float s, e; ts2(h, bh2, s, e);
    e += l + bl2;
    h = s + e;
    l = e - (h - s);
}

__device__ __forceinline__ float gelu_exact(float v) {
    return 0.5f * v * (1.0f + erff(v * 0.70710678118654752f));
}

// ---------------- LN1 in ff: writes h_hi (main path) + h_lo ----------------
__global__ __launch_bounds__(256)
void ln_ff_kernel(const float* __restrict__ X, const float* __restrict__ w,
                  const float* __restrict__ bia, float* __restrict__ Yh,
                  float* __restrict__ Yl)
{
    __shared__ float sh[8], slo[8], sqh[8], sql[8];
    __shared__ double sm_mean, sm_inv;
    int row = blockIdx.x;
    const float* xr = X + (size_t)row * DIMC;
    int t = threadIdx.x;
    float x0 = xr[t], x1 = xr[t+256], x2 = xr[t+512];
    float sH = 0.f, sL = 0.f, qH = 0.f, qL = 0.f;
    ffacc_f(sH, sL, x0); ffacc_f(sH, sL, x1); ffacc_f(sH, sL, x2);
    ffacc_p(qH, qL, x0, x0); ffacc_p(qH, qL, x1, x1); ffacc_p(qH, qL, x2, x2);
    int lane = t & 31, warp = t >> 5;
    #pragma unroll
    for (int o = 16; o; o >>= 1) {
        float oh = __shfl_xor_sync(0xffffffffu, sH, o);
        float ol = __shfl_xor_sync(0xffffffffu, sL, o);
        ffadd(sH, sL, oh, ol);
        oh = __shfl_xor_sync(0xffffffffu, qH, o);
        ol = __shfl_xor_sync(0xffffffffu, qL, o);
        ffadd(qH, qL, oh, ol);
    }
    if (lane == 0) { sh[warp]=sH; slo[warp]=sL; sqh[warp]=qH; sql[warp]=qL; }
    __syncthreads();
    if (t == 0) {
        double ms = 0.0, mq = 0.0;
        #pragma unroll
        for (int i = 0; i < 8; i++) {
            ms += (double)sh[i] + (double)slo[i];
            mq += (double)sqh[i] + (double)sql[i];
        }
        double mean = ms / 768.0;
        double var  = mq / 768.0 - mean*mean;
        sm_mean = mean;
        sm_inv  = 1.0 / sqrt(var + 1e-5);
    }
    __syncthreads();
    double mean = sm_mean, inv = sm_inv;
    float mh = (float)mean, ml = (float)(mean - (double)mh);
    float ih = (float)inv,  il = (float)(inv  - (double)ih);
    #pragma unroll
    for (int rep = 0; rep < 3; rep++) {
        int c = t + rep*256;
        float xv = (rep==0)?x0:((rep==1)?x1:x2);
        float wv = w[c], bv = bia[c];
        float th, tl; ts2(xv, -mh, th, tl); tl -= ml;
        float ph = th * ih;
        float pl = fmaf(th, ih, -ph);
        pl += th*il + tl*ih;
        float uh = ph * wv;
        float ul = fmaf(ph, wv, -uh);
        ul = fmaf(pl, wv, ul);
        float rh, rl; ts2(uh, bv, rh, rl); rl += ul;
        float oh = rh + rl;
        float ol = rl - (oh - rh);
        Yh[(size_t)row*DIMC + c] = oh;
        Yl[(size_t)row*DIMC + c] = ol;
    }
}

// ---------------- ff GEMM (packed f32x2, per-lane order identical) ----------
#define FFM_K 0
#define FFM_Q 1

template<int MODE>
__global__ __launch_bounds__(256)
void ffgemm_kernel(const float* __restrict__ Ah, const float* __restrict__ Al,
                   const float* __restrict__ W, const float* __restrict__ bias,
                   float* __restrict__ Ch, float* __restrict__ Cl)
{
    __shared__ float Ash[16*68], Asl[16*68], Ws[16*68];
    const int tid = threadIdx.x;
    const int tx = tid & 15, ty = tid >> 4;
    const int m0 = blockIdx.y * 64;
    const int n0 = blockIdx.x * 64;
    const int wrow0 = (MODE == FFM_K) ? 768 : 0;
    const ull NEG1 = dup2(-1.0f);
    ull aH2[4][2], aL2[4][2];
    #pragma unroll
    for (int i = 0; i < 4; i++)
        #pragma unroll
        for (int j = 0; j < 2; j++) { aH2[i][j] = 0ULL; aL2[i][j] = 0ULL; }

    const int lrow = tid >> 2;
    const int lc4  = (tid & 3) * 4;
    int arow;
    if (MODE == FFM_Q) { int m = m0 + lrow; arow = (m >> 6)*NTOK + (m & 63); }
    else               arow = m0 + lrow;

    for (int k0 = 0; k0 < DIMC; k0 += 16) {
        float4 vh = *(const float4*)(Ah + (size_t)arow*DIMC + k0 + lc4);
        float4 vl = *(const float4*)(Al + (size_t)arow*DIMC + k0 + lc4);
        float4 vw = *(const float4*)(W + (size_t)(wrow0 + n0 + lrow)*DIMC + k0 + lc4);
        Ash[(lc4+0)*68+lrow]=vh.x; Ash[(lc4+1)*68+lrow]=vh.y; Ash[(lc4+2)*68+lrow]=vh.z; Ash[(lc4+3)*68+lrow]=vh.w;
        Asl[(lc4+0)*68+lrow]=vl.x; Asl[(lc4+1)*68+lrow]=vl.y; Asl[(lc4+2)*68+lrow]=vl.z; Asl[(lc4+3)*68+lrow]=vl.w;
        Ws [(lc4+0)*68+lrow]=vw.x; Ws [(lc4+1)*68+lrow]=vw.y; Ws [(lc4+2)*68+lrow]=vw.z; Ws [(lc4+3)*68+lrow]=vw.w;
        __syncthreads();
        #pragma unroll
        for (int kk = 0; kk < 16; kk++) {
            float4 ah4 = *(const float4*)&Ash[kk*68 + ty*4];
            float4 al4 = *(const float4*)&Asl[kk*68 + ty*4];
            ulonglong2 wq = *(const ulonglong2*)&Ws[kk*68 + tx*4];
            ull wp[2] = {wq.x, wq.y};
            float ahv[4] = {ah4.x, ah4.y, ah4.z, ah4.w};
            float alv[4] = {al4.x, al4.y, al4.z, al4.w};
            #pragma unroll
            for (int i = 0; i < 4; i++) {
                ull ahd = dup2(ahv[i]);
                ull ald = dup2(alv[i]);
                #pragma unroll
                for (int j2 = 0; j2 < 2; j2++) {
                    // per lane: p = ah*w; e = fma(ah,w,-p); e = fma(al,w,e);
                    ull p2 = mul2(ahd, wp[j2]);
                    ull e2 = fma2(ahd, wp[j2], neg2(p2));
                    e2 = fma2(ald, wp[j2], e2);
                    // ts2(aH, p): s=aH+p; z=s-aH; er=(aH-(s-z))+(p-z)
                    ull s2 = add2(aH2[i][j2], p2);
                    ull z2 = fma2(aH2[i][j2], NEG1, s2);   // s - aH
                    ull t1 = fma2(z2, NEG1, s2);           // s - z
                    ull t2 = fma2(t1, NEG1, aH2[i][j2]);   // aH - t1
                    ull t3 = fma2(z2, NEG1, p2);           // p - z
                    ull er2 = add2(t2, t3);
                    aH2[i][j2] = s2;
                    aL2[i][j2] = add2(aL2[i][j2], add2(er2, e2));
                }
            }
        }
        __syncthreads();
    }

    #pragma unroll
    for (int i = 0; i < 4; i++) {
        float aH[4], aL[4];
        upk2(aH2[i][0], aH[0], aH[1]); upk2(aH2[i][1], aH[2], aH[3]);
        upk2(aL2[i][0], aL[0], aL[1]); upk2(aL2[i][1], aL[2], aL[3]);
        int m = m0 + ty*4 + i;
        float4 rh, rl;
        float* ph = &rh.x; float* pl = &rl.x;
        #pragma unroll
        for (int j = 0; j < 4; j++) {
            int col = n0 + tx*4 + j;
            float hi = aH[j], lo = aL[j];
            float h2 = hi + lo;
            float l2 = lo - (h2 - hi);
            float bv = bias[wrow0 + col];
            float s, e; ts2(h2, bv, s, e); e += l2;
            float oh = s + e;
            float ol = e - (oh - s);
            ph[j] = oh; pl[j] = ol;
        }
        int col0 = n0 + tx*4;
        int head = col0 >> 6, d = col0 & 63;
        size_t off;
        if (MODE == FFM_Q) {
            int b = m >> 6, q = m & 63;
            off = (((size_t)(b*HEADS + head))*LTN + q)*HD + d;
        } else {
            int b = m / NTOK, n = m - (m/NTOK)*NTOK;
            off = (((size_t)(b*HEADS + head))*NTOK + n)*HD + d;
        }
        *(float4*)&Ch[off] = rh;
        *(float4*)&Cl[off] = rl;
    }
}

// ---------------- ff QK^T -> double logits (packed f32x2) ----------------
#define SMEM_FFQK (4*64*68*4)

__global__ __launch_bounds__(256)
void ffqk_kernel(const float* __restrict__ Qh, const float* __restrict__ Ql,
                 const float* __restrict__ Kh, const float* __restrict__ Kl,
                 double* __restrict__ Lg)
{
    extern __shared__ float smf[];
    float* sQh = smf;
    float* sQl = smf + 64*68;
    float* sKh = smf + 2*64*68;
    float* sKl = smf + 3*64*68;
    int bh = blockIdx.x, nt = blockIdx.y;
    int tid = threadIdx.x;
    int tx = tid & 15, ty = tid >> 4;
    size_t qbase = (size_t)bh * LTN * HD;
    size_t kbase = ((size_t)bh * NTOK + nt*64) * HD;
    const ull NEG1 = dup2(-1.0f);

    for (int l = tid; l < 1024; l += 256) {
        int row = l >> 4, c4 = (l & 15) * 4;
        float4 a = *(const float4*)&Qh[qbase + (size_t)row*HD + c4];
        float4 b = *(const float4*)&Ql[qbase + (size_t)row*HD + c4];
        float4 c = *(const float4*)&Kh[kbase + (size_t)row*HD + c4];
        float4 d = *(const float4*)&Kl[kbase + (size_t)row*HD + c4];
        sQh[(c4+0)*68+row]=a.x; sQh[(c4+1)*68+row]=a.y; sQh[(c4+2)*68+row]=a.z; sQh[(c4+3)*68+row]=a.w;
        sQl[(c4+0)*68+row]=b.x; sQl[(c4+1)*68+row]=b.y; sQl[(c4+2)*68+row]=b.z; sQl[(c4+3)*68+row]=b.w;
        sKh[(c4+0)*68+row]=c.x; sKh[(c4+1)*68+row]=c.y; sKh[(c4+2)*68+row]=c.z; sKh[(c4+3)*68+row]=c.w;
        sKl[(c4+0)*68+row]=d.x; sKl[(c4+1)*68+row]=d.y; sKl[(c4+2)*68+row]=d.z; sKl[(c4+3)*68+row]=d.w;
    }
    __syncthreads();
    ull aH2[4][2], aL2[4][2];
    #pragma unroll
    for (int i = 0; i < 4; i++)
        #pragma unroll
        for (int j = 0; j < 2; j++) { aH2[i][j]=0ULL; aL2[i][j]=0ULL; }
    for (int d = 0; d < 64; d++) {
        float4 qh4 = *(const float4*)&sQh[d*68 + ty*4];
        float4 ql4 = *(const float4*)&sQl[d*68 + ty*4];
        ulonglong2 khq = *(const ulonglong2*)&sKh[d*68 + tx*4];
        ulonglong2 klq = *(const ulonglong2*)&sKl[d*68 + tx*4];
        ull khp[2] = {khq.x, khq.y};
        ull klp[2] = {klq.x, klq.y};
        float qh[4]={qh4.x,qh4.y,qh4.z,qh4.w}, ql[4]={ql4.x,ql4.y,ql4.z,ql4.w};
        #pragma unroll
        for (int i = 0; i < 4; i++) {
            ull qhd = dup2(qh[i]);
            ull qld = dup2(ql[i]);
            #pragma unroll
            for (int j2 = 0; j2 < 2; j2++) {
                // per lane: p=qh*kh; e=fma(qh,kh,-p); e=fma(qh,kl,e); e=fma(ql,kh,e)
                ull p2 = mul2(qhd, khp[j2]);
                ull e2 = fma2(qhd, khp[j2], neg2(p2));
                e2 = fma2(qhd, klp[j2], e2);
                e2 = fma2(qld, khp[j2], e2);
                ull s2 = add2(aH2[i][j2], p2);
                ull z2 = fma2(aH2[i][j2], NEG1, s2);
                ull t1 = fma2(z2, NEG1, s2);
                ull t2 = fma2(t1, NEG1, aH2[i][j2]);
                ull t3 = fma2(z2, NEG1, p2);
                ull er2 = add2(t2, t3);
                aH2[i][j2] = s2;
                aL2[i][j2] = add2(aL2[i][j2], add2(er2, e2));
            }
        }
    }
    #pragma unroll
    for (int i = 0; i < 4; i++) {
        float aH[4], aL[4];
        upk2(aH2[i][0], aH[0], aH[1]); upk2(aH2[i][1], aH[2], aH[3]);
        upk2(aL2[i][0], aL[0], aL[1]); upk2(aL2[i][1], aL[2], aL[3]);
        int q = ty*4 + i;
        #pragma unroll
        for (int j = 0; j < 4; j++) {
            int key = nt*64 + tx*4 + j;
            Lg[((size_t)bh*LTN + q)*NTOK + key] =
                ((double)aH[j] + (double)aL[j]) * 0.125;
        }
    }
}

// ---------------- exact double softmax + key sums; also V2 fp32-emulated sums ----------------
__global__ __launch_bounds__(256)
void score_soft_kernel(const double* __restrict__ Lg, double* __restrict__ spartd,
                       float* __restrict__ spartf2)
{
    __shared__ double sl[NTOK];
    __shared__ double sred[16];
    int b = blockIdx.x, h = blockIdx.y;
    int bh = b*HEADS + h;
    const double* L = Lg + (size_t)bh * LTN * NTOK;
    int t = threadIdx.x;
    int lane = t & 31, warp = t >> 5;
    double acc0 = 0.0, acc1 = 0.0;
    float  f0 = 0.f,   f1 = 0.f;

    for (int q = 0; q < LTN; q++) {
        __syncthreads();
        const double* lq = L + (size_t)q * NTOK;
        double m = lq[t];
        m = fmax(m, lq[t+256]);
        if (t < 64) m = fmax(m, lq[t+512]);
        #pragma unroll
        for (int o = 16; o; o >>= 1) m = fmax(m, __shfl_xor_sync(0xffffffffu, m, o));
        if (lane == 0) sred[warp] = m;
        __syncthreads();
        if (t < 32) {
            double mm = (lane < 8) ? sred[lane] : -1e300;
            #pragma unroll
            for (int o = 4; o; o >>= 1) mm = fmax(mm, __shfl_xor_sync(0xffffffffu, mm, o));
            if (lane == 0) sred[0] = mm;
        }
        __syncthreads();
        m = sred[0];
        double sum = 0.0;
        {
            double p = exp(lq[t] - m);       sl[t] = p;       sum += p;
            p = exp(lq[t+256] - m);          sl[t+256] = p;   sum += p;
            if (t < 64) { p = exp(lq[t+512] - m); sl[t+512] = p; sum += p; }
        }
        #pragma unroll
        for (int o = 16; o; o >>= 1) sum += __shfl_xor_sync(0xffffffffu, sum, o);
        if (lane == 0) sred[8+warp] = sum;
        __syncthreads();
        if (t < 32) {
            double ss = (lane < 8) ? sred[8+lane] : 0.0;
            #pragma unroll
            for (int o = 4; o; o >>= 1) ss += __shfl_xor_sync(0xffffffffu, ss, o);
            if (lane == 0) sred[8] = ss;
        }
        __syncthreads();
        double inv = 1.0 / sred[8];
        double a0 = sl[64  + t] * inv;
        double a1 = sl[320 + t] * inv;
        acc0 += a0;
        acc1 += a1;
        f0 += (float)a0;
        f1 += (float)a1;
    }
    spartd[(size_t)bh*512 + t]        = acc0;
    spartd[(size_t)bh*512 + 256 + t]  = acc1;
    spartf2[(size_t)bh*512 + t]       = f0 / 64.0f;
    spartf2[(size_t)bh*512 + 256 + t] = f1 / 64.0f;
}

// ---------------- V1: R4-style fp32-emulated score from main fp32 q/k ----------------
__global__ __launch_bounds__(256)
void score_emul4_kernel(const float* __restrict__ Q, const float* __restrict__ K,
                        float* __restrict__ spartf1)
{
    __shared__ float sq[64];
    __shared__ float sl[NTOK];
    __shared__ float sred[16];
    int b = blockIdx.x, h = blockIdx.y;
    int bh = b*HEADS + h;
    size_t base = (size_t)bh * NTOK * HD;
    int t = threadIdx.x;
    int lane = t & 31, warp = t >> 5;
    float acc0 = 0.f, acc1 = 0.f;

    for (int q = 0; q < LTN; q++) {
        __syncthreads();
        if (t < 16)
            *(float4*)&sq[t*4] = *(const float4*)&Q[base + (size_t)q*HD + t*4];
        __syncthreads();
        #pragma unroll
        for (int rep = 0; rep < 3; rep++) {
            int j = t + rep*256;
            if (j < NTOK) {
                const float* kr = &K[base + (size_t)j*HD];
                float s0=0.f, s1=0.f, s2=0.f, s3=0.f;
                #pragma unroll
                for (int d = 0; d < 64; d += 4) {
                    s0 = fmaf(sq[d+0], kr[d+0], s0);
                    s1 = fmaf(sq[d+1], kr[d+1], s1);
                    s2 = fmaf(sq[d+2], kr[d+2], s2);
                    s3 = fmaf(sq[d+3], kr[d+3], s3);
                }
                sl[j] = ((s0+s1)+(s2+s3)) * 0.125f;
            }
        }
        __syncthreads();
        float m = -3.4e38f;
        m = fmaxf(m, sl[t]);
        m = fmaxf(m, sl[t+256]);
        if (t < 64) m = fmaxf(m, sl[t+512]);
        #pragma unroll
        for (int o = 16; o; o >>= 1) m = fmaxf(m, __shfl_xor_sync(0xffffffffu, m, o));
        if (lane == 0) sred[warp] = m;
        __syncthreads();
        if (t < 32) {
            float mm = (lane < 8) ? sred[lane] : -3.4e38f;
            #pragma unroll
            for (int o = 4; o; o >>= 1) mm = fmaxf(mm, __shfl_xor_sync(0xffffffffu, mm, o));
            if (lane == 0) sred[0] = mm;
        }
        __syncthreads();
        m = sred[0];
        #pragma unroll
        for (int rep = 0; rep < 3; rep++) {
            int j = t + rep*256;
            if (j < NTOK) {
                float d = sl[j] - m;
                sl[j] = (float)exp((double)d);
            }
        }
        __syncthreads();
        float ls = sl[t] + sl[t+256];
        if (t < 64) ls += sl[t+512];
        #pragma unroll
        for (int o = 16; o; o >>= 1) ls += __shfl_xor_sync(0xffffffffu, ls, o);
        if (lane == 0) sred[8+warp] = ls;
        __syncthreads();
        if (t < 32) {
            float ss = (lane < 8) ? sred[8+lane] : 0.f;
            #pragma unroll
            for (int o = 4; o; o >>= 1) ss += __shfl_xor_sync(0xffffffffu, ss, o);
            if (lane == 0) sred[8] = ss;
        }
        __syncthreads();
        float S = sred[8];
        acc0 += sl[64  + t] / S;
        acc1 += sl[320 + t] / S;
    }
    spartf1[(size_t)bh*512 + t]       = acc0 / 64.0f;
    spartf1[(size_t)bh*512 + 256 + t] = acc1 / 64.0f;
}

// ---------------- reductions: exact(double), V1(fp32 seq), V2(fp32 seq) ----------------
__global__ __launch_bounds__(512)
void score_reduce_kernel(const double* __restrict__ spartd,
                         const float* __restrict__ spartf1,
                         const float* __restrict__ spartf2,
                         double* __restrict__ dscore,
                         float* __restrict__ sv1, float* __restrict__ sv2)
{
    int b = blockIdx.x;
    int j = threadIdx.x;
    double s = 0.0;
    float e1 = 0.f, e2 = 0.f;
    #pragma unroll
    for (int h = 0; h < HEADS; h++) {
        size_t o = (size_t)(b*HEADS + h)*512 + j;
        s  += spartd[o] / 64.0;
        e1 += spartf1[o];
        e2 += spartf2[o];
    }
    dscore[b*2*LSN + j] = s / 12.0;
    sv1[b*2*LSN + j] = e1 / 12.0f;
    sv2[b*2*LSN + j] = e2 / 12.0f;
}

// ---------------- main-path fp32 SGEMM (packed f32x2) ----------------
#define EPI_QKV  0
#define EPI_PROJ 1
#define EPI_GELU 2
#define EPI_OUT  3

template<int EPI>
__global__ __launch_bounds__(256)
void sgemm_nt(const float* __restrict__ A, const float* __restrict__ Bw,
              const float* __restrict__ bias, const float* __restrict__ res,
              float* __restrict__ Cq, float* __restrict__ Ck, float* __restrict__ Cv,
              float* __restrict__ Cc, int M, int N, int K)
{
    __shared__ float As[16][132];
    __shared__ float Bs[16][132];
    const int tid = threadIdx.x;
    const int tx = tid & 15;
    const int ty = tid >> 4;
    const int m0 = blockIdx.y * 128;
    const int n0 = blockIdx.x * 128;
    ull acc2[8][4];
    #pragma unroll
    for (int i = 0; i < 8; i++)
        #pragma unroll
        for (int j = 0; j < 4; j++) acc2[i][j] = 0ULL;

    const int lrow = tid >> 2;
    const int lc4  = (tid & 3) * 4;

    for (int k0 = 0; k0 < K; k0 += 16) {
        #pragma unroll
        for (int half = 0; half < 2; half++) {
            int row = lrow + half*64;
            float4 va = *(const float4*)(A  + (size_t)(m0+row)*K + k0 + lc4);
            As[lc4+0][row]=va.x; As[lc4+1][row]=va.y; As[lc4+2][row]=va.z; As[lc4+3][row]=va.w;
            float4 vb = *(const float4*)(Bw + (size_t)(n0+row)*K + k0 + lc4);
            Bs[lc4+0][row]=vb.x; Bs[lc4+1][row]=vb.y; Bs[lc4+2][row]=vb.z; Bs[lc4+3][row]=vb.w;
        }
        __syncthreads();
        #pragma unroll
        for (int kk = 0; kk < 16; kk++) {
            float4 a0 = *(const float4*)&As[kk][ty*4];
            float4 a1 = *(const float4*)&As[kk][64 + ty*4];
            ulonglong2 b01 = *(const ulonglong2*)&Bs[kk][tx*4];
            ulonglong2 b23 = *(const ulonglong2*)&Bs[kk][64 + tx*4];
            ull bp0 = b01.x, bp1 = b01.y, bp2 = b23.x, bp3 = b23.y;
            float av[8] = {a0.x,a0.y,a0.z,a0.w,a1.x,a1.y,a1.z,a1.w};
            #pragma unroll
            for (int i = 0; i < 8; i++) {
                ull ad = dup2(av[i]);
                acc2[i][0] = fma2(ad, bp0, acc2[i][0]);
                acc2[i][1] = fma2(ad, bp1, acc2[i][1]);
                acc2[i][2] = fma2(ad, bp2, acc2[i][2]);
                acc2[i][3] = fma2(ad, bp3, acc2[i][3]);
            }
        }
        __syncthreads();
    }

    #pragma unroll
    for (int i = 0; i < 8; i++) {
        float accf[8];
        upk2(acc2[i][0], accf[0], accf[1]);
        upk2(acc2[i][1], accf[2], accf[3]);
        upk2(acc2[i][2], accf[4], accf[5]);
        upk2(acc2[i][3], accf[6], accf[7]);
        int rloc = (i < 4) ? (ty*4 + i) : (64 + ty*4 + i - 4);
        int row = m0 + rloc;
        #pragma unroll
        for (int jq = 0; jq < 2; jq++) {
            int col = n0 + jq*64 + tx*4;
            float4 r;
            r.x = accf[jq*4+0] + bias[col+0];
            r.y = accf[jq*4+1] + bias[col+1];
            r.z = accf[jq*4+2] + bias[col+2];
            r.w = accf[jq*4+3] + bias[col+3];
            if constexpr (EPI == EPI_QKV) {
                int which = col / 768;
                int rem   = col - which*768;
                int head  = rem >> 6;
                int dd    = rem & 63;
                int bb    = row / NTOK;
                int nt    = row - bb*NTOK;
                float* targ = (which == 0) ? Cq : ((which == 1) ? Ck : Cv);
                *(float4*)&targ[(((size_t)(bb*HEADS + head))*NTOK + nt)*HD + dd] = r;
            } else if constexpr (EPI == EPI_PROJ) {
                size_t o = (size_t)row*N + col;
                r.x += res[o+0]; r.y += res[o+1]; r.z += res[o+2]; r.w += res[o+3];
                *(float4*)&Cc[o] = r;
            } else if constexpr (EPI == EPI_GELU) {
                r.x = gelu_exact(r.x); r.y = gelu_exact(r.y);
                r.z = gelu_exact(r.z); r.w = gelu_exact(r.w);
                *(float4*)&Cc[(size_t)row*N + col] = r;
            } else {
                size_t o = (size_t)row*N + col;
                r.x += res[o+0]; r.y += res[o+1]; r.z += res[o+2]; r.w += res[o+3];
                *(float4*)&Cc[o] = r;
            }
        }
    }
}

// ---------------- attention (fp32 main path, packed f32x2 QK) ----------------
#define SK_PAD 68
#define SMEM_ATTN ((2048 + 64*SK_PAD + 32*577) * 4)

__global__ __launch_bounds__(256)
void attn_softmax_kernel(const float* __restrict__ Q, const float* __restrict__ Km,
                         float* __restrict__ attn_out)
{
    extern __shared__ float sm[];
    float* sQ = sm;
    float* sK = sm + 2048;
    float* sS = sm + 2048 + 64*SK_PAD;
    int bh = blockIdx.x;
    int qt = blockIdx.y;
    int tid = threadIdx.x;
    int tx = tid & 15, ty = tid >> 4;
    int q0 = qt * 32;
    size_t base = (size_t)bh * NTOK * HD;

    for (int l = tid; l < 512; l += 256) {
        int row = l >> 4, c4 = (l & 15) * 4;
        *(float4*)&sQ[row*64 + c4] = *(const float4*)&Q[base + (size_t)(q0+row)*HD + c4];
    }
    for (int kt = 0; kt < 9; kt++) {
        __syncthreads();
        for (int l = tid; l < 1024; l += 256) {
            int row = l >> 4, c4 = (l & 15) * 4;
            float4 v = *(const float4*)&Km[base + (size_t)(kt*64+row)*HD + c4];
            sK[(c4+0)*SK_PAD + row] = v.x;
            sK[(c4+1)*SK_PAD + row] = v.y;
            sK[(c4+2)*SK_PAD + row] = v.z;
            sK[(c4+3)*SK_PAD + row] = v.w;
        }
        __syncthreads();
        ull acc2[2][2] = {{0ULL,0ULL},{0ULL,0ULL}};
        #pragma unroll
        for (int d = 0; d < 64; d++) {
            float qa = sQ[(2*ty)*64 + d];
            float qb = sQ[(2*ty+1)*64 + d];
            ulonglong2 kq = *(const ulonglong2*)&sK[d*SK_PAD + tx*4];
            ull qad = dup2(qa), qbd = dup2(qb);
            acc2[0][0] = fma2(qad, kq.x, acc2[0][0]);
            acc2[0][1] = fma2(qad, kq.y, acc2[0][1]);
            acc2[1][0] = fma2(qbd, kq.x, acc2[1][0]);
            acc2[1][1] = fma2(qbd, kq.y, acc2[1][1]);
        }
        #pragma unroll
        for (int i2 = 0; i2 < 2; i2++) {
            float f0, f1, f2, f3;
            upk2(acc2[i2][0], f0, f1);
            upk2(acc2[i2][1], f2, f3);
            float* dst = &sS[(2*ty+i2)*577 + kt*64 + tx*4];
            dst[0] = f0 * 0.125f;
            dst[1] = f1 * 0.125f;
            dst[2] = f2 * 0.125f;
            dst[3] = f3 * 0.125f;
        }
    }
    __syncthreads();
    int warp = tid >> 5, lane = tid & 31;
    for (int r = warp*4; r < warp*4 + 4; r++) {
        float* srow = &sS[r*577];
        float m = -3.4e38f;
        for (int j = lane; j < NTOK; j += 32) m = fmaxf(m, srow[j]);
        #pragma unroll
        for (int o = 16; o; o >>= 1) m = fmaxf(m, __shfl_xor_sync(0xffffffffu, m, o));
        float s = 0.f;
        for (int j = lane; j < NTOK; j += 32) {
            float p = expf(srow[j] - m);
            srow[j] = p;
            s += p;
        }
        #pragma unroll
        for (int o = 16; o; o >>= 1) s += __shfl_xor_sync(0xffffffffu, s, o);
        size_t obase = ((size_t)bh*NTOK + q0 + r) * NTOK;
        for (int j = lane; j < NTOK; j += 32) attn_out[obase + j] = srow[j] / s;
    }
}

// ---------------- PV (packed f32x2) ----------------
__global__ __launch_bounds__(256)
void attn_pv_kernel(const float* __restrict__ P, const float* __restrict__ V,
                    float* __restrict__ XA)
{
    __shared__ float sP[64*33];
    __shared__ float sV[32*64];
    int bh = blockIdx.x, qt = blockIdx.y;
    int b = bh / HEADS, h = bh % HEADS;
    int tid = threadIdx.x, tx = tid & 15, ty = tid >> 4;
    int q0 = qt * 64;
    ull acc2[4][2];
    #pragma unroll
    for (int i = 0; i < 4; i++) { acc2[i][0] = 0ULL; acc2[i][1] = 0ULL; }
    size_t pbase = ((size_t)bh*NTOK + q0) * NTOK;
    size_t vbase = (size_t)bh * NTOK * HD;

    for (int k0 = 0; k0 < NTOK; k0 += 32) {
        __syncthreads();
        for (int l = tid; l < 512; l += 256) {
            int row = l >> 3, c4 = (l & 7) * 4;
            float4 p = *(const float4*)&P[pbase + (size_t)row*NTOK + k0 + c4];
            sP[row*33 + c4+0] = p.x;
            sP[row*33 + c4+1] = p.y;
            sP[row*33 + c4+2] = p.z;
            sP[row*33 + c4+3] = p.w;
        }
        for (int l = tid; l < 512; l += 256) {
            int row = l >> 4, c4 = (l & 15) * 4;
            *(float4*)&sV[row*64 + c4] = *(const float4*)&V[vbase + (size_t)(k0+row)*HD + c4];
        }
        __syncthreads();
        #pragma unroll
        for (int kk = 0; kk < 32; kk++) {
            ulonglong2 vq = *(const ulonglong2*)&sV[kk*64 + tx*4];
            float a0 = sP[(ty*4+0)*33 + kk];
            float a1 = sP[(ty*4+1)*33 + kk];
            float a2 = sP[(ty*4+2)*33 + kk];
            float a3 = sP[(ty*4+3)*33 + kk];
            ull ad0 = dup2(a0), ad1 = dup2(a1), ad2 = dup2(a2), ad3 = dup2(a3);
            acc2[0][0] = fma2(ad0, vq.x, acc2[0][0]);
            acc2[0][1] = fma2(ad0, vq.y, acc2[0][1]);
            acc2[1][0] = fma2(ad1, vq.x, acc2[1][0]);
            acc2[1][1] = fma2(ad1, vq.y, acc2[1][1]);
            acc2[2][0] = fma2(ad2, vq.x, acc2[2][0]);
            acc2[2][1] = fma2(ad2, vq.y, acc2[2][1]);
            acc2[3][0] = fma2(ad3, vq.x, acc2[3][0]);
            acc2[3][1] = fma2(ad3, vq.y, acc2[3][1]);
        }
    }
    #pragma unroll
    for (int i = 0; i < 4; i++) {
        int q = q0 + ty*4 + i;
        float4 r;
        upk2(acc2[i][0], r.x, r.y);
        upk2(acc2[i][1], r.z, r.w);
        *(float4*)&XA[((size_t)b*NTOK + q)*DIMC + h*HD + tx*4] = r;
    }
}

// ---------------- sort (exact) + intersection-flag swap -> final order ----------------
__global__ __launch_bounds__(256)
void sort_flag_kernel(const double* __restrict__ dscore,
                      const float* __restrict__ sv1, const float* __restrict__ sv2,
                      int* __restrict__ order)
{
    __shared__ double sv[256];
    __shared__ int    si[256];
    __shared__ int    flg[256];
    int b = blockIdx.x, grp = blockIdx.y, tid = threadIdx.x;
    int group = b*2 + grp;
    int gbase = b*2*LSN + grp*LSN;
    sv[tid] = dscore[gbase + tid];
    si[tid] = tid;
    __syncthreads();
    for (int k = 2; k <= 256; k <<= 1) {
        for (int j = k >> 1; j > 0; j >>= 1) {
            int ixj = tid ^ j;
            if (ixj > tid) {
                double va = sv[tid], vb = sv[ixj];
                int    ia = si[tid], ib = si[ixj];
                bool a_first = (va > vb) || (va == vb && ia < ib);
                bool desc = ((tid & k) == 0);
                bool doswap = desc ? (!a_first) : a_first;
                if (doswap) { sv[tid]=vb; sv[ixj]=va; si[tid]=ib; si[ixj]=ia; }
            }
            __syncthreads();
        }
    }
    int f = 0;
    if (tid < 255) {
        int u = si[tid], v = si[tid+1];
        float a1 = sv1[gbase + u], b1 = sv1[gbase + v];
        float a2 = sv2[gbase + u], b2 = sv2[gbase + v];
        bool inv1 = (b1 > a1) || (b1 == a1 && v < u);
        bool inv2 = (b2 > a2) || (b2 == a2 && v < u);
        f = (inv1 && inv2) ? 1 : 0;
    }
    flg[tid] = f;
    __syncthreads();
    int fprev = (tid > 0) ? flg[tid-1] : 0;
    int src = flg[tid] ? tid+1 : (fprev ? tid-1 : tid);
    order[group*LSN + tid] = si[src];
}

__global__ __launch_bounds__(256)
void emit_kernel(const int* __restrict__ order,
                 const int* __restrict__ gi_ps, const int* __restrict__ gi_s,
                 float* __restrict__ out, int* __restrict__ top_ps,
                 int* __restrict__ top_s)
{
    int b = blockIdx.x, grp = blockIdx.y, tid = threadIdx.x;
    int group = b*2 + grp;
    int idx = order[group*LSN + tid];
    const int* gi = grp ? gi_s : gi_ps;
    float gval = (float)gi[b*LSN + idx];
    if (tid < KEEPN) {
        out[(grp ? KEEP_S_OFF : KEEP_PS_OFF) + b*KEEPN + tid] = gval;
        (grp ? top_s : top_ps)[b*LSN + tid] = idx;
    } else {
        out[(grp ? REM_S_OFF : REM_PS_OFF) + b*REMN + (tid - KEEPN)] = gval;
    }
}

__global__ void idx_copy_kernel(const int* __restrict__ git, float* __restrict__ out)
{
    int i = blockIdx.x*256 + threadIdx.x;
    if (i < BATCH*LTN) out[GIT_OFF + i] = (float)git[i];
}

// ---------------- gather kept tokens + LN2 ----------------
__global__ __launch_bounds__(256)
void gather_ln2_kernel(const float* __restrict__ X1, const int* __restrict__ topps,
                       const int* __restrict__ tops, const float* __restrict__ w,
                       const float* __restrict__ bia, float* __restrict__ XN,
                       float* __restrict__ HN)
{
    __shared__ float sb[16];
    int i = blockIdx.x;
    int b = blockIdx.y;
    int src;
    if (i < LTN)              src = i;
    else if (i < LTN + KEEPN) src = LTN + topps[b*LSN + (i - LTN)];
    else                      src = LTN + LSN + tops[b*LSN + (i - LTN - KEEPN)];
    const float* xr = X1 + ((size_t)b*NTOK + src) * DIMC;
    size_t ob = ((size_t)b*NKEEP + i) * DIMC;
    int t = threadIdx.x;
    float v0 = xr[t], v1 = xr[t+256], v2 = xr[t+512];
    XN[ob+t] = v0; XN[ob+t+256] = v1; XN[ob+t+512] = v2;
    float s = v0+v1+v2;
    float q = v0*v0 + v1*v1 + v2*v2;
    int lane = t & 31, warp = t >> 5;
    #pragma unroll
    for (int o = 16; o; o >>= 1) {
        s += __shfl_xor_sync(0xffffffffu, s, o);
        q += __shfl_xor_sync(0xffffffffu, q, o);
    }
    if (lane == 0) { sb[warp] = s; sb[8+warp] = q; }
    __syncthreads();
    if (t < 32) {
        float s2 = (lane < 8) ? sb[lane] : 0.f;
        float q2 = (lane < 8) ? sb[8+lane] : 0.f;
        #pragma unroll
        for (int o = 4; o; o >>= 1) {
            s2 += __shfl_xor_sync(0xffffffffu, s2, o);
            q2 += __shfl_xor_sync(0xffffffffu, q2, o);
        }
        if (lane == 0) { sb[0] = s2; sb[1] = q2; }
    }
    __syncthreads();
    float mean = sb[0] * (1.f/768.f);
    float var  = sb[1] * (1.f/768.f) - mean*mean;
    float inv  = rsqrtf(var + 1e-5f);
    HN[ob+t]     = (v0-mean)*inv*w[t]     + bia[t];
    HN[ob+t+256] = (v1-mean)*inv*w[t+256] + bia[t+256];
    HN[ob+t+512] = (v2-mean)*inv*w[t+512] + bia[t+512];
}

// ---------------- launch ----------------
extern "C" void kernel_launch(void* const* d_in, const int* in_sizes, int n_in,
                              void* d_out, int out_size)
{
    const float* x     = (const float*)d_in[0];
    const int*   git   = (const int*)  d_in[1];
    const int*   gips  = (const int*)  d_in[2];
    const int*   gis   = (const int*)  d_in[3];
    const float* ln1w  = (const float*)d_in[4];
    const float* ln1b  = (const float*)d_in[5];
    const float* qkvw  = (const float*)d_in[6];
    const float* qkvb  = (const float*)d_in[7];
    const float* projw = (const float*)d_in[8];
    const float* projb = (const float*)d_in[9];
    const float* ln2w  = (const float*)d_in[10];
    const float* ln2b  = (const float*)d_in[11];
    const float* fc1w  = (const float*)d_in[12];
    const float* fc1b  = (const float*)d_in[13];
    const float* fc2w  = (const float*)d_in[14];
    const float* fc2b  = (const float*)d_in[15];
    float* out = (float*)d_out;

    float *ph, *phlo, *pq, *pk, *pv, *pxa, *px1, *pxn, *phn, *pact;
    float *pkffh, *pkffl, *pqffh, *pqffl, *pspartf1, *pspartf2, *psv1, *psv2;
    double *pL, *pspartd, *pdscore;
    int *porder, *ptopps, *ptops;
    cudaGetSymbolAddress((void**)&ph,      g_h);
    cudaGetSymbolAddress((void**)&phlo,    g_hlo);
    cudaGetSymbolAddress((void**)&pq,      g_q);
    cudaGetSymbolAddress((void**)&pk,      g_k);
    cudaGetSymbolAddress((void**)&pv,      g_v);
    cudaGetSymbolAddress((void**)&pxa,     g_xa);
    cudaGetSymbolAddress((void**)&px1,     g_x1);
    cudaGetSymbolAddress((void**)&pxn,     g_xn);
    cudaGetSymbolAddress((void**)&phn,     g_hn);
    cudaGetSymbolAddress((void**)&pact,    g_act);
    cudaGetSymbolAddress((void**)&pkffh,   g_kffh);
    cudaGetSymbolAddress((void**)&pkffl,   g_kffl);
    cudaGetSymbolAddress((void**)&pqffh,   g_qffh);
    cudaGetSymbolAddress((void**)&pqffl,   g_qffl);
    cudaGetSymbolAddress((void**)&pL,      g_L);
    cudaGetSymbolAddress((void**)&pspartd, g_spartd);
    cudaGetSymbolAddress((void**)&pspartf1,g_spartf1);
    cudaGetSymbolAddress((void**)&pspartf2,g_spartf2);
    cudaGetSymbolAddress((void**)&pdscore, g_dscore);
    cudaGetSymbolAddress((void**)&psv1,    g_sv1);
    cudaGetSymbolAddress((void**)&psv2,    g_sv2);
    cudaGetSymbolAddress((void**)&porder,  g_order);
    cudaGetSymbolAddress((void**)&ptopps,  g_top_ps);
    cudaGetSymbolAddress((void**)&ptops,   g_top_s);

    float* attn_out = out + ATTN_OFF;

    cudaFuncSetAttribute(attn_softmax_kernel,
                         cudaFuncAttributeMaxDynamicSharedMemorySize, SMEM_ATTN);
    cudaFuncSetAttribute(ffqk_kernel,
                         cudaFuncAttributeMaxDynamicSharedMemorySize, SMEM_FFQK);

    // 1. LN1 in ff (h_hi also feeds main path)
    ln_ff_kernel<<<M1, 256>>>(x, ln1w, ln1b, ph, phlo);
    // 2. main QKV GEMM (fp32, f32x2-packed, bit-identical per lane)
    sgemm_nt<EPI_QKV><<<dim3(3*DIMC/128, M1/128), 256>>>(
        ph, qkvw, qkvb, nullptr, pq, pk, pv, nullptr, M1, 3*DIMC, DIMC);
    // 3. ff K (all rows) and ff Q (template rows)
    ffgemm_kernel<FFM_K><<<dim3(DIMC/64, M1/64), 256>>>(ph, phlo, qkvw, qkvb, pkffh, pkffl);
    ffgemm_kernel<FFM_Q><<<dim3(DIMC/64, (BATCH*LTN)/64), 256>>>(ph, phlo, qkvw, qkvb, pqffh, pqffl);
    // 4. ff logits -> double
    ffqk_kernel<<<dim3(BATCH*HEADS, NTOK/64), 256, SMEM_FFQK>>>(pqffh, pqffl, pkffh, pkffl, pL);
    // 5. exact scores + V2 emulation (same pass), V1 emulation, reductions
    score_soft_kernel<<<dim3(BATCH, HEADS), 256>>>(pL, pspartd, pspartf2);
    score_emul4_kernel<<<dim3(BATCH, HEADS), 256>>>(pq, pk, pspartf1);
    score_reduce_kernel<<<BATCH, 512>>>(pspartd, pspartf1, pspartf2, pdscore, psv1, psv2);
    // 6. main attention (attn output)
    attn_softmax_kernel<<<dim3(BATCH*HEADS, NTOK/32), 256, SMEM_ATTN>>>(pq, pk, attn_out);
    // 7. PV
    attn_pv_kernel<<<dim3(BATCH*HEADS, NTOK/64), 256>>>(attn_out, pv, pxa);
    // 8. proj + residual
    sgemm_nt<EPI_PROJ><<<dim3(DIMC/128, M1/128), 256>>>(
        pxa, projw, projb, x, nullptr, nullptr, nullptr, px1, M1, DIMC, DIMC);
    // 9. exact sort + intersection-of-emulations swap -> emit
    sort_flag_kernel<<<dim3(BATCH, 2), 256>>>(pdscore, psv1, psv2, porder);
    emit_kernel<<<dim3(BATCH, 2), 256>>>(porder, gips, gis, out, ptopps, ptops);
    idx_copy_kernel<<<(BATCH*LTN + 255)/256, 256>>>(git, out);
    // 10. gather + LN2
    gather_ln2_kernel<<<dim3(NKEEP, BATCH), 256>>>(px1, ptopps, ptops, ln2w, ln2b, pxn, phn);
    // 11. MLP
    sgemm_nt<EPI_GELU><<<dim3(HID/128, M2/128), 256>>>(
        phn, fc1w, fc1b, nullptr, nullptr, nullptr, nullptr, pact, M2, HID, DIMC);
    sgemm_nt<EPI_OUT><<<dim3(DIMC/128, M2/128), 256>>>(
        pact, fc2w, fc2b, pxn, nullptr, nullptr, nullptr, out, M2, DIMC, HID);
}

// round 12
// speedup vs baseline: 1.2168x; 1.1397x over previous
#include <cuda_runtime.h>

// ---------------- problem constants ----------------
#define BATCH  32
#define NTOK   576
#define DIMC   768
#define HEADS  12
#define HD     64
#define LTN    64
#define LSN    256
#define KEEPN  180
#define REMN   76
#define NKEEP  424
#define HID    3072

#define M1     (BATCH*NTOK)   // 18432
#define M2     (BATCH*NKEEP)  // 13568

// output layout (flattened tuple, float32, reference order)
#define GIT_OFF      10420224
#define KEEP_PS_OFF  10422272
#define KEEP_S_OFF   10428032
#define REM_PS_OFF   10433792
#define REM_S_OFF    10436224
#define ATTN_OFF     10438656

// ---------------- device scratch ----------------
__device__ __align__(16) float g_h  [M1*DIMC];
__device__ __align__(16) float g_hlo[M1*DIMC];
__device__ __align__(16) float g_q  [M1*DIMC];
__device__ __align__(16) float g_k  [M1*DIMC];
__device__ __align__(16) float g_v  [M1*DIMC];
__device__ __align__(16) float g_xa [M1*DIMC];
__device__ __align__(16) float g_x1 [M1*DIMC];
__device__ __align__(16) float g_xn [M2*DIMC];
__device__ __align__(16) float g_hn [M2*DIMC];
__device__ __align__(16) float g_act[(size_t)M2*HID];
__device__ __align__(16) float g_kffh[M1*DIMC];
__device__ __align__(16) float g_kffl[M1*DIMC];
__device__ __align__(16) float g_qffh[BATCH*HEADS*LTN*HD];
__device__ __align__(16) float g_qffl[BATCH*HEADS*LTN*HD];
__device__ __align__(16) double g_L[(size_t)BATCH*HEADS*LTN*NTOK];
__device__ __align__(16) double g_spartd [(size_t)BATCH*HEADS*512];
__device__ __align__(16) float  g_spartf2[(size_t)BATCH*HEADS*512];
__device__ __align__(16) float  g_spartf1[(size_t)BATCH*HEADS*512];
__device__ __align__(16) double g_dscore[BATCH*2*LSN];
__device__ __align__(16) float  g_sv1[BATCH*2*LSN];
__device__ __align__(16) float  g_sv2[BATCH*2*LSN];
__device__ __align__(16) int    g_order[64*LSN];
__device__ __align__(16) int    g_top_ps[BATCH*LSN];
__device__ __align__(16) int    g_top_s [BATCH*LSN];

// ---------------- packed f32x2 helpers (per-lane IEEE rn, bit-identical) ----
typedef unsigned long long ull;
__device__ __forceinline__ ull pk2(float lo, float hi) {
    ull r;
    asm("mov.b64 %0, {%1, %2};" : "=l"(r)
        : "r"(__float_as_uint(lo)), "r"(__float_as_uint(hi)));
    return r;
}
__device__ __forceinline__ ull dup2(float v) { return pk2(v, v); }
__device__ __forceinline__ void upk2(ull v, float& lo, float& hi) {
    unsigned a, b;
    asm("mov.b64 {%0, %1}, %2;" : "=r"(a), "=r"(b) : "l"(v));
    lo = __uint_as_float(a); hi = __uint_as_float(b);
}
__device__ __forceinline__ ull fma2(ull a, ull b, ull c) {
    ull d; asm("fma.rn.f32x2 %0, %1, %2, %3;" : "=l"(d) : "l"(a), "l"(b), "l"(c));
    return d;
}
__device__ __forceinline__ ull add2(ull a, ull b) {
    ull d; asm("add.rn.f32x2 %0, %1, %2;" : "=l"(d) : "l"(a), "l"(b));
    return d;
}
__device__ __forceinline__ ull mul2(ull a, ull b) {
    ull d; asm("mul.rn.f32x2 %0, %1, %2;" : "=l"(d) : "l"(a), "l"(b));
    return d;
}
__device__ __forceinline__ ull neg2(ull a) {
    const ull m = 0x8000000080000000ULL;
    ull d; asm("xor.b64 %0, %1, %2;" : "=l"(d) : "l"(a), "l"(m));
    return d;
}
__device__ __forceinline__ unsigned f2tf(float f) {
    unsigned r; asm("cvt.rna.tf32.f32 %0, %1;" : "=r"(r) : "f"(f));
    return r;
}

// ---------------- ff (double-single) helpers ----------------
__device__ __forceinline__ void ts2(float a, float b, float& s, float& e) {
    s = a + b;
    float z = s - a;
    e = (a - (s - z)) + (b - z);
}
__device__ __forceinline__ void ffacc_f(float& h, float& l, float v) {
    float s, e; ts2(h, v, s, e); h = s; l += e;
}
__device__ __forceinline__ void ffacc_p(float& h, float& l, float a, float b) {
    float p = a * b;
    float e = fmaf(a, b, -p);
    float s, er; ts2(h, p, s, er);
    h = s; l += er + e;
}
__device__ __forceinline__ void ffadd(float& h, float& l, float bh2, float bl2) {
    float s, e; ts2(h, bh2, s, e);
    e += l + bl2;
    h = s + e;
    l = e - (h - s);
}

__device__ __forceinline__ float gelu_exact(float v) {
    return 0.5f * v * (1.0f + erff(v * 0.70710678118654752f));
}

// ---------------- LN1 in ff: writes h_hi (main path) + h_lo ----------------
__global__ __launch_bounds__(256)
void ln_ff_kernel(const float* __restrict__ X, const float* __restrict__ w,
                  const float* __restrict__ bia, float* __restrict__ Yh,
                  float* __restrict__ Yl)
{
    __shared__ float sh[8], slo[8], sqh[8], sql[8];
    __shared__ double sm_mean, sm_inv;
    int row = blockIdx.x;
    const float* xr = X + (size_t)row * DIMC;
    int t = threadIdx.x;
    float x0 = xr[t], x1 = xr[t+256], x2 = xr[t+512];
    float sH = 0.f, sL = 0.f, qH = 0.f, qL = 0.f;
    ffacc_f(sH, sL, x0); ffacc_f(sH, sL, x1); ffacc_f(sH, sL, x2);
    ffacc_p(qH, qL, x0, x0); ffacc_p(qH, qL, x1, x1); ffacc_p(qH, qL, x2, x2);
    int lane = t & 31, warp = t >> 5;
    #pragma unroll
    for (int o = 16; o; o >>= 1) {
        float oh = __shfl_xor_sync(0xffffffffu, sH, o);
        float ol = __shfl_xor_sync(0xffffffffu, sL, o);
        ffadd(sH, sL, oh, ol);
        oh = __shfl_xor_sync(0xffffffffu, qH, o);
        ol = __shfl_xor_sync(0xffffffffu, qL, o);
        ffadd(qH, qL, oh, ol);
    }
    if (lane == 0) { sh[warp]=sH; slo[warp]=sL; sqh[warp]=qH; sql[warp]=qL; }
    __syncthreads();
    if (t == 0) {
        double ms = 0.0, mq = 0.0;
        #pragma unroll
        for (int i = 0; i < 8; i++) {
            ms += (double)sh[i] + (double)slo[i];
            mq += (double)sqh[i] + (double)sql[i];
        }
        double mean = ms / 768.0;
        double var  = mq / 768.0 - mean*mean;
        sm_mean = mean;
        sm_inv  = 1.0 / sqrt(var + 1e-5);
    }
    __syncthreads();
    double mean = sm_mean, inv = sm_inv;
    float mh = (float)mean, ml = (float)(mean - (double)mh);
    float ih = (float)inv,  il = (float)(inv  - (double)ih);
    #pragma unroll
    for (int rep = 0; rep < 3; rep++) {
        int c = t + rep*256;
        float xv = (rep==0)?x0:((rep==1)?x1:x2);
        float wv = w[c], bv = bia[c];
        float th, tl; ts2(xv, -mh, th, tl); tl -= ml;
        float ph = th * ih;
        float pl = fmaf(th, ih, -ph);
        pl += th*il + tl*ih;
        float uh = ph * wv;
        float ul = fmaf(ph, wv, -uh);
        ul = fmaf(pl, wv, ul);
        float rh, rl; ts2(uh, bv, rh, rl); rl += ul;
        float oh = rh + rl;
        float ol = rl - (oh - rh);
        Yh[(size_t)row*DIMC + c] = oh;
        Yl[(size_t)row*DIMC + c] = ol;
    }
}

// ---------------- ff GEMM (packed f32x2, per-lane order identical) ----------
#define FFM_K 0
#define FFM_Q 1

template<int MODE>
__global__ __launch_bounds__(256)
void ffgemm_kernel(const float* __restrict__ Ah, const float* __restrict__ Al,
                   const float* __restrict__ W, const float* __restrict__ bias,
                   float* __restrict__ Ch, float* __restrict__ Cl)
{
    __shared__ float Ash[16*68], Asl[16*68], Ws[16*68];
    const int tid = threadIdx.x;
    const int tx = tid & 15, ty = tid >> 4;
    const int m0 = blockIdx.y * 64;
    const int n0 = blockIdx.x * 64;
    const int wrow0 = (MODE == FFM_K) ? 768 : 0;
    const ull NEG1 = dup2(-1.0f);
    ull aH2[4][2], aL2[4][2];
    #pragma unroll
    for (int i = 0; i < 4; i++)
        #pragma unroll
        for (int j = 0; j < 2; j++) { aH2[i][j] = 0ULL; aL2[i][j] = 0ULL; }

    const int lrow = tid >> 2;
    const int lc4  = (tid & 3) * 4;
    int arow;
    if (MODE == FFM_Q) { int m = m0 + lrow; arow = (m >> 6)*NTOK + (m & 63); }
    else               arow = m0 + lrow;

    for (int k0 = 0; k0 < DIMC; k0 += 16) {
        float4 vh = *(const float4*)(Ah + (size_t)arow*DIMC + k0 + lc4);
        float4 vl = *(const float4*)(Al + (size_t)arow*DIMC + k0 + lc4);
        float4 vw = *(const float4*)(W + (size_t)(wrow0 + n0 + lrow)*DIMC + k0 + lc4);
        Ash[(lc4+0)*68+lrow]=vh.x; Ash[(lc4+1)*68+lrow]=vh.y; Ash[(lc4+2)*68+lrow]=vh.z; Ash[(lc4+3)*68+lrow]=vh.w;
        Asl[(lc4+0)*68+lrow]=vl.x; Asl[(lc4+1)*68+lrow]=vl.y; Asl[(lc4+2)*68+lrow]=vl.z; Asl[(lc4+3)*68+lrow]=vl.w;
        Ws [(lc4+0)*68+lrow]=vw.x; Ws [(lc4+1)*68+lrow]=vw.y; Ws [(lc4+2)*68+lrow]=vw.z; Ws [(lc4+3)*68+lrow]=vw.w;
        __syncthreads();
        #pragma unroll
        for (int kk = 0; kk < 16; kk++) {
            float4 ah4 = *(const float4*)&Ash[kk*68 + ty*4];
            float4 al4 = *(const float4*)&Asl[kk*68 + ty*4];
            ulonglong2 wq = *(const ulonglong2*)&Ws[kk*68 + tx*4];
            ull wp[2] = {wq.x, wq.y};
            float ahv[4] = {ah4.x, ah4.y, ah4.z, ah4.w};
            float alv[4] = {al4.x, al4.y, al4.z, al4.w};
            #pragma unroll
            for (int i = 0; i < 4; i++) {
                ull ahd = dup2(ahv[i]);
                ull ald = dup2(alv[i]);
                #pragma unroll
                for (int j2 = 0; j2 < 2; j2++) {
                    ull p2 = mul2(ahd, wp[j2]);
                    ull e2 = fma2(ahd, wp[j2], neg2(p2));
                    e2 = fma2(ald, wp[j2], e2);
                    ull s2 = add2(aH2[i][j2], p2);
                    ull z2 = fma2(aH2[i][j2], NEG1, s2);
                    ull t1 = fma2(z2, NEG1, s2);
                    ull t2 = fma2(t1, NEG1, aH2[i][j2]);
                    ull t3 = fma2(z2, NEG1, p2);
                    ull er2 = add2(t2, t3);
                    aH2[i][j2] = s2;
                    aL2[i][j2] = add2(aL2[i][j2], add2(er2, e2));
                }
            }
        }
        __syncthreads();
    }

    #pragma unroll
    for (int i = 0; i < 4; i++) {
        float aH[4], aL[4];
        upk2(aH2[i][0], aH[0], aH[1]); upk2(aH2[i][1], aH[2], aH[3]);
        upk2(aL2[i][0], aL[0], aL[1]); upk2(aL2[i][1], aL[2], aL[3]);
        int m = m0 + ty*4 + i;
        float4 rh, rl;
        float* ph = &rh.x; float* pl = &rl.x;
        #pragma unroll
        for (int j = 0; j < 4; j++) {
            int col = n0 + tx*4 + j;
            float hi = aH[j], lo = aL[j];
            float h2 = hi + lo;
            float l2 = lo - (h2 - hi);
            float bv = bias[wrow0 + col];
            float s, e; ts2(h2, bv, s, e); e += l2;
            float oh = s + e;
            float ol = e - (oh - s);
            ph[j] = oh; pl[j] = ol;
        }
        int col0 = n0 + tx*4;
        int head = col0 >> 6, d = col0 & 63;
        size_t off;
        if (MODE == FFM_Q) {
            int b = m >> 6, q = m & 63;
            off = (((size_t)(b*HEADS + head))*LTN + q)*HD + d;
        } else {
            int b = m / NTOK, n = m - (m/NTOK)*NTOK;
            off = (((size_t)(b*HEADS + head))*NTOK + n)*HD + d;
        }
        *(float4*)&Ch[off] = rh;
        *(float4*)&Cl[off] = rl;
    }
}

// ---------------- ff QK^T -> double logits (packed f32x2) ----------------
#define SMEM_FFQK (4*64*68*4)

__global__ __launch_bounds__(256)
void ffqk_kernel(const float* __restrict__ Qh, const float* __restrict__ Ql,
                 const float* __restrict__ Kh, const float* __restrict__ Kl,
                 double* __restrict__ Lg)
{
    extern __shared__ float smf[];
    float* sQh = smf;
    float* sQl = smf + 64*68;
    float* sKh = smf + 2*64*68;
    float* sKl = smf + 3*64*68;
    int bh = blockIdx.x, nt = blockIdx.y;
    int tid = threadIdx.x;
    int tx = tid & 15, ty = tid >> 4;
    size_t qbase = (size_t)bh * LTN * HD;
    size_t kbase = ((size_t)bh * NTOK + nt*64) * HD;
    const ull NEG1 = dup2(-1.0f);

    for (int l = tid; l < 1024; l += 256) {
        int row = l >> 4, c4 = (l & 15) * 4;
        float4 a = *(const float4*)&Qh[qbase + (size_t)row*HD + c4];
        float4 b = *(const float4*)&Ql[qbase + (size_t)row*HD + c4];
        float4 c = *(const float4*)&Kh[kbase + (size_t)row*HD + c4];
        float4 d = *(const float4*)&Kl[kbase + (size_t)row*HD + c4];
        sQh[(c4+0)*68+row]=a.x; sQh[(c4+1)*68+row]=a.y; sQh[(c4+2)*68+row]=a.z; sQh[(c4+3)*68+row]=a.w;
        sQl[(c4+0)*68+row]=b.x; sQl[(c4+1)*68+row]=b.y; sQl[(c4+2)*68+row]=b.z; sQl[(c4+3)*68+row]=b.w;
        sKh[(c4+0)*68+row]=c.x; sKh[(c4+1)*68+row]=c.y; sKh[(c4+2)*68+row]=c.z; sKh[(c4+3)*68+row]=c.w;
        sKl[(c4+0)*68+row]=d.x; sKl[(c4+1)*68+row]=d.y; sKl[(c4+2)*68+row]=d.z; sKl[(c4+3)*68+row]=d.w;
    }
    __syncthreads();
    ull aH2[4][2], aL2[4][2];
    #pragma unroll
    for (int i = 0; i < 4; i++)
        #pragma unroll
        for (int j = 0; j < 2; j++) { aH2[i][j]=0ULL; aL2[i][j]=0ULL; }
    for (int d = 0; d < 64; d++) {
        float4 qh4 = *(const float4*)&sQh[d*68 + ty*4];
        float4 ql4 = *(const float4*)&sQl[d*68 + ty*4];
        ulonglong2 khq = *(const ulonglong2*)&sKh[d*68 + tx*4];
        ulonglong2 klq = *(const ulonglong2*)&sKl[d*68 + tx*4];
        ull khp[2] = {khq.x, khq.y};
        ull klp[2] = {klq.x, klq.y};
        float qh[4]={qh4.x,qh4.y,qh4.z,qh4.w}, ql[4]={ql4.x,ql4.y,ql4.z,ql4.w};
        #pragma unroll
        for (int i = 0; i < 4; i++) {
            ull qhd = dup2(qh[i]);
            ull qld = dup2(ql[i]);
            #pragma unroll
            for (int j2 = 0; j2 < 2; j2++) {
                ull p2 = mul2(qhd, khp[j2]);
                ull e2 = fma2(qhd, khp[j2], neg2(p2));
                e2 = fma2(qhd, klp[j2], e2);
                e2 = fma2(qld, khp[j2], e2);
                ull s2 = add2(aH2[i][j2], p2);
                ull z2 = fma2(aH2[i][j2], NEG1, s2);
                ull t1 = fma2(z2, NEG1, s2);
                ull t2 = fma2(t1, NEG1, aH2[i][j2]);
                ull t3 = fma2(z2, NEG1, p2);
                ull er2 = add2(t2, t3);
                aH2[i][j2] = s2;
                aL2[i][j2] = add2(aL2[i][j2], add2(er2, e2));
            }
        }
    }
    #pragma unroll
    for (int i = 0; i < 4; i++) {
        float aH[4], aL[4];
        upk2(aH2[i][0], aH[0], aH[1]); upk2(aH2[i][1], aH[2], aH[3]);
        upk2(aL2[i][0], aL[0], aL[1]); upk2(aL2[i][1], aL[2], aL[3]);
        int q = ty*4 + i;
        #pragma unroll
        for (int j = 0; j < 4; j++) {
            int key = nt*64 + tx*4 + j;
            Lg[((size_t)bh*LTN + q)*NTOK + key] =
                ((double)aH[j] + (double)aL[j]) * 0.125;
        }
    }
}

// ---------------- exact double softmax + key sums; also V2 fp32-emulated sums ----------------
__global__ __launch_bounds__(256)
void score_soft_kernel(const double* __restrict__ Lg, double* __restrict__ spartd,
                       float* __restrict__ spartf2)
{
    __shared__ double sl[NTOK];
    __shared__ double sred[16];
    int b = blockIdx.x, h = blockIdx.y;
    int bh = b*HEADS + h;
    const double* L = Lg + (size_t)bh * LTN * NTOK;
    int t = threadIdx.x;
    int lane = t & 31, warp = t >> 5;
    double acc0 = 0.0, acc1 = 0.0;
    float  f0 = 0.f,   f1 = 0.f;

    for (int q = 0; q < LTN; q++) {
        __syncthreads();
        const double* lq = L + (size_t)q * NTOK;
        double m = lq[t];
        m = fmax(m, lq[t+256]);
        if (t < 64) m = fmax(m, lq[t+512]);
        #pragma unroll
        for (int o = 16; o; o >>= 1) m = fmax(m, __shfl_xor_sync(0xffffffffu, m, o));
        if (lane == 0) sred[warp] = m;
        __syncthreads();
        if (t < 32) {
            double mm = (lane < 8) ? sred[lane] : -1e300;
            #pragma unroll
            for (int o = 4; o; o >>= 1) mm = fmax(mm, __shfl_xor_sync(0xffffffffu, mm, o));
            if (lane == 0) sred[0] = mm;
        }
        __syncthreads();
        m = sred[0];
        double sum = 0.0;
        {
            double p = exp(lq[t] - m);       sl[t] = p;       sum += p;
            p = exp(lq[t+256] - m);          sl[t+256] = p;   sum += p;
            if (t < 64) { p = exp(lq[t+512] - m); sl[t+512] = p; sum += p; }
        }
        #pragma unroll
        for (int o = 16; o; o >>= 1) sum += __shfl_xor_sync(0xffffffffu, sum, o);
        if (lane == 0) sred[8+warp] = sum;
        __syncthreads();
        if (t < 32) {
            double ss = (lane < 8) ? sred[8+lane] : 0.0;
            #pragma unroll
            for (int o = 4; o; o >>= 1) ss += __shfl_xor_sync(0xffffffffu, ss, o);
            if (lane == 0) sred[8] = ss;
        }
        __syncthreads();
        double inv = 1.0 / sred[8];
        double a0 = sl[64  + t] * inv;
        double a1 = sl[320 + t] * inv;
        acc0 += a0;
        acc1 += a1;
        f0 += (float)a0;
        f1 += (float)a1;
    }
    spartd[(size_t)bh*512 + t]        = acc0;
    spartd[(size_t)bh*512 + 256 + t]  = acc1;
    spartf2[(size_t)bh*512 + t]       = f0 / 64.0f;
    spartf2[(size_t)bh*512 + 256 + t] = f1 / 64.0f;
}

// ---------------- V1: R4-style fp32-emulated score from main fp32 q/k ----------------
__global__ __launch_bounds__(256)
void score_emul4_kernel(const float* __restrict__ Q, const float* __restrict__ K,
                        float* __restrict__ spartf1)
{
    __shared__ float sq[64];
    __shared__ float sl[NTOK];
    __shared__ float sred[16];
    int b = blockIdx.x, h = blockIdx.y;
    int bh = b*HEADS + h;
    size_t base = (size_t)bh * NTOK * HD;
    int t = threadIdx.x;
    int lane = t & 31, warp = t >> 5;
    float acc0 = 0.f, acc1 = 0.f;

    for (int q = 0; q < LTN; q++) {
        __syncthreads();
        if (t < 16)
            *(float4*)&sq[t*4] = *(const float4*)&Q[base + (size_t)q*HD + t*4];
        __syncthreads();
        #pragma unroll
        for (int rep = 0; rep < 3; rep++) {
            int j = t + rep*256;
            if (j < NTOK) {
                const float* kr = &K[base + (size_t)j*HD];
                float s0=0.f, s1=0.f, s2=0.f, s3=0.f;
                #pragma unroll
                for (int d = 0; d < 64; d += 4) {
                    s0 = fmaf(sq[d+0], kr[d+0], s0);
                    s1 = fmaf(sq[d+1], kr[d+1], s1);
                    s2 = fmaf(sq[d+2], kr[d+2], s2);
                    s3 = fmaf(sq[d+3], kr[d+3], s3);
                }
                sl[j] = ((s0+s1)+(s2+s3)) * 0.125f;
            }
        }
        __syncthreads();
        float m = -3.4e38f;
        m = fmaxf(m, sl[t]);
        m = fmaxf(m, sl[t+256]);
        if (t < 64) m = fmaxf(m, sl[t+512]);
        #pragma unroll
        for (int o = 16; o; o >>= 1) m = fmaxf(m, __shfl_xor_sync(0xffffffffu, m, o));
        if (lane == 0) sred[warp] = m;
        __syncthreads();
        if (t < 32) {
            float mm = (lane < 8) ? sred[lane] : -3.4e38f;
            #pragma unroll
            for (int o = 4; o; o >>= 1) mm = fmaxf(mm, __shfl_xor_sync(0xffffffffu, mm, o));
            if (lane == 0) sred[0] = mm;
        }
        __syncthreads();
        m = sred[0];
        #pragma unroll
        for (int rep = 0; rep < 3; rep++) {
            int j = t + rep*256;
            if (j < NTOK) {
                float d = sl[j] - m;
                sl[j] = (float)exp((double)d);
            }
        }
        __syncthreads();
        float ls = sl[t] + sl[t+256];
        if (t < 64) ls += sl[t+512];
        #pragma unroll
        for (int o = 16; o; o >>= 1) ls += __shfl_xor_sync(0xffffffffu, ls, o);
        if (lane == 0) sred[8+warp] = ls;
        __syncthreads();
        if (t < 32) {
            float ss = (lane < 8) ? sred[8+lane] : 0.f;
            #pragma unroll
            for (int o = 4; o; o >>= 1) ss += __shfl_xor_sync(0xffffffffu, ss, o);
            if (lane == 0) sred[8] = ss;
        }
        __syncthreads();
        float S = sred[8];
        acc0 += sl[64  + t] / S;
        acc1 += sl[320 + t] / S;
    }
    spartf1[(size_t)bh*512 + t]       = acc0 / 64.0f;
    spartf1[(size_t)bh*512 + 256 + t] = acc1 / 64.0f;
}

// ---------------- reductions: exact(double), V1(fp32 seq), V2(fp32 seq) ----------------
__global__ __launch_bounds__(512)
void score_reduce_kernel(const double* __restrict__ spartd,
                         const float* __restrict__ spartf1,
                         const float* __restrict__ spartf2,
                         double* __restrict__ dscore,
                         float* __restrict__ sv1, float* __restrict__ sv2)
{
    int b = blockIdx.x;
    int j = threadIdx.x;
    double s = 0.0;
    float e1 = 0.f, e2 = 0.f;
    #pragma unroll
    for (int h = 0; h < HEADS; h++) {
        size_t o = (size_t)(b*HEADS + h)*512 + j;
        s  += spartd[o] / 64.0;
        e1 += spartf1[o];
        e2 += spartf2[o];
    }
    dscore[b*2*LSN + j] = s / 12.0;
    sv1[b*2*LSN + j] = e1 / 12.0f;
    sv2[b*2*LSN + j] = e2 / 12.0f;
}

// ---------------- main-path fp32 SGEMM (packed f32x2) — QKV only ----------------
#define EPI_QKV  0

template<int EPI>
__global__ __launch_bounds__(256)
void sgemm_nt(const float* __restrict__ A, const float* __restrict__ Bw,
              const float* __restrict__ bias, const float* __restrict__ res,
              float* __restrict__ Cq, float* __restrict__ Ck, float* __restrict__ Cv,
              float* __restrict__ Cc, int M, int N, int K)
{
    __shared__ float As[16][132];
    __shared__ float Bs[16][132];
    const int tid = threadIdx.x;
    const int tx = tid & 15;
    const int ty = tid >> 4;
    const int m0 = blockIdx.y * 128;
    const int n0 = blockIdx.x * 128;
    ull acc2[8][4];
    #pragma unroll
    for (int i = 0; i < 8; i++)
        #pragma unroll
        for (int j = 0; j < 4; j++) acc2[i][j] = 0ULL;

    const int lrow = tid >> 2;
    const int lc4  = (tid & 3) * 4;

    for (int k0 = 0; k0 < K; k0 += 16) {
        #pragma unroll
        for (int half = 0; half < 2; half++) {
            int row = lrow + half*64;
            float4 va = *(const float4*)(A  + (size_t)(m0+row)*K + k0 + lc4);
            As[lc4+0][row]=va.x; As[lc4+1][row]=va.y; As[lc4+2][row]=va.z; As[lc4+3][row]=va.w;
            float4 vb = *(const float4*)(Bw + (size_t)(n0+row)*K + k0 + lc4);
            Bs[lc4+0][row]=vb.x; Bs[lc4+1][row]=vb.y; Bs[lc4+2][row]=vb.z; Bs[lc4+3][row]=vb.w;
        }
        __syncthreads();
        #pragma unroll
        for (int kk = 0; kk < 16; kk++) {
            float4 a0 = *(const float4*)&As[kk][ty*4];
            float4 a1 = *(const float4*)&As[kk][64 + ty*4];
            ulonglong2 b01 = *(const ulonglong2*)&Bs[kk][tx*4];
            ulonglong2 b23 = *(const ulonglong2*)&Bs[kk][64 + tx*4];
            ull bp0 = b01.x, bp1 = b01.y, bp2 = b23.x, bp3 = b23.y;
            float av[8] = {a0.x,a0.y,a0.z,a0.w,a1.x,a1.y,a1.z,a1.w};
            #pragma unroll
            for (int i = 0; i < 8; i++) {
                ull ad = dup2(av[i]);
                acc2[i][0] = fma2(ad, bp0, acc2[i][0]);
                acc2[i][1] = fma2(ad, bp1, acc2[i][1]);
                acc2[i][2] = fma2(ad, bp2, acc2[i][2]);
                acc2[i][3] = fma2(ad, bp3, acc2[i][3]);
            }
        }
        __syncthreads();
    }

    #pragma unroll
    for (int i = 0; i < 8; i++) {
        float accf[8];
        upk2(acc2[i][0], accf[0], accf[1]);
        upk2(acc2[i][1], accf[2], accf[3]);
        upk2(acc2[i][2], accf[4], accf[5]);
        upk2(acc2[i][3], accf[6], accf[7]);
        int rloc = (i < 4) ? (ty*4 + i) : (64 + ty*4 + i - 4);
        int row = m0 + rloc;
        #pragma unroll
        for (int jq = 0; jq < 2; jq++) {
            int col = n0 + jq*64 + tx*4;
            float4 r;
            r.x = accf[jq*4+0] + bias[col+0];
            r.y = accf[jq*4+1] + bias[col+1];
            r.z = accf[jq*4+2] + bias[col+2];
            r.w = accf[jq*4+3] + bias[col+3];
            int which = col / 768;
            int rem   = col - which*768;
            int head  = rem >> 6;
            int dd    = rem & 63;
            int bb    = row / NTOK;
            int nt    = row - bb*NTOK;
            float* targ = (which == 0) ? Cq : ((which == 1) ? Ck : Cv);
            *(float4*)&targ[(((size_t)(bb*HEADS + head))*NTOK + nt)*HD + dd] = r;
        }
    }
}

// ---------------- tf32 tensor-core GEMM (proj / fc1 / fc2; 1e-3 tolerance path) ----
#define TEPI_PROJ 0
#define TEPI_GELU 1
#define TEPI_OUT  2

template<int EPI>
__global__ __launch_bounds__(256)
void tf32gemm_kernel(const float* __restrict__ A, const float* __restrict__ Bw,
                     const float* __restrict__ bias, const float* __restrict__ res,
                     float* __restrict__ C, int M, int N, int K)
{
    __shared__ unsigned As[128*36];
    __shared__ unsigned Bs[128*36];
    const int tid = threadIdx.x;
    const int warp = tid >> 5, lane = tid & 31;
    const int wr = warp >> 2, wc = warp & 3;
    const int g = lane >> 2, t = lane & 3;
    const int m0 = blockIdx.y * 128, n0 = blockIdx.x * 128;
    const int lr = tid >> 3;
    const int lk = (tid & 7) * 4;

    float acc[4][4][4];
    #pragma unroll
    for (int i = 0; i < 4; i++)
        #pragma unroll
        for (int j = 0; j < 4; j++)
            #pragma unroll
            for (int r = 0; r < 4; r++) acc[i][j][r] = 0.f;

    float4 pa[4], pb[4];
    #pragma unroll
    for (int p = 0; p < 4; p++) {
        pa[p] = *(const float4*)(A  + (size_t)(m0 + p*32 + lr)*K + lk);
        pb[p] = *(const float4*)(Bw + (size_t)(n0 + p*32 + lr)*K + lk);
    }

    for (int k0 = 0; k0 < K; k0 += 32) {
        __syncthreads();
        #pragma unroll
        for (int p = 0; p < 4; p++) {
            int m = p*32 + lr;
            As[m*36+lk+0]=f2tf(pa[p].x); As[m*36+lk+1]=f2tf(pa[p].y);
            As[m*36+lk+2]=f2tf(pa[p].z); As[m*36+lk+3]=f2tf(pa[p].w);
            Bs[m*36+lk+0]=f2tf(pb[p].x); Bs[m*36+lk+1]=f2tf(pb[p].y);
            Bs[m*36+lk+2]=f2tf(pb[p].z); Bs[m*36+lk+3]=f2tf(pb[p].w);
        }
        __syncthreads();
        if (k0 + 32 < K) {
            #pragma unroll
            for (int p = 0; p < 4; p++) {
                pa[p] = *(const float4*)(A  + (size_t)(m0 + p*32 + lr)*K + k0 + 32 + lk);
                pb[p] = *(const float4*)(Bw + (size_t)(n0 + p*32 + lr)*K + k0 + 32 + lk);
            }
        }
        #pragma unroll
        for (int ks = 0; ks < 32; ks += 8) {
            unsigned af[4][4], bf[4][2];
            #pragma unroll
            for (int i = 0; i < 4; i++) {
                int row = wr*64 + i*16 + g;
                af[i][0] = As[row*36 + ks + t];
                af[i][1] = As[(row+8)*36 + ks + t];
                af[i][2] = As[row*36 + ks + t + 4];
                af[i][3] = As[(row+8)*36 + ks + t + 4];
            }
            #pragma unroll
            for (int j = 0; j < 4; j++) {
                int n = wc*32 + j*8 + g;
                bf[j][0] = Bs[n*36 + ks + t];
                bf[j][1] = Bs[n*36 + ks + t + 4];
            }
            #pragma unroll
            for (int i = 0; i < 4; i++)
                #pragma unroll
                for (int j = 0; j < 4; j++)
                    asm volatile(
                        "mma.sync.aligned.m16n8k8.row.col.f32.tf32.tf32.f32 "
                        "{%0,%1,%2,%3}, {%4,%5,%6,%7}, {%8,%9}, {%0,%1,%2,%3};"
                        : "+f"(acc[i][j][0]), "+f"(acc[i][j][1]),
                          "+f"(acc[i][j][2]), "+f"(acc[i][j][3])
                        : "r"(af[i][0]), "r"(af[i][1]), "r"(af[i][2]), "r"(af[i][3]),
                          "r"(bf[j][0]), "r"(bf[j][1]));
        }
    }

    #pragma unroll
    for (int i = 0; i < 4; i++) {
        int r0 = m0 + wr*64 + i*16 + g;
        #pragma unroll
        for (int j = 0; j < 4; j++) {
            int c0 = n0 + wc*32 + j*8 + 2*t;
            float b0v = bias[c0], b1v = bias[c0+1];
            float v00 = acc[i][j][0] + b0v, v01 = acc[i][j][1] + b1v;
            float v10 = acc[i][j][2] + b0v, v11 = acc[i][j][3] + b1v;
            size_t o0 = (size_t)r0*N + c0;
            size_t o1 = (size_t)(r0+8)*N + c0;
            if constexpr (EPI == TEPI_GELU) {
                v00 = gelu_exact(v00); v01 = gelu_exact(v01);
                v10 = gelu_exact(v10); v11 = gelu_exact(v11);
            } else {
                float2 r0v = *(const float2*)&res[o0];
                float2 r1v = *(const float2*)&res[o1];
                v00 += r0v.x; v01 += r0v.y;
                v10 += r1v.x; v11 += r1v.y;
            }
            float2 w0; w0.x = v00; w0.y = v01;
            float2 w1; w1.x = v10; w1.y = v11;
            *(float2*)&C[o0] = w0;
            *(float2*)&C[o1] = w1;
        }
    }
}

// ---------------- attention (fp32 main path, packed f32x2 QK) ----------------
#define SK_PAD 68
#define SMEM_ATTN ((2048 + 64*SK_PAD + 32*577) * 4)

__global__ __launch_bounds__(256)
void attn_softmax_kernel(const float* __restrict__ Q, const float* __restrict__ Km,
                         float* __restrict__ attn_out)
{
    extern __shared__ float sm[];
    float* sQ = sm;
    float* sK = sm + 2048;
    float* sS = sm + 2048 + 64*SK_PAD;
    int bh = blockIdx.x;
    int qt = blockIdx.y;
    int tid = threadIdx.x;
    int tx = tid & 15, ty = tid >> 4;
    int q0 = qt * 32;
    size_t base = (size_t)bh * NTOK * HD;

    for (int l = tid; l < 512; l += 256) {
        int row = l >> 4, c4 = (l & 15) * 4;
        *(float4*)&sQ[row*64 + c4] = *(const float4*)&Q[base + (size_t)(q0+row)*HD + c4];
    }
    for (int kt = 0; kt < 9; kt++) {
        __syncthreads();
        for (int l = tid; l < 1024; l += 256) {
            int row = l >> 4, c4 = (l & 15) * 4;
            float4 v = *(const float4*)&Km[base + (size_t)(kt*64+row)*HD + c4];
            sK[(c4+0)*SK_PAD + row] = v.x;
            sK[(c4+1)*SK_PAD + row] = v.y;
            sK[(c4+2)*SK_PAD + row] = v.z;
            sK[(c4+3)*SK_PAD + row] = v.w;
        }
        __syncthreads();
        ull acc2[2][2] = {{0ULL,0ULL},{0ULL,0ULL}};
        #pragma unroll
        for (int d = 0; d < 64; d++) {
            float qa = sQ[(2*ty)*64 + d];
            float qb = sQ[(2*ty+1)*64 + d];
            ulonglong2 kq = *(const ulonglong2*)&sK[d*SK_PAD + tx*4];
            ull qad = dup2(qa), qbd = dup2(qb);
            acc2[0][0] = fma2(qad, kq.x, acc2[0][0]);
            acc2[0][1] = fma2(qad, kq.y, acc2[0][1]);
            acc2[1][0] = fma2(qbd, kq.x, acc2[1][0]);
            acc2[1][1] = fma2(qbd, kq.y, acc2[1][1]);
        }
        #pragma unroll
        for (int i2 = 0; i2 < 2; i2++) {
            float f0, f1, f2, f3;
            upk2(acc2[i2][0], f0, f1);
            upk2(acc2[i2][1], f2, f3);
            float* dst = &sS[(2*ty+i2)*577 + kt*64 + tx*4];
            dst[0] = f0 * 0.125f;
            dst[1] = f1 * 0.125f;
            dst[2] = f2 * 0.125f;
            dst[3] = f3 * 0.125f;
        }
    }
    __syncthreads();
    int warp = tid >> 5, lane = tid & 31;
    for (int r = warp*4; r < warp*4 + 4; r++) {
        float* srow = &sS[r*577];
        float m = -3.4e38f;
        for (int j = lane; j < NTOK; j += 32) m = fmaxf(m, srow[j]);
        #pragma unroll
        for (int o = 16; o; o >>= 1) m = fmaxf(m, __shfl_xor_sync(0xffffffffu, m, o));
        float s = 0.f;
        for (int j = lane; j < NTOK; j += 32) {
            float p = expf(srow[j] - m);
            srow[j] = p;
            s += p;
        }
        #pragma unroll
        for (int o = 16; o; o >>= 1) s += __shfl_xor_sync(0xffffffffu, s, o);
        size_t obase = ((size_t)bh*NTOK + q0 + r) * NTOK;
        for (int j = lane; j < NTOK; j += 32) attn_out[obase + j] = srow[j] / s;
    }
}

// ---------------- PV (packed f32x2) ----------------
__global__ __launch_bounds__(256)
void attn_pv_kernel(const float* __restrict__ P, const float* __restrict__ V,
                    float* __restrict__ XA)
{
    __shared__ float sP[64*33];
    __shared__ float sV[32*64];
    int bh = blockIdx.x, qt = blockIdx.y;
    int b = bh / HEADS, h = bh % HEADS;
    int tid = threadIdx.x, tx = tid & 15, ty = tid >> 4;
    int q0 = qt * 64;
    ull acc2[4][2];
    #pragma unroll
    for (int i = 0; i < 4; i++) { acc2[i][0] = 0ULL; acc2[i][1] = 0ULL; }
    size_t pbase = ((size_t)bh*NTOK + q0) * NTOK;
    size_t vbase = (size_t)bh * NTOK * HD;

    for (int k0 = 0; k0 < NTOK; k0 += 32) {
        __syncthreads();
        for (int l = tid; l < 512; l += 256) {
            int row = l >> 3, c4 = (l & 7) * 4;
            float4 p = *(const float4*)&P[pbase + (size_t)row*NTOK + k0 + c4];
            sP[row*33 + c4+0] = p.x;
            sP[row*33 + c4+1] = p.y;
            sP[row*33 + c4+2] = p.z;
            sP[row*33 + c4+3] = p.w;
        }
        for (int l = tid; l < 512; l += 256) {
            int row = l >> 4, c4 = (l & 15) * 4;
            *(float4*)&sV[row*64 + c4] = *(const float4*)&V[vbase + (size_t)(k0+row)*HD + c4];
        }
        __syncthreads();
        #pragma unroll
        for (int kk = 0; kk < 32; kk++) {
            ulonglong2 vq = *(const ulonglong2*)&sV[kk*64 + tx*4];
            float a0 = sP[(ty*4+0)*33 + kk];
            float a1 = sP[(ty*4+1)*33 + kk];
            float a2 = sP[(ty*4+2)*33 + kk];
            float a3 = sP[(ty*4+3)*33 + kk];
            ull ad0 = dup2(a0), ad1 = dup2(a1), ad2 = dup2(a2), ad3 = dup2(a3);
            acc2[0][0] = fma2(ad0, vq.x, acc2[0][0]);
            acc2[0][1] = fma2(ad0, vq.y, acc2[0][1]);
            acc2[1][0] = fma2(ad1, vq.x, acc2[1][0]);
            acc2[1][1] = fma2(ad1, vq.y, acc2[1][1]);
            acc2[2][0] = fma2(ad2, vq.x, acc2[2][0]);
            acc2[2][1] = fma2(ad2, vq.y, acc2[2][1]);
            acc2[3][0] = fma2(ad3, vq.x, acc2[3][0]);
            acc2[3][1] = fma2(ad3, vq.y, acc2[3][1]);
        }
    }
    #pragma unroll
    for (int i = 0; i < 4; i++) {
        int q = q0 + ty*4 + i;
        float4 r;
        upk2(acc2[i][0], r.x, r.y);
        upk2(acc2[i][1], r.z, r.w);
        *(float4*)&XA[((size_t)b*NTOK + q)*DIMC + h*HD + tx*4] = r;
    }
}

// ---------------- sort (exact) + intersection-flag swap -> final order ----------------
__global__ __launch_bounds__(256)
void sort_flag_kernel(const double* __restrict__ dscore,
                      const float* __restrict__ sv1, const float* __restrict__ sv2,
                      int* __restrict__ order)
{
    __shared__ double sv[256];
    __shared__ int    si[256];
    __shared__ int    flg[256];
    int b = blockIdx.x, grp = blockIdx.y, tid = threadIdx.x;
    int group = b*2 + grp;
    int gbase = b*2*LSN + grp*LSN;
    sv[tid] = dscore[gbase + tid];
    si[tid] = tid;
    __syncthreads();
    for (int k = 2; k <= 256; k <<= 1) {
        for (int j = k >> 1; j > 0; j >>= 1) {
            int ixj = tid ^ j;
            if (ixj > tid) {
                double va = sv[tid], vb = sv[ixj];
                int    ia = si[tid], ib = si[ixj];
                bool a_first = (va > vb) || (va == vb && ia < ib);
                bool desc = ((tid & k) == 0);
                bool doswap = desc ? (!a_first) : a_first;
                if (doswap) { sv[tid]=vb; sv[ixj]=va; si[tid]=ib; si[ixj]=ia; }
            }
            __syncthreads();
        }
    }
    int f = 0;
    if (tid < 255) {
        int u = si[tid], v = si[tid+1];
        float a1 = sv1[gbase + u], b1 = sv1[gbase + v];
        float a2 = sv2[gbase + u], b2 = sv2[gbase + v];
        bool inv1 = (b1 > a1) || (b1 == a1 && v < u);
        bool inv2 = (b2 > a2) || (b2 == a2 && v < u);
        f = (inv1 && inv2) ? 1 : 0;
    }
    flg[tid] = f;
    __syncthreads();
    int fprev = (tid > 0) ? flg[tid-1] : 0;
    int src = flg[tid] ? tid+1 : (fprev ? tid-1 : tid);
    order[group*LSN + tid] = si[src];
}

__global__ __launch_bounds__(256)
void emit_kernel(const int* __restrict__ order,
                 const int* __restrict__ gi_ps, const int* __restrict__ gi_s,
                 float* __restrict__ out, int* __restrict__ top_ps,
                 int* __restrict__ top_s)
{
    int b = blockIdx.x, grp = blockIdx.y, tid = threadIdx.x;
    int group = b*2 + grp;
    int idx = order[group*LSN + tid];
    const int* gi = grp ? gi_s : gi_ps;
    float gval = (float)gi[b*LSN + idx];
    if (tid < KEEPN) {
        out[(grp ? KEEP_S_OFF : KEEP_PS_OFF) + b*KEEPN + tid] = gval;
        (grp ? top_s : top_ps)[b*LSN + tid] = idx;
    } else {
        out[(grp ? REM_S_OFF : REM_PS_OFF) + b*REMN + (tid - KEEPN)] = gval;
    }
}

__global__ void idx_copy_kernel(const int* __restrict__ git, float* __restrict__ out)
{
    int i = blockIdx.x*256 + threadIdx.x;
    if (i < BATCH*LTN) out[GIT_OFF + i] = (float)git[i];
}

// ---------------- gather kept tokens + LN2 ----------------
__global__ __launch_bounds__(256)
void gather_ln2_kernel(const float* __restrict__ X1, const int* __restrict__ topps,
                       const int* __restrict__ tops, const float* __restrict__ w,
                       const float* __restrict__ bia, float* __restrict__ XN,
                       float* __restrict__ HN)
{
    __shared__ float sb[16];
    int i = blockIdx.x;
    int b = blockIdx.y;
    int src;
    if (i < LTN)              src = i;
    else if (i < LTN + KEEPN) src = LTN + topps[b*LSN + (i - LTN)];
    else                      src = LTN + LSN + tops[b*LSN + (i - LTN - KEEPN)];
    const float* xr = X1 + ((size_t)b*NTOK + src) * DIMC;
    size_t ob = ((size_t)b*NKEEP + i) * DIMC;
    int t = threadIdx.x;
    float v0 = xr[t], v1 = xr[t+256], v2 = xr[t+512];
    XN[ob+t] = v0; XN[ob+t+256] = v1; XN[ob+t+512] = v2;
    float s = v0+v1+v2;
    float q = v0*v0 + v1*v1 + v2*v2;
    int lane = t & 31, warp = t >> 5;
    #pragma unroll
    for (int o = 16; o; o >>= 1) {
        s += __shfl_xor_sync(0xffffffffu, s, o);
        q += __shfl_xor_sync(0xffffffffu, q, o);
    }
    if (lane == 0) { sb[warp] = s; sb[8+warp] = q; }
    __syncthreads();
    if (t < 32) {
        float s2 = (lane < 8) ? sb[lane] : 0.f;
        float q2 = (lane < 8) ? sb[8+lane] : 0.f;
        #pragma unroll
        for (int o = 4; o; o >>= 1) {
            s2 += __shfl_xor_sync(0xffffffffu, s2, o);
            q2 += __shfl_xor_sync(0xffffffffu, q2, o);
        }
        if (lane == 0) { sb[0] = s2; sb[1] = q2; }
    }
    __syncthreads();
    float mean = sb[0] * (1.f/768.f);
    float var  = sb[1] * (1.f/768.f) - mean*mean;
    float inv  = rsqrtf(var + 1e-5f);
    HN[ob+t]     = (v0-mean)*inv*w[t]     + bia[t];
    HN[ob+t+256] = (v1-mean)*inv*w[t+256] + bia[t+256];
    HN[ob+t+512] = (v2-mean)*inv*w[t+512] + bia[t+512];
}

// ---------------- launch ----------------
extern "C" void kernel_launch(void* const* d_in, const int* in_sizes, int n_in,
                              void* d_out, int out_size)
{
    const float* x     = (const float*)d_in[0];
    const int*   git   = (const int*)  d_in[1];
    const int*   gips  = (const int*)  d_in[2];
    const int*   gis   = (const int*)  d_in[3];
    const float* ln1w  = (const float*)d_in[4];
    const float* ln1b  = (const float*)d_in[5];
    const float* qkvw  = (const float*)d_in[6];
    const float* qkvb  = (const float*)d_in[7];
    const float* projw = (const float*)d_in[8];
    const float* projb = (const float*)d_in[9];
    const float* ln2w  = (const float*)d_in[10];
    const float* ln2b  = (const float*)d_in[11];
    const float* fc1w  = (const float*)d_in[12];
    const float* fc1b  = (const float*)d_in[13];
    const float* fc2w  = (const float*)d_in[14];
    const float* fc2b  = (const float*)d_in[15];
    float* out = (float*)d_out;

    float *ph, *phlo, *pq, *pk, *pv, *pxa, *px1, *pxn, *phn, *pact;
    float *pkffh, *pkffl, *pqffh, *pqffl, *pspartf1, *pspartf2, *psv1, *psv2;
    double *pL, *pspartd, *pdscore;
    int *porder, *ptopps, *ptops;
    cudaGetSymbolAddress((void**)&ph,      g_h);
    cudaGetSymbolAddress((void**)&phlo,    g_hlo);
    cudaGetSymbolAddress((void**)&pq,      g_q);
    cudaGetSymbolAddress((void**)&pk,      g_k);
    cudaGetSymbolAddress((void**)&pv,      g_v);
    cudaGetSymbolAddress((void**)&pxa,     g_xa);
    cudaGetSymbolAddress((void**)&px1,     g_x1);
    cudaGetSymbolAddress((void**)&pxn,     g_xn);
    cudaGetSymbolAddress((void**)&phn,     g_hn);
    cudaGetSymbolAddress((void**)&pact,    g_act);
    cudaGetSymbolAddress((void**)&pkffh,   g_kffh);
    cudaGetSymbolAddress((void**)&pkffl,   g_kffl);
    cudaGetSymbolAddress((void**)&pqffh,   g_qffh);
    cudaGetSymbolAddress((void**)&pqffl,   g_qffl);
    cudaGetSymbolAddress((void**)&pL,      g_L);
    cudaGetSymbolAddress((void**)&pspartd, g_spartd);
    cudaGetSymbolAddress((void**)&pspartf1,g_spartf1);
    cudaGetSymbolAddress((void**)&pspartf2,g_spartf2);
    cudaGetSymbolAddress((void**)&pdscore, g_dscore);
    cudaGetSymbolAddress((void**)&psv1,    g_sv1);
    cudaGetSymbolAddress((void**)&psv2,    g_sv2);
    cudaGetSymbolAddress((void**)&porder,  g_order);
    cudaGetSymbolAddress((void**)&ptopps,  g_top_ps);
    cudaGetSymbolAddress((void**)&ptops,   g_top_s);

    float* attn_out = out + ATTN_OFF;

    cudaFuncSetAttribute(attn_softmax_kernel,
                         cudaFuncAttributeMaxDynamicSharedMemorySize, SMEM_ATTN);
    cudaFuncSetAttribute(ffqk_kernel,
                         cudaFuncAttributeMaxDynamicSharedMemorySize, SMEM_FFQK);

    // 1. LN1 in ff (h_hi also feeds main path)
    ln_ff_kernel<<<M1, 256>>>(x, ln1w, ln1b, ph, phlo);
    // 2. main QKV GEMM (fp32, bit-identical — feeds V1 emulation; SACRED)
    sgemm_nt<EPI_QKV><<<dim3(3*DIMC/128, M1/128), 256>>>(
        ph, qkvw, qkvb, nullptr, pq, pk, pv, nullptr, M1, 3*DIMC, DIMC);
    // 3. ff K (all rows) and ff Q (template rows)  (SACRED)
    ffgemm_kernel<FFM_K><<<dim3(DIMC/64, M1/64), 256>>>(ph, phlo, qkvw, qkvb, pkffh, pkffl);
    ffgemm_kernel<FFM_Q><<<dim3(DIMC/64, (BATCH*LTN)/64), 256>>>(ph, phlo, qkvw, qkvb, pqffh, pqffl);
    // 4. ff logits -> double  (SACRED)
    ffqk_kernel<<<dim3(BATCH*HEADS, NTOK/64), 256, SMEM_FFQK>>>(pqffh, pqffl, pkffh, pkffl, pL);
    // 5. exact scores + V2 emulation, V1 emulation, reductions  (SACRED)
    score_soft_kernel<<<dim3(BATCH, HEADS), 256>>>(pL, pspartd, pspartf2);
    score_emul4_kernel<<<dim3(BATCH, HEADS), 256>>>(pq, pk, pspartf1);
    score_reduce_kernel<<<BATCH, 512>>>(pspartd, pspartf1, pspartf2, pdscore, psv1, psv2);
    // 6. main attention (attn output, fp32)
    attn_softmax_kernel<<<dim3(BATCH*HEADS, NTOK/32), 256, SMEM_ATTN>>>(pq, pk, attn_out);
    // 7. PV (fp32)
    attn_pv_kernel<<<dim3(BATCH*HEADS, NTOK/64), 256>>>(attn_out, pv, pxa);
    // 8. proj + residual -> tf32 tensor cores (x-path only, 1e-3 tol)
    tf32gemm_kernel<TEPI_PROJ><<<dim3(DIMC/128, M1/128), 256>>>(
        pxa, projw, projb, x, px1, M1, DIMC, DIMC);
    // 9. exact sort + intersection-of-emulations swap -> emit  (SACRED)
    sort_flag_kernel<<<dim3(BATCH, 2), 256>>>(pdscore, psv1, psv2, porder);
    emit_kernel<<<dim3(BATCH, 2), 256>>>(porder, gips, gis, out, ptopps, ptops);
    idx_copy_kernel<<<(BATCH*LTN + 255)/256, 256>>>(git, out);
    // 10. gather + LN2
    gather_ln2_kernel<<<dim3(NKEEP, BATCH), 256>>>(px1, ptopps, ptops, ln2w, ln2b, pxn, phn);
    // 11. MLP -> tf32 tensor cores (x-path only)
    tf32gemm_kernel<TEPI_GELU><<<dim3(HID/128, M2/128), 256>>>(
        phn, fc1w, fc1b, nullptr, pact, M2, HID, DIMC);
    tf32gemm_kernel<TEPI_OUT><<<dim3(DIMC/128, M2/128), 256>>>(
        pact, fc2w, fc2b, pxn, out, M2, DIMC, HID);
}

// round 13
// speedup vs baseline: 1.3590x; 1.1168x over previous
#include <cuda_runtime.h>

// ---------------- problem constants ----------------
#define BATCH  32
#define NTOK   576
#define DIMC   768
#define HEADS  12
#define HD     64
#define LTN    64
#define LSN    256
#define KEEPN  180
#define REMN   76
#define NKEEP  424
#define HID    3072

#define M1     (BATCH*NTOK)   // 18432
#define M2     (BATCH*NKEEP)  // 13568

// output layout (flattened tuple, float32, reference order)
#define GIT_OFF      10420224
#define KEEP_PS_OFF  10422272
#define KEEP_S_OFF   10428032
#define REM_PS_OFF   10433792
#define REM_S_OFF    10436224
#define ATTN_OFF     10438656

// ---------------- device scratch ----------------
__device__ __align__(16) float g_h  [M1*DIMC];
__device__ __align__(16) float g_hlo[M1*DIMC];
__device__ __align__(16) float g_q  [M1*DIMC];
__device__ __align__(16) float g_k  [M1*DIMC];
__device__ __align__(16) float g_v  [M1*DIMC];
__device__ __align__(16) float g_xa [M1*DIMC];
__device__ __align__(16) float g_x1 [M1*DIMC];
__device__ __align__(16) float g_xn [M2*DIMC];
__device__ __align__(16) float g_hn [M2*DIMC];
__device__ __align__(16) float g_act[(size_t)M2*HID];
__device__ __align__(16) float g_kffh[M1*DIMC];
__device__ __align__(16) float g_kffl[M1*DIMC];
__device__ __align__(16) float g_qffh[BATCH*HEADS*LTN*HD];
__device__ __align__(16) float g_qffl[BATCH*HEADS*LTN*HD];
__device__ __align__(16) double g_L[(size_t)BATCH*HEADS*LTN*NTOK];
__device__ __align__(16) double g_spartd [(size_t)BATCH*HEADS*512];
__device__ __align__(16) float  g_spartf2[(size_t)BATCH*HEADS*512];
__device__ __align__(16) float  g_spartf1[(size_t)BATCH*HEADS*512];
__device__ __align__(16) double g_dscore[BATCH*2*LSN];
__device__ __align__(16) float  g_sv1[BATCH*2*LSN];
__device__ __align__(16) float  g_sv2[BATCH*2*LSN];
__device__ __align__(16) int    g_order[64*LSN];
__device__ __align__(16) int    g_top_ps[BATCH*LSN];
__device__ __align__(16) int    g_top_s [BATCH*LSN];

// ---------------- packed f32x2 helpers (per-lane IEEE rn) ----
typedef unsigned long long ull;
__device__ __forceinline__ ull pk2(float lo, float hi) {
    ull r;
    asm("mov.b64 %0, {%1, %2};" : "=l"(r)
        : "r"(__float_as_uint(lo)), "r"(__float_as_uint(hi)));
    return r;
}
__device__ __forceinline__ ull dup2(float v) { return pk2(v, v); }
__device__ __forceinline__ void upk2(ull v, float& lo, float& hi) {
    unsigned a, b;
    asm("mov.b64 {%0, %1}, %2;" : "=r"(a), "=r"(b) : "l"(v));
    lo = __uint_as_float(a); hi = __uint_as_float(b);
}
__device__ __forceinline__ ull fma2(ull a, ull b, ull c) {
    ull d; asm("fma.rn.f32x2 %0, %1, %2, %3;" : "=l"(d) : "l"(a), "l"(b), "l"(c));
    return d;
}
__device__ __forceinline__ ull add2(ull a, ull b) {
    ull d; asm("add.rn.f32x2 %0, %1, %2;" : "=l"(d) : "l"(a), "l"(b));
    return d;
}
__device__ __forceinline__ ull mul2(ull a, ull b) {
    ull d; asm("mul.rn.f32x2 %0, %1, %2;" : "=l"(d) : "l"(a), "l"(b));
    return d;
}
__device__ __forceinline__ ull neg2(ull a) {
    const ull m = 0x8000000080000000ULL;
    ull d; asm("xor.b64 %0, %1, %2;" : "=l"(d) : "l"(a), "l"(m));
    return d;
}
__device__ __forceinline__ unsigned f2tf(float f) {
    unsigned r; asm("cvt.rna.tf32.f32 %0, %1;" : "=r"(r) : "f"(f));
    return r;
}

// ---------------- ff (double-single) helpers ----------------
__device__ __forceinline__ void ts2(float a, float b, float& s, float& e) {
    s = a + b;
    float z = s - a;
    e = (a - (s - z)) + (b - z);
}
__device__ __forceinline__ void ffacc_f(float& h, float& l, float v) {
    float s, e; ts2(h, v, s, e); h = s; l += e;
}
__device__ __forceinline__ void ffacc_p(float& h, float& l, float a, float b) {
    float p = a * b;
    float e = fmaf(a, b, -p);
    float s, er; ts2(h, p, s, er);
    h = s; l += er + e;
}
__device__ __forceinline__ void ffadd(float& h, float& l, float bh2, float bl2) {
    float s, e; ts2(h, bh2, s, e);
    e += l + bl2;
    h = s + e;
    l = e - (h - s);
}

__device__ __forceinline__ float gelu_exact(float v) {
    return 0.5f * v * (1.0f + erff(v * 0.70710678118654752f));
}

// ---------------- LN1 in ff: writes h_hi (main path) + h_lo ----------------
__global__ __launch_bounds__(256)
void ln_ff_kernel(const float* __restrict__ X, const float* __restrict__ w,
                  const float* __restrict__ bia, float* __restrict__ Yh,
                  float* __restrict__ Yl)
{
    __shared__ float sh[8], slo[8], sqh[8], sql[8];
    __shared__ double sm_mean, sm_inv;
    int row = blockIdx.x;
    const float* xr = X + (size_t)row * DIMC;
    int t = threadIdx.x;
    float x0 = xr[t], x1 = xr[t+256], x2 = xr[t+512];
    float sH = 0.f, sL = 0.f, qH = 0.f, qL = 0.f;
    ffacc_f(sH, sL, x0); ffacc_f(sH, sL, x1); ffacc_f(sH, sL, x2);
    ffacc_p(qH, qL, x0, x0); ffacc_p(qH, qL, x1, x1); ffacc_p(qH, qL, x2, x2);
    int lane = t & 31, warp = t >> 5;
    #pragma unroll
    for (int o = 16; o; o >>= 1) {
        float oh = __shfl_xor_sync(0xffffffffu, sH, o);
        float ol = __shfl_xor_sync(0xffffffffu, sL, o);
        ffadd(sH, sL, oh, ol);
        oh = __shfl_xor_sync(0xffffffffu, qH, o);
        ol = __shfl_xor_sync(0xffffffffu, qL, o);
        ffadd(qH, qL, oh, ol);
    }
    if (lane == 0) { sh[warp]=sH; slo[warp]=sL; sqh[warp]=qH; sql[warp]=qL; }
    __syncthreads();
    if (t == 0) {
        double ms = 0.0, mq = 0.0;
        #pragma unroll
        for (int i = 0; i < 8; i++) {
            ms += (double)sh[i] + (double)slo[i];
            mq += (double)sqh[i] + (double)sql[i];
        }
        double mean = ms / 768.0;
        double var  = mq / 768.0 - mean*mean;
        sm_mean = mean;
        sm_inv  = 1.0 / sqrt(var + 1e-5);
    }
    __syncthreads();
    double mean = sm_mean, inv = sm_inv;
    float mh = (float)mean, ml = (float)(mean - (double)mh);
    float ih = (float)inv,  il = (float)(inv  - (double)ih);
    #pragma unroll
    for (int rep = 0; rep < 3; rep++) {
        int c = t + rep*256;
        float xv = (rep==0)?x0:((rep==1)?x1:x2);
        float wv = w[c], bv = bia[c];
        float th, tl; ts2(xv, -mh, th, tl); tl -= ml;
        float ph = th * ih;
        float pl = fmaf(th, ih, -ph);
        pl += th*il + tl*ih;
        float uh = ph * wv;
        float ul = fmaf(ph, wv, -uh);
        ul = fmaf(pl, wv, ul);
        float rh, rl; ts2(uh, bv, rh, rl); rl += ul;
        float oh = rh + rl;
        float ol = rl - (oh - rh);
        Yh[(size_t)row*DIMC + c] = oh;
        Yl[(size_t)row*DIMC + c] = ol;
    }
}

// ---------------- ff GEMM (packed f32x2, Kahan compensation) ----------
#define FFM_K 0
#define FFM_Q 1

template<int MODE>
__global__ __launch_bounds__(256)
void ffgemm_kernel(const float* __restrict__ Ah, const float* __restrict__ Al,
                   const float* __restrict__ W, const float* __restrict__ bias,
                   float* __restrict__ Ch, float* __restrict__ Cl)
{
    __shared__ float Ash[16*68], Asl[16*68], Ws[16*68];
    const int tid = threadIdx.x;
    const int tx = tid & 15, ty = tid >> 4;
    const int m0 = blockIdx.y * 64;
    const int n0 = blockIdx.x * 64;
    const int wrow0 = (MODE == FFM_K) ? 768 : 0;
    const ull NEG1 = dup2(-1.0f);
    ull sS[4][2], cC[4][2];
    #pragma unroll
    for (int i = 0; i < 4; i++)
        #pragma unroll
        for (int j = 0; j < 2; j++) { sS[i][j] = 0ULL; cC[i][j] = 0ULL; }

    const int lrow = tid >> 2;
    const int lc4  = (tid & 3) * 4;
    int arow;
    if (MODE == FFM_Q) { int m = m0 + lrow; arow = (m >> 6)*NTOK + (m & 63); }
    else               arow = m0 + lrow;

    for (int k0 = 0; k0 < DIMC; k0 += 16) {
        float4 vh = *(const float4*)(Ah + (size_t)arow*DIMC + k0 + lc4);
        float4 vl = *(const float4*)(Al + (size_t)arow*DIMC + k0 + lc4);
        float4 vw = *(const float4*)(W + (size_t)(wrow0 + n0 + lrow)*DIMC + k0 + lc4);
        Ash[(lc4+0)*68+lrow]=vh.x; Ash[(lc4+1)*68+lrow]=vh.y; Ash[(lc4+2)*68+lrow]=vh.z; Ash[(lc4+3)*68+lrow]=vh.w;
        Asl[(lc4+0)*68+lrow]=vl.x; Asl[(lc4+1)*68+lrow]=vl.y; Asl[(lc4+2)*68+lrow]=vl.z; Asl[(lc4+3)*68+lrow]=vl.w;
        Ws [(lc4+0)*68+lrow]=vw.x; Ws [(lc4+1)*68+lrow]=vw.y; Ws [(lc4+2)*68+lrow]=vw.z; Ws [(lc4+3)*68+lrow]=vw.w;
        __syncthreads();
        #pragma unroll
        for (int kk = 0; kk < 16; kk++) {
            float4 ah4 = *(const float4*)&Ash[kk*68 + ty*4];
            float4 al4 = *(const float4*)&Asl[kk*68 + ty*4];
            ulonglong2 wq = *(const ulonglong2*)&Ws[kk*68 + tx*4];
            ull wp[2] = {wq.x, wq.y};
            float ahv[4] = {ah4.x, ah4.y, ah4.z, ah4.w};
            float alv[4] = {al4.x, al4.y, al4.z, al4.w};
            #pragma unroll
            for (int i = 0; i < 4; i++) {
                ull ahd = dup2(ahv[i]);
                ull ald = dup2(alv[i]);
                #pragma unroll
                for (int j2 = 0; j2 < 2; j2++) {
                    // exact product: p + e
                    ull p2 = mul2(ahd, wp[j2]);
                    ull e2 = fma2(ahd, wp[j2], neg2(p2));
                    e2 = fma2(ald, wp[j2], e2);
                    // Kahan: y = p - c; t = s + y; c = ((t-s) - y) - e; s = t
                    ull y2 = fma2(cC[i][j2], NEG1, p2);
                    ull t2 = add2(sS[i][j2], y2);
                    ull d2 = fma2(sS[i][j2], NEG1, t2);
                    ull cn = fma2(y2, NEG1, d2);
                    cC[i][j2] = fma2(e2, NEG1, cn);
                    sS[i][j2] = t2;
                }
            }
        }
        __syncthreads();
    }

    #pragma unroll
    for (int i = 0; i < 4; i++) {
        float aH[4], aC[4];
        upk2(sS[i][0], aH[0], aH[1]); upk2(sS[i][1], aH[2], aH[3]);
        upk2(cC[i][0], aC[0], aC[1]); upk2(cC[i][1], aC[2], aC[3]);
        int m = m0 + ty*4 + i;
        float4 rh, rl;
        float* ph = &rh.x; float* pl = &rl.x;
        #pragma unroll
        for (int j = 0; j < 4; j++) {
            int col = n0 + tx*4 + j;
            float hi = aH[j], lo = -aC[j];   // true sum = s - c
            float h2 = hi + lo;
            float l2 = lo - (h2 - hi);
            float bv = bias[wrow0 + col];
            float s, e; ts2(h2, bv, s, e); e += l2;
            float oh = s + e;
            float ol = e - (oh - s);
            ph[j] = oh; pl[j] = ol;
        }
        int col0 = n0 + tx*4;
        int head = col0 >> 6, d = col0 & 63;
        size_t off;
        if (MODE == FFM_Q) {
            int b = m >> 6, q = m & 63;
            off = (((size_t)(b*HEADS + head))*LTN + q)*HD + d;
        } else {
            int b = m / NTOK, n = m - (m/NTOK)*NTOK;
            off = (((size_t)(b*HEADS + head))*NTOK + n)*HD + d;
        }
        *(float4*)&Ch[off] = rh;
        *(float4*)&Cl[off] = rl;
    }
}

// ---------------- ff QK^T -> double logits (packed f32x2, Kahan) ----------------
#define SMEM_FFQK (4*64*68*4)

__global__ __launch_bounds__(256)
void ffqk_kernel(const float* __restrict__ Qh, const float* __restrict__ Ql,
                 const float* __restrict__ Kh, const float* __restrict__ Kl,
                 double* __restrict__ Lg)
{
    extern __shared__ float smf[];
    float* sQh = smf;
    float* sQl = smf + 64*68;
    float* sKh = smf + 2*64*68;
    float* sKl = smf + 3*64*68;
    int bh = blockIdx.x, nt = blockIdx.y;
    int tid = threadIdx.x;
    int tx = tid & 15, ty = tid >> 4;
    size_t qbase = (size_t)bh * LTN * HD;
    size_t kbase = ((size_t)bh * NTOK + nt*64) * HD;
    const ull NEG1 = dup2(-1.0f);

    for (int l = tid; l < 1024; l += 256) {
        int row = l >> 4, c4 = (l & 15) * 4;
        float4 a = *(const float4*)&Qh[qbase + (size_t)row*HD + c4];
        float4 b = *(const float4*)&Ql[qbase + (size_t)row*HD + c4];
        float4 c = *(const float4*)&Kh[kbase + (size_t)row*HD + c4];
        float4 d = *(const float4*)&Kl[kbase + (size_t)row*HD + c4];
        sQh[(c4+0)*68+row]=a.x; sQh[(c4+1)*68+row]=a.y; sQh[(c4+2)*68+row]=a.z; sQh[(c4+3)*68+row]=a.w;
        sQl[(c4+0)*68+row]=b.x; sQl[(c4+1)*68+row]=b.y; sQl[(c4+2)*68+row]=b.z; sQl[(c4+3)*68+row]=b.w;
        sKh[(c4+0)*68+row]=c.x; sKh[(c4+1)*68+row]=c.y; sKh[(c4+2)*68+row]=c.z; sKh[(c4+3)*68+row]=c.w;
        sKl[(c4+0)*68+row]=d.x; sKl[(c4+1)*68+row]=d.y; sKl[(c4+2)*68+row]=d.z; sKl[(c4+3)*68+row]=d.w;
    }
    __syncthreads();
    ull sS[4][2], cC[4][2];
    #pragma unroll
    for (int i = 0; i < 4; i++)
        #pragma unroll
        for (int j = 0; j < 2; j++) { sS[i][j]=0ULL; cC[i][j]=0ULL; }
    for (int d = 0; d < 64; d++) {
        float4 qh4 = *(const float4*)&sQh[d*68 + ty*4];
        float4 ql4 = *(const float4*)&sQl[d*68 + ty*4];
        ulonglong2 khq = *(const ulonglong2*)&sKh[d*68 + tx*4];
        ulonglong2 klq = *(const ulonglong2*)&sKl[d*68 + tx*4];
        ull khp[2] = {khq.x, khq.y};
        ull klp[2] = {klq.x, klq.y};
        float qh[4]={qh4.x,qh4.y,qh4.z,qh4.w}, ql[4]={ql4.x,ql4.y,ql4.z,ql4.w};
        #pragma unroll
        for (int i = 0; i < 4; i++) {
            ull qhd = dup2(qh[i]);
            ull qld = dup2(ql[i]);
            #pragma unroll
            for (int j2 = 0; j2 < 2; j2++) {
                ull p2 = mul2(qhd, khp[j2]);
                ull e2 = fma2(qhd, khp[j2], neg2(p2));
                e2 = fma2(qhd, klp[j2], e2);
                e2 = fma2(qld, khp[j2], e2);
                ull y2 = fma2(cC[i][j2], NEG1, p2);
                ull t2 = add2(sS[i][j2], y2);
                ull d2 = fma2(sS[i][j2], NEG1, t2);
                ull cn = fma2(y2, NEG1, d2);
                cC[i][j2] = fma2(e2, NEG1, cn);
                sS[i][j2] = t2;
            }
        }
    }
    #pragma unroll
    for (int i = 0; i < 4; i++) {
        float aH[4], aC[4];
        upk2(sS[i][0], aH[0], aH[1]); upk2(sS[i][1], aH[2], aH[3]);
        upk2(cC[i][0], aC[0], aC[1]); upk2(cC[i][1], aC[2], aC[3]);
        int q = ty*4 + i;
        #pragma unroll
        for (int j = 0; j < 4; j++) {
            int key = nt*64 + tx*4 + j;
            Lg[((size_t)bh*LTN + q)*NTOK + key] =
                ((double)aH[j] - (double)aC[j]) * 0.125;
        }
    }
}

// ---------------- exact double softmax + key sums; also V2 fp32-emulated sums ----------------
__global__ __launch_bounds__(256)
void score_soft_kernel(const double* __restrict__ Lg, double* __restrict__ spartd,
                       float* __restrict__ spartf2)
{
    __shared__ double sl[NTOK];
    __shared__ double sred[16];
    int b = blockIdx.x, h = blockIdx.y;
    int bh = b*HEADS + h;
    const double* L = Lg + (size_t)bh * LTN * NTOK;
    int t = threadIdx.x;
    int lane = t & 31, warp = t >> 5;
    double acc0 = 0.0, acc1 = 0.0;
    float  f0 = 0.f,   f1 = 0.f;

    for (int q = 0; q < LTN; q++) {
        __syncthreads();
        const double* lq = L + (size_t)q * NTOK;
        double m = lq[t];
        m = fmax(m, lq[t+256]);
        if (t < 64) m = fmax(m, lq[t+512]);
        #pragma unroll
        for (int o = 16; o; o >>= 1) m = fmax(m, __shfl_xor_sync(0xffffffffu, m, o));
        if (lane == 0) sred[warp] = m;
        __syncthreads();
        if (t < 32) {
            double mm = (lane < 8) ? sred[lane] : -1e300;
            #pragma unroll
            for (int o = 4; o; o >>= 1) mm = fmax(mm, __shfl_xor_sync(0xffffffffu, mm, o));
            if (lane == 0) sred[0] = mm;
        }
        __syncthreads();
        m = sred[0];
        double sum = 0.0;
        {
            double p = exp(lq[t] - m);       sl[t] = p;       sum += p;
            p = exp(lq[t+256] - m);          sl[t+256] = p;   sum += p;
            if (t < 64) { p = exp(lq[t+512] - m); sl[t+512] = p; sum += p; }
        }
        #pragma unroll
        for (int o = 16; o; o >>= 1) sum += __shfl_xor_sync(0xffffffffu, sum, o);
        if (lane == 0) sred[8+warp] = sum;
        __syncthreads();
        if (t < 32) {
            double ss = (lane < 8) ? sred[8+lane] : 0.0;
            #pragma unroll
            for (int o = 4; o; o >>= 1) ss += __shfl_xor_sync(0xffffffffu, ss, o);
            if (lane == 0) sred[8] = ss;
        }
        __syncthreads();
        double inv = 1.0 / sred[8];
        double a0 = sl[64  + t] * inv;
        double a1 = sl[320 + t] * inv;
        acc0 += a0;
        acc1 += a1;
        f0 += (float)a0;
        f1 += (float)a1;
    }
    spartd[(size_t)bh*512 + t]        = acc0;
    spartd[(size_t)bh*512 + 256 + t]  = acc1;
    spartf2[(size_t)bh*512 + t]       = f0 / 64.0f;
    spartf2[(size_t)bh*512 + 256 + t] = f1 / 64.0f;
}

// ---------------- V1: R4-style fp32-emulated score from main fp32 q/k ----------------
__global__ __launch_bounds__(256)
void score_emul4_kernel(const float* __restrict__ Q, const float* __restrict__ K,
                        float* __restrict__ spartf1)
{
    __shared__ float sq[64];
    __shared__ float sl[NTOK];
    __shared__ float sred[16];
    int b = blockIdx.x, h = blockIdx.y;
    int bh = b*HEADS + h;
    size_t base = (size_t)bh * NTOK * HD;
    int t = threadIdx.x;
    int lane = t & 31, warp = t >> 5;
    float acc0 = 0.f, acc1 = 0.f;

    for (int q = 0; q < LTN; q++) {
        __syncthreads();
        if (t < 16)
            *(float4*)&sq[t*4] = *(const float4*)&Q[base + (size_t)q*HD + t*4];
        __syncthreads();
        #pragma unroll
        for (int rep = 0; rep < 3; rep++) {
            int j = t + rep*256;
            if (j < NTOK) {
                const float* kr = &K[base + (size_t)j*HD];
                float s0=0.f, s1=0.f, s2=0.f, s3=0.f;
                #pragma unroll
                for (int d = 0; d < 64; d += 4) {
                    s0 = fmaf(sq[d+0], kr[d+0], s0);
                    s1 = fmaf(sq[d+1], kr[d+1], s1);
                    s2 = fmaf(sq[d+2], kr[d+2], s2);
                    s3 = fmaf(sq[d+3], kr[d+3], s3);
                }
                sl[j] = ((s0+s1)+(s2+s3)) * 0.125f;
            }
        }
        __syncthreads();
        float m = -3.4e38f;
        m = fmaxf(m, sl[t]);
        m = fmaxf(m, sl[t+256]);
        if (t < 64) m = fmaxf(m, sl[t+512]);
        #pragma unroll
        for (int o = 16; o; o >>= 1) m = fmaxf(m, __shfl_xor_sync(0xffffffffu, m, o));
        if (lane == 0) sred[warp] = m;
        __syncthreads();
        if (t < 32) {
            float mm = (lane < 8) ? sred[lane] : -3.4e38f;
            #pragma unroll
            for (int o = 4; o; o >>= 1) mm = fmaxf(mm, __shfl_xor_sync(0xffffffffu, mm, o));
            if (lane == 0) sred[0] = mm;
        }
        __syncthreads();
        m = sred[0];
        #pragma unroll
        for (int rep = 0; rep < 3; rep++) {
            int j = t + rep*256;
            if (j < NTOK) {
                float d = sl[j] - m;
                sl[j] = (float)exp((double)d);
            }
        }
        __syncthreads();
        float ls = sl[t] + sl[t+256];
        if (t < 64) ls += sl[t+512];
        #pragma unroll
        for (int o = 16; o; o >>= 1) ls += __shfl_xor_sync(0xffffffffu, ls, o);
        if (lane == 0) sred[8+warp] = ls;
        __syncthreads();
        if (t < 32) {
            float ss = (lane < 8) ? sred[8+lane] : 0.f;
            #pragma unroll
            for (int o = 4; o; o >>= 1) ss += __shfl_xor_sync(0xffffffffu, ss, o);
            if (lane == 0) sred[8] = ss;
        }
        __syncthreads();
        float S = sred[8];
        acc0 += sl[64  + t] / S;
        acc1 += sl[320 + t] / S;
    }
    spartf1[(size_t)bh*512 + t]       = acc0 / 64.0f;
    spartf1[(size_t)bh*512 + 256 + t] = acc1 / 64.0f;
}

// ---------------- reductions: exact(double), V1(fp32 seq), V2(fp32 seq) ----------------
__global__ __launch_bounds__(512)
void score_reduce_kernel(const double* __restrict__ spartd,
                         const float* __restrict__ spartf1,
                         const float* __restrict__ spartf2,
                         double* __restrict__ dscore,
                         float* __restrict__ sv1, float* __restrict__ sv2)
{
    int b = blockIdx.x;
    int j = threadIdx.x;
    double s = 0.0;
    float e1 = 0.f, e2 = 0.f;
    #pragma unroll
    for (int h = 0; h < HEADS; h++) {
        size_t o = (size_t)(b*HEADS + h)*512 + j;
        s  += spartd[o] / 64.0;
        e1 += spartf1[o];
        e2 += spartf2[o];
    }
    dscore[b*2*LSN + j] = s / 12.0;
    sv1[b*2*LSN + j] = e1 / 12.0f;
    sv2[b*2*LSN + j] = e2 / 12.0f;
}

// ---------------- main-path fp32 SGEMM (packed f32x2) — QKV only (SACRED) ----
#define EPI_QKV  0

template<int EPI>
__global__ __launch_bounds__(256)
void sgemm_nt(const float* __restrict__ A, const float* __restrict__ Bw,
              const float* __restrict__ bias, const float* __restrict__ res,
              float* __restrict__ Cq, float* __restrict__ Ck, float* __restrict__ Cv,
              float* __restrict__ Cc, int M, int N, int K)
{
    __shared__ float As[16][132];
    __shared__ float Bs[16][132];
    const int tid = threadIdx.x;
    const int tx = tid & 15;
    const int ty = tid >> 4;
    const int m0 = blockIdx.y * 128;
    const int n0 = blockIdx.x * 128;
    ull acc2[8][4];
    #pragma unroll
    for (int i = 0; i < 8; i++)
        #pragma unroll
        for (int j = 0; j < 4; j++) acc2[i][j] = 0ULL;

    const int lrow = tid >> 2;
    const int lc4  = (tid & 3) * 4;

    for (int k0 = 0; k0 < K; k0 += 16) {
        #pragma unroll
        for (int half = 0; half < 2; half++) {
            int row = lrow + half*64;
            float4 va = *(const float4*)(A  + (size_t)(m0+row)*K + k0 + lc4);
            As[lc4+0][row]=va.x; As[lc4+1][row]=va.y; As[lc4+2][row]=va.z; As[lc4+3][row]=va.w;
            float4 vb = *(const float4*)(Bw + (size_t)(n0+row)*K + k0 + lc4);
            Bs[lc4+0][row]=vb.x; Bs[lc4+1][row]=vb.y; Bs[lc4+2][row]=vb.z; Bs[lc4+3][row]=vb.w;
        }
        __syncthreads();
        #pragma unroll
        for (int kk = 0; kk < 16; kk++) {
            float4 a0 = *(const float4*)&As[kk][ty*4];
            float4 a1 = *(const float4*)&As[kk][64 + ty*4];
            ulonglong2 b01 = *(const ulonglong2*)&Bs[kk][tx*4];
            ulonglong2 b23 = *(const ulonglong2*)&Bs[kk][64 + tx*4];
            ull bp0 = b01.x, bp1 = b01.y, bp2 = b23.x, bp3 = b23.y;
            float av[8] = {a0.x,a0.y,a0.z,a0.w,a1.x,a1.y,a1.z,a1.w};
            #pragma unroll
            for (int i = 0; i < 8; i++) {
                ull ad = dup2(av[i]);
                acc2[i][0] = fma2(ad, bp0, acc2[i][0]);
                acc2[i][1] = fma2(ad, bp1, acc2[i][1]);
                acc2[i][2] = fma2(ad, bp2, acc2[i][2]);
                acc2[i][3] = fma2(ad, bp3, acc2[i][3]);
            }
        }
        __syncthreads();
    }

    #pragma unroll
    for (int i = 0; i < 8; i++) {
        float accf[8];
        upk2(acc2[i][0], accf[0], accf[1]);
        upk2(acc2[i][1], accf[2], accf[3]);
        upk2(acc2[i][2], accf[4], accf[5]);
        upk2(acc2[i][3], accf[6], accf[7]);
        int rloc = (i < 4) ? (ty*4 + i) : (64 + ty*4 + i - 4);
        int row = m0 + rloc;
        #pragma unroll
        for (int jq = 0; jq < 2; jq++) {
            int col = n0 + jq*64 + tx*4;
            float4 r;
            r.x = accf[jq*4+0] + bias[col+0];
            r.y = accf[jq*4+1] + bias[col+1];
            r.z = accf[jq*4+2] + bias[col+2];
            r.w = accf[jq*4+3] + bias[col+3];
            int which = col / 768;
            int rem   = col - which*768;
            int head  = rem >> 6;
            int dd    = rem & 63;
            int bb    = row / NTOK;
            int nt    = row - bb*NTOK;
            float* targ = (which == 0) ? Cq : ((which == 1) ? Ck : Cv);
            *(float4*)&targ[(((size_t)(bb*HEADS + head))*NTOK + nt)*HD + dd] = r;
        }
    }
}

// ---------------- tf32 tensor-core GEMM (proj / fc1 / fc2; 1e-3 tolerance path) ----
#define TEPI_PROJ 0
#define TEPI_GELU 1
#define TEPI_OUT  2

template<int EPI>
__global__ __launch_bounds__(256)
void tf32gemm_kernel(const float* __restrict__ A, const float* __restrict__ Bw,
                     const float* __restrict__ bias, const float* __restrict__ res,
                     float* __restrict__ C, int M, int N, int K)
{
    __shared__ unsigned As[128*36];
    __shared__ unsigned Bs[128*36];
    const int tid = threadIdx.x;
    const int warp = tid >> 5, lane = tid & 31;
    const int wr = warp >> 2, wc = warp & 3;
    const int g = lane >> 2, t = lane & 3;
    const int m0 = blockIdx.y * 128, n0 = blockIdx.x * 128;
    const int lr = tid >> 3;
    const int lk = (tid & 7) * 4;

    float acc[4][4][4];
    #pragma unroll
    for (int i = 0; i < 4; i++)
        #pragma unroll
        for (int j = 0; j < 4; j++)
            #pragma unroll
            for (int r = 0; r < 4; r++) acc[i][j][r] = 0.f;

    float4 pa[4], pb[4];
    #pragma unroll
    for (int p = 0; p < 4; p++) {
        pa[p] = *(const float4*)(A  + (size_t)(m0 + p*32 + lr)*K + lk);
        pb[p] = *(const float4*)(Bw + (size_t)(n0 + p*32 + lr)*K + lk);
    }

    for (int k0 = 0; k0 < K; k0 += 32) {
        __syncthreads();
        #pragma unroll
        for (int p = 0; p < 4; p++) {
            int m = p*32 + lr;
            As[m*36+lk+0]=f2tf(pa[p].x); As[m*36+lk+1]=f2tf(pa[p].y);
            As[m*36+lk+2]=f2tf(pa[p].z); As[m*36+lk+3]=f2tf(pa[p].w);
            Bs[m*36+lk+0]=f2tf(pb[p].x); Bs[m*36+lk+1]=f2tf(pb[p].y);
            Bs[m*36+lk+2]=f2tf(pb[p].z); Bs[m*36+lk+3]=f2tf(pb[p].w);
        }
        __syncthreads();
        if (k0 + 32 < K) {
            #pragma unroll
            for (int p = 0; p < 4; p++) {
                pa[p] = *(const float4*)(A  + (size_t)(m0 + p*32 + lr)*K + k0 + 32 + lk);
                pb[p] = *(const float4*)(Bw + (size_t)(n0 + p*32 + lr)*K + k0 + 32 + lk);
            }
        }
        #pragma unroll
        for (int ks = 0; ks < 32; ks += 8) {
            unsigned af[4][4], bf[4][2];
            #pragma unroll
            for (int i = 0; i < 4; i++) {
                int row = wr*64 + i*16 + g;
                af[i][0] = As[row*36 + ks + t];
                af[i][1] = As[(row+8)*36 + ks + t];
                af[i][2] = As[row*36 + ks + t + 4];
                af[i][3] = As[(row+8)*36 + ks + t + 4];
            }
            #pragma unroll
            for (int j = 0; j < 4; j++) {
                int n = wc*32 + j*8 + g;
                bf[j][0] = Bs[n*36 + ks + t];
                bf[j][1] = Bs[n*36 + ks + t + 4];
            }
            #pragma unroll
            for (int i = 0; i < 4; i++)
                #pragma unroll
                for (int j = 0; j < 4; j++)
                    asm volatile(
                        "mma.sync.aligned.m16n8k8.row.col.f32.tf32.tf32.f32 "
                        "{%0,%1,%2,%3}, {%4,%5,%6,%7}, {%8,%9}, {%0,%1,%2,%3};"
                        : "+f"(acc[i][j][0]), "+f"(acc[i][j][1]),
                          "+f"(acc[i][j][2]), "+f"(acc[i][j][3])
                        : "r"(af[i][0]), "r"(af[i][1]), "r"(af[i][2]), "r"(af[i][3]),
                          "r"(bf[j][0]), "r"(bf[j][1]));
        }
    }

    #pragma unroll
    for (int i = 0; i < 4; i++) {
        int r0 = m0 + wr*64 + i*16 + g;
        #pragma unroll
        for (int j = 0; j < 4; j++) {
            int c0 = n0 + wc*32 + j*8 + 2*t;
            float b0v = bias[c0], b1v = bias[c0+1];
            float v00 = acc[i][j][0] + b0v, v01 = acc[i][j][1] + b1v;
            float v10 = acc[i][j][2] + b0v, v11 = acc[i][j][3] + b1v;
            size_t o0 = (size_t)r0*N + c0;
            size_t o1 = (size_t)(r0+8)*N + c0;
            if constexpr (EPI == TEPI_GELU) {
                v00 = gelu_exact(v00); v01 = gelu_exact(v01);
                v10 = gelu_exact(v10); v11 = gelu_exact(v11);
            } else {
                float2 r0v = *(const float2*)&res[o0];
                float2 r1v = *(const float2*)&res[o1];
                v00 += r0v.x; v01 += r0v.y;
                v10 += r1v.x; v11 += r1v.y;
            }
            float2 w0; w0.x = v00; w0.y = v01;
            float2 w1; w1.x = v10; w1.y = v11;
            *(float2*)&C[o0] = w0;
            *(float2*)&C[o1] = w1;
        }
    }
}

// ---------------- attention (fp32 main path, packed f32x2 QK) ----------------
#define SK_PAD 68
#define SMEM_ATTN ((2048 + 64*SK_PAD + 32*577) * 4)

__global__ __launch_bounds__(256)
void attn_softmax_kernel(const float* __restrict__ Q, const float* __restrict__ Km,
                         float* __restrict__ attn_out)
{
    extern __shared__ float sm[];
    float* sQ = sm;
    float* sK = sm + 2048;
    float* sS = sm + 2048 + 64*SK_PAD;
    int bh = blockIdx.x;
    int qt = blockIdx.y;
    int tid = threadIdx.x;
    int tx = tid & 15, ty = tid >> 4;
    int q0 = qt * 32;
    size_t base = (size_t)bh * NTOK * HD;

    for (int l = tid; l < 512; l += 256) {
        int row = l >> 4, c4 = (l & 15) * 4;
        *(float4*)&sQ[row*64 + c4] = *(const float4*)&Q[base + (size_t)(q0+row)*HD + c4];
    }
    for (int kt = 0; kt < 9; kt++) {
        __syncthreads();
        for (int l = tid; l < 1024; l += 256) {
            int row = l >> 4, c4 = (l & 15) * 4;
            float4 v = *(const float4*)&Km[base + (size_t)(kt*64+row)*HD + c4];
            sK[(c4+0)*SK_PAD + row] = v.x;
            sK[(c4+1)*SK_PAD + row] = v.y;
            sK[(c4+2)*SK_PAD + row] = v.z;
            sK[(c4+3)*SK_PAD + row] = v.w;
        }
        __syncthreads();
        ull acc2[2][2] = {{0ULL,0ULL},{0ULL,0ULL}};
        #pragma unroll
        for (int d = 0; d < 64; d++) {
            float qa = sQ[(2*ty)*64 + d];
            float qb = sQ[(2*ty+1)*64 + d];
            ulonglong2 kq = *(const ulonglong2*)&sK[d*SK_PAD + tx*4];
            ull qad = dup2(qa), qbd = dup2(qb);
            acc2[0][0] = fma2(qad, kq.x, acc2[0][0]);
            acc2[0][1] = fma2(qad, kq.y, acc2[0][1]);
            acc2[1][0] = fma2(qbd, kq.x, acc2[1][0]);
            acc2[1][1] = fma2(qbd, kq.y, acc2[1][1]);
        }
        #pragma unroll
        for (int i2 = 0; i2 < 2; i2++) {
            float f0, f1, f2, f3;
            upk2(acc2[i2][0], f0, f1);
            upk2(acc2[i2][1], f2, f3);
            float* dst = &sS[(2*ty+i2)*577 + kt*64 + tx*4];
            dst[0] = f0 * 0.125f;
            dst[1] = f1 * 0.125f;
            dst[2] = f2 * 0.125f;
            dst[3] = f3 * 0.125f;
        }
    }
    __syncthreads();
    int warp = tid >> 5, lane = tid & 31;
    for (int r = warp*4; r < warp*4 + 4; r++) {
        float* srow = &sS[r*577];
        float m = -3.4e38f;
        for (int j = lane; j < NTOK; j += 32) m = fmaxf(m, srow[j]);
        #pragma unroll
        for (int o = 16; o; o >>= 1) m = fmaxf(m, __shfl_xor_sync(0xffffffffu, m, o));
        float s = 0.f;
        for (int j = lane; j < NTOK; j += 32) {
            float p = expf(srow[j] - m);
            srow[j] = p;
            s += p;
        }
        #pragma unroll
        for (int o = 16; o; o >>= 1) s += __shfl_xor_sync(0xffffffffu, s, o);
        size_t obase = ((size_t)bh*NTOK + q0 + r) * NTOK;
        for (int j = lane; j < NTOK; j += 32) attn_out[obase + j] = srow[j] / s;
    }
}

// ---------------- PV -> tf32 tensor cores (x-path only, 1e-3 tol) ----------------
__global__ __launch_bounds__(128)
void pv_tf32_kernel(const float* __restrict__ P, const float* __restrict__ V,
                    float* __restrict__ XA)
{
    __shared__ unsigned sP[64*36];
    __shared__ unsigned sVt[64*36];
    int bh = blockIdx.x, mt = blockIdx.y;
    int b = bh / HEADS, h = bh % HEADS;
    int tid = threadIdx.x;
    int warp = tid >> 5, lane = tid & 31;
    int g = lane >> 2, t = lane & 3;
    int m0 = mt * 64;
    size_t pbase = ((size_t)bh*NTOK + m0) * NTOK;
    size_t vbase = (size_t)bh * NTOK * HD;

    float acc[8][4];
    #pragma unroll
    for (int j = 0; j < 8; j++)
        #pragma unroll
        for (int r = 0; r < 4; r++) acc[j][r] = 0.f;

    for (int k0 = 0; k0 < NTOK; k0 += 32) {
        __syncthreads();
        // P tile: 64 rows x 32 k
        {
            int prow = tid >> 1;
            int pc0 = (tid & 1) * 16;
            #pragma unroll
            for (int c4 = 0; c4 < 16; c4 += 4) {
                float4 pv4 = *(const float4*)&P[pbase + (size_t)prow*NTOK + k0 + pc0 + c4];
                sP[prow*36 + pc0 + c4 + 0] = f2tf(pv4.x);
                sP[prow*36 + pc0 + c4 + 1] = f2tf(pv4.y);
                sP[prow*36 + pc0 + c4 + 2] = f2tf(pv4.z);
                sP[prow*36 + pc0 + c4 + 3] = f2tf(pv4.w);
            }
        }
        // V tile: 32 k-rows x 64 c, transposed into sVt[c][k]
        {
            int vrow = tid >> 2;
            int vc0 = (tid & 3) * 16;
            #pragma unroll
            for (int c4 = 0; c4 < 16; c4 += 4) {
                float4 vv4 = *(const float4*)&V[vbase + (size_t)(k0+vrow)*HD + vc0 + c4];
                sVt[(vc0+c4+0)*36 + vrow] = f2tf(vv4.x);
                sVt[(vc0+c4+1)*36 + vrow] = f2tf(vv4.y);
                sVt[(vc0+c4+2)*36 + vrow] = f2tf(vv4.z);
                sVt[(vc0+c4+3)*36 + vrow] = f2tf(vv4.w);
            }
        }
        __syncthreads();
        #pragma unroll
        for (int ks = 0; ks < 32; ks += 8) {
            unsigned af[4];
            int row = warp*16 + g;
            af[0] = sP[row*36 + ks + t];
            af[1] = sP[(row+8)*36 + ks + t];
            af[2] = sP[row*36 + ks + t + 4];
            af[3] = sP[(row+8)*36 + ks + t + 4];
            #pragma unroll
            for (int j = 0; j < 8; j++) {
                unsigned bf0 = sVt[(j*8+g)*36 + ks + t];
                unsigned bf1 = sVt[(j*8+g)*36 + ks + t + 4];
                asm volatile(
                    "mma.sync.aligned.m16n8k8.row.col.f32.tf32.tf32.f32 "
                    "{%0,%1,%2,%3}, {%4,%5,%6,%7}, {%8,%9}, {%0,%1,%2,%3};"
                    : "+f"(acc[j][0]), "+f"(acc[j][1]), "+f"(acc[j][2]), "+f"(acc[j][3])
                    : "r"(af[0]), "r"(af[1]), "r"(af[2]), "r"(af[3]),
                      "r"(bf0), "r"(bf1));
            }
        }
    }
    int q0r = m0 + warp*16 + g;
    #pragma unroll
    for (int j = 0; j < 8; j++) {
        int c0 = j*8 + 2*t;
        float2 w0; w0.x = acc[j][0]; w0.y = acc[j][1];
        float2 w1; w1.x = acc[j][2]; w1.y = acc[j][3];
        *(float2*)&XA[((size_t)b*NTOK + q0r)*DIMC + h*HD + c0] = w0;
        *(float2*)&XA[((size_t)b*NTOK + q0r + 8)*DIMC + h*HD + c0] = w1;
    }
}

// ---------------- sort (exact) + intersection-flag swap -> final order ----------------
__global__ __launch_bounds__(256)
void sort_flag_kernel(const double* __restrict__ dscore,
                      const float* __restrict__ sv1, const float* __restrict__ sv2,
                      int* __restrict__ order)
{
    __shared__ double sv[256];
    __shared__ int    si[256];
    __shared__ int    flg[256];
    int b = blockIdx.x, grp = blockIdx.y, tid = threadIdx.x;
    int group = b*2 + grp;
    int gbase = b*2*LSN + grp*LSN;
    sv[tid] = dscore[gbase + tid];
    si[tid] = tid;
    __syncthreads();
    for (int k = 2; k <= 256; k <<= 1) {
        for (int j = k >> 1; j > 0; j >>= 1) {
            int ixj = tid ^ j;
            if (ixj > tid) {
                double va = sv[tid], vb = sv[ixj];
                int    ia = si[tid], ib = si[ixj];
                bool a_first = (va > vb) || (va == vb && ia < ib);
                bool desc = ((tid & k) == 0);
                bool doswap = desc ? (!a_first) : a_first;
                if (doswap) { sv[tid]=vb; sv[ixj]=va; si[tid]=ib; si[ixj]=ia; }
            }
            __syncthreads();
        }
    }
    int f = 0;
    if (tid < 255) {
        int u = si[tid], v = si[tid+1];
        float a1 = sv1[gbase + u], b1 = sv1[gbase + v];
        float a2 = sv2[gbase + u], b2 = sv2[gbase + v];
        bool inv1 = (b1 > a1) || (b1 == a1 && v < u);
        bool inv2 = (b2 > a2) || (b2 == a2 && v < u);
        f = (inv1 && inv2) ? 1 : 0;
    }
    flg[tid] = f;
    __syncthreads();
    int fprev = (tid > 0) ? flg[tid-1] : 0;
    int src = flg[tid] ? tid+1 : (fprev ? tid-1 : tid);
    order[group*LSN + tid] = si[src];
}

__global__ __launch_bounds__(256)
void emit_kernel(const int* __restrict__ order,
                 const int* __restrict__ gi_ps, const int* __restrict__ gi_s,
                 float* __restrict__ out, int* __restrict__ top_ps,
                 int* __restrict__ top_s)
{
    int b = blockIdx.x, grp = blockIdx.y, tid = threadIdx.x;
    int group = b*2 + grp;
    int idx = order[group*LSN + tid];
    const int* gi = grp ? gi_s : gi_ps;
    float gval = (float)gi[b*LSN + idx];
    if (tid < KEEPN) {
        out[(grp ? KEEP_S_OFF : KEEP_PS_OFF) + b*KEEPN + tid] = gval;
        (grp ? top_s : top_ps)[b*LSN + tid] = idx;
    } else {
        out[(grp ? REM_S_OFF : REM_PS_OFF) + b*REMN + (tid - KEEPN)] = gval;
    }
}

__global__ void idx_copy_kernel(const int* __restrict__ git, float* __restrict__ out)
{
    int i = blockIdx.x*256 + threadIdx.x;
    if (i < BATCH*LTN) out[GIT_OFF + i] = (float)git[i];
}

// ---------------- gather kept tokens + LN2 ----------------
__global__ __launch_bounds__(256)
void gather_ln2_kernel(const float* __restrict__ X1, const int* __restrict__ topps,
                       const int* __restrict__ tops, const float* __restrict__ w,
                       const float* __restrict__ bia, float* __restrict__ XN,
                       float* __restrict__ HN)
{
    __shared__ float sb[16];
    int i = blockIdx.x;
    int b = blockIdx.y;
    int src;
    if (i < LTN)              src = i;
    else if (i < LTN + KEEPN) src = LTN + topps[b*LSN + (i - LTN)];
    else                      src = LTN + LSN + tops[b*LSN + (i - LTN - KEEPN)];
    const float* xr = X1 + ((size_t)b*NTOK + src) * DIMC;
    size_t ob = ((size_t)b*NKEEP + i) * DIMC;
    int t = threadIdx.x;
    float v0 = xr[t], v1 = xr[t+256], v2 = xr[t+512];
    XN[ob+t] = v0; XN[ob+t+256] = v1; XN[ob+t+512] = v2;
    float s = v0+v1+v2;
    float q = v0*v0 + v1*v1 + v2*v2;
    int lane = t & 31, warp = t >> 5;
    #pragma unroll
    for (int o = 16; o; o >>= 1) {
        s += __shfl_xor_sync(0xffffffffu, s, o);
        q += __shfl_xor_sync(0xffffffffu, q, o);
    }
    if (lane == 0) { sb[warp] = s; sb[8+warp] = q; }
    __syncthreads();
    if (t < 32) {
        float s2 = (lane < 8) ? sb[lane] : 0.f;
        float q2 = (lane < 8) ? sb[8+lane] : 0.f;
        #pragma unroll
        for (int o = 4; o; o >>= 1) {
            s2 += __shfl_xor_sync(0xffffffffu, s2, o);
            q2 += __shfl_xor_sync(0xffffffffu, q2, o);
        }
        if (lane == 0) { sb[0] = s2; sb[1] = q2; }
    }
    __syncthreads();
    float mean = sb[0] * (1.f/768.f);
    float var  = sb[1] * (1.f/768.f) - mean*mean;
    float inv  = rsqrtf(var + 1e-5f);
    HN[ob+t]     = (v0-mean)*inv*w[t]     + bia[t];
    HN[ob+t+256] = (v1-mean)*inv*w[t+256] + bia[t+256];
    HN[ob+t+512] = (v2-mean)*inv*w[t+512] + bia[t+512];
}

// ---------------- launch ----------------
extern "C" void kernel_launch(void* const* d_in, const int* in_sizes, int n_in,
                              void* d_out, int out_size)
{
    const float* x     = (const float*)d_in[0];
    const int*   git   = (const int*)  d_in[1];
    const int*   gips  = (const int*)  d_in[2];
    const int*   gis   = (const int*)  d_in[3];
    const float* ln1w  = (const float*)d_in[4];
    const float* ln1b  = (const float*)d_in[5];
    const float* qkvw  = (const float*)d_in[6];
    const float* qkvb  = (const float*)d_in[7];
    const float* projw = (const float*)d_in[8];
    const float* projb = (const float*)d_in[9];
    const float* ln2w  = (const float*)d_in[10];
    const float* ln2b  = (const float*)d_in[11];
    const float* fc1w  = (const float*)d_in[12];
    const float* fc1b  = (const float*)d_in[13];
    const float* fc2w  = (const float*)d_in[14];
    const float* fc2b  = (const float*)d_in[15];
    float* out = (float*)d_out;

    float *ph, *phlo, *pq, *pk, *pv, *pxa, *px1, *pxn, *phn, *pact;
    float *pkffh, *pkffl, *pqffh, *pqffl, *pspartf1, *pspartf2, *psv1, *psv2;
    double *pL, *pspartd, *pdscore;
    int *porder, *ptopps, *ptops;
    cudaGetSymbolAddress((void**)&ph,      g_h);
    cudaGetSymbolAddress((void**)&phlo,    g_hlo);
    cudaGetSymbolAddress((void**)&pq,      g_q);
    cudaGetSymbolAddress((void**)&pk,      g_k);
    cudaGetSymbolAddress((void**)&pv,      g_v);
    cudaGetSymbolAddress((void**)&pxa,     g_xa);
    cudaGetSymbolAddress((void**)&px1,     g_x1);
    cudaGetSymbolAddress((void**)&pxn,     g_xn);
    cudaGetSymbolAddress((void**)&phn,     g_hn);
    cudaGetSymbolAddress((void**)&pact,    g_act);
    cudaGetSymbolAddress((void**)&pkffh,   g_kffh);
    cudaGetSymbolAddress((void**)&pkffl,   g_kffl);
    cudaGetSymbolAddress((void**)&pqffh,   g_qffh);
    cudaGetSymbolAddress((void**)&pqffl,   g_qffl);
    cudaGetSymbolAddress((void**)&pL,      g_L);
    cudaGetSymbolAddress((void**)&pspartd, g_spartd);
    cudaGetSymbolAddress((void**)&pspartf1,g_spartf1);
    cudaGetSymbolAddress((void**)&pspartf2,g_spartf2);
    cudaGetSymbolAddress((void**)&pdscore, g_dscore);
    cudaGetSymbolAddress((void**)&psv1,    g_sv1);
    cudaGetSymbolAddress((void**)&psv2,    g_sv2);
    cudaGetSymbolAddress((void**)&porder,  g_order);
    cudaGetSymbolAddress((void**)&ptopps,  g_top_ps);
    cudaGetSymbolAddress((void**)&ptops,   g_top_s);

    float* attn_out = out + ATTN_OFF;

    cudaFuncSetAttribute(attn_softmax_kernel,
                         cudaFuncAttributeMaxDynamicSharedMemorySize, SMEM_ATTN);
    cudaFuncSetAttribute(ffqk_kernel,
                         cudaFuncAttributeMaxDynamicSharedMemorySize, SMEM_FFQK);

    // 1. LN1 in ff (h_hi also feeds main path)
    ln_ff_kernel<<<M1, 256>>>(x, ln1w, ln1b, ph, phlo);
    // 2. main QKV GEMM (fp32, bit-identical — feeds V1 emulation; SACRED)
    sgemm_nt<EPI_QKV><<<dim3(3*DIMC/128, M1/128), 256>>>(
        ph, qkvw, qkvb, nullptr, pq, pk, pv, nullptr, M1, 3*DIMC, DIMC);
    // 3. ff K (all rows) and ff Q (template rows) — Kahan compensated
    ffgemm_kernel<FFM_K><<<dim3(DIMC/64, M1/64), 256>>>(ph, phlo, qkvw, qkvb, pkffh, pkffl);
    ffgemm_kernel<FFM_Q><<<dim3(DIMC/64, (BATCH*LTN)/64), 256>>>(ph, phlo, qkvw, qkvb, pqffh, pqffl);
    // 4. ff logits -> double — Kahan compensated
    ffqk_kernel<<<dim3(BATCH*HEADS, NTOK/64), 256, SMEM_FFQK>>>(pqffh, pqffl, pkffh, pkffl, pL);
    // 5. exact scores + V2 emulation, V1 emulation, reductions
    score_soft_kernel<<<dim3(BATCH, HEADS), 256>>>(pL, pspartd, pspartf2);
    score_emul4_kernel<<<dim3(BATCH, HEADS), 256>>>(pq, pk, pspartf1);
    score_reduce_kernel<<<BATCH, 512>>>(pspartd, pspartf1, pspartf2, pdscore, psv1, psv2);
    // 6. main attention (attn output, fp32)
    attn_softmax_kernel<<<dim3(BATCH*HEADS, NTOK/32), 256, SMEM_ATTN>>>(pq, pk, attn_out);
    // 7. PV -> tf32 tensor cores
    pv_tf32_kernel<<<dim3(BATCH*HEADS, NTOK/64), 128>>>(attn_out, pv, pxa);
    // 8. proj + residual -> tf32 tensor cores
    tf32gemm_kernel<TEPI_PROJ><<<dim3(DIMC/128, M1/128), 256>>>(
        pxa, projw, projb, x, px1, M1, DIMC, DIMC);
    // 9. exact sort + intersection-of-emulations swap -> emit
    sort_flag_kernel<<<dim3(BATCH, 2), 256>>>(pdscore, psv1, psv2, porder);
    emit_kernel<<<dim3(BATCH, 2), 256>>>(porder, gips, gis, out, ptopps, ptops);
    idx_copy_kernel<<<(BATCH*LTN + 255)/256, 256>>>(git, out);
    // 10. gather + LN2
    gather_ln2_kernel<<<dim3(NKEEP, BATCH), 256>>>(px1, ptopps, ptops, ln2w, ln2b, pxn, phn);
    // 11. MLP -> tf32 tensor cores
    tf32gemm_kernel<TEPI_GELU><<<dim3(HID/128, M2/128), 256>>>(
        phn, fc1w, fc1b, nullptr, pact, M2, HID, DIMC);
    tf32gemm_kernel<TEPI_OUT><<<dim3(DIMC/128, M2/128), 256>>>(
        pact, fc2w, fc2b, pxn, out, M2, DIMC, HID);
}

// round 14
// speedup vs baseline: 1.4811x; 1.0899x over previous
#include <cuda_runtime.h>

// ---------------- problem constants ----------------
#define BATCH  32
#define NTOK   576
#define DIMC   768
#define HEADS  12
#define HD     64
#define LTN    64
#define LSN    256
#define KEEPN  180
#define REMN   76
#define NKEEP  424
#define HID    3072

#define M1     (BATCH*NTOK)   // 18432
#define M2     (BATCH*NKEEP)  // 13568

// output layout (flattened tuple, float32, reference order)
#define GIT_OFF      10420224
#define KEEP_PS_OFF  10422272
#define KEEP_S_OFF   10428032
#define REM_PS_OFF   10433792
#define REM_S_OFF    10436224
#define ATTN_OFF     10438656

// ---------------- device scratch ----------------
__device__ __align__(16) float g_h  [M1*DIMC];
__device__ __align__(16) float g_hlo[M1*DIMC];
__device__ __align__(16) float g_q  [M1*DIMC];
__device__ __align__(16) float g_k  [M1*DIMC];
__device__ __align__(16) float g_v  [M1*DIMC];
__device__ __align__(16) float g_xa [M1*DIMC];
__device__ __align__(16) float g_x1 [M1*DIMC];
__device__ __align__(16) float g_xn [M2*DIMC];
__device__ __align__(16) float g_hn [M2*DIMC];
__device__ __align__(16) float g_act[(size_t)M2*HID];
__device__ __align__(16) float g_kffh[M1*DIMC];
__device__ __align__(16) float g_kffl[M1*DIMC];
__device__ __align__(16) float g_qffh[BATCH*HEADS*LTN*HD];
__device__ __align__(16) float g_qffl[BATCH*HEADS*LTN*HD];
__device__ __align__(16) double g_L[(size_t)BATCH*HEADS*LTN*NTOK];
__device__ __align__(16) double g_spartd [(size_t)BATCH*HEADS*512];
__device__ __align__(16) float  g_spartf2[(size_t)BATCH*HEADS*512];
__device__ __align__(16) float  g_spartf1[(size_t)BATCH*HEADS*512];
__device__ __align__(16) double g_dscore[BATCH*2*LSN];
__device__ __align__(16) float  g_sv1[BATCH*2*LSN];
__device__ __align__(16) float  g_sv2[BATCH*2*LSN];
__device__ __align__(16) int    g_order[64*LSN];
__device__ __align__(16) int    g_top_ps[BATCH*LSN];
__device__ __align__(16) int    g_top_s [BATCH*LSN];

// ---------------- packed f32x2 helpers (per-lane IEEE rn) ----
typedef unsigned long long ull;
__device__ __forceinline__ ull pk2(float lo, float hi) {
    ull r;
    asm("mov.b64 %0, {%1, %2};" : "=l"(r)
        : "r"(__float_as_uint(lo)), "r"(__float_as_uint(hi)));
    return r;
}
__device__ __forceinline__ ull dup2(float v) { return pk2(v, v); }
__device__ __forceinline__ void upk2(ull v, float& lo, float& hi) {
    unsigned a, b;
    asm("mov.b64 {%0, %1}, %2;" : "=r"(a), "=r"(b) : "l"(v));
    lo = __uint_as_float(a); hi = __uint_as_float(b);
}
__device__ __forceinline__ ull fma2(ull a, ull b, ull c) {
    ull d; asm("fma.rn.f32x2 %0, %1, %2, %3;" : "=l"(d) : "l"(a), "l"(b), "l"(c));
    return d;
}
__device__ __forceinline__ ull add2(ull a, ull b) {
    ull d; asm("add.rn.f32x2 %0, %1, %2;" : "=l"(d) : "l"(a), "l"(b));
    return d;
}
__device__ __forceinline__ ull mul2(ull a, ull b) {
    ull d; asm("mul.rn.f32x2 %0, %1, %2;" : "=l"(d) : "l"(a), "l"(b));
    return d;
}
__device__ __forceinline__ ull neg2(ull a) {
    const ull m = 0x8000000080000000ULL;
    ull d; asm("xor.b64 %0, %1, %2;" : "=l"(d) : "l"(a), "l"(m));
    return d;
}
__device__ __forceinline__ unsigned f2tf(float f) {
    unsigned r; asm("cvt.rna.tf32.f32 %0, %1;" : "=r"(r) : "f"(f));
    return r;
}

// ---------------- ff (double-single) helpers ----------------
__device__ __forceinline__ void ts2(float a, float b, float& s, float& e) {
    s = a + b;
    float z = s - a;
    e = (a - (s - z)) + (b - z);
}
__device__ __forceinline__ void ffacc_f(float& h, float& l, float v) {
    float s, e; ts2(h, v, s, e); h = s; l += e;
}
__device__ __forceinline__ void ffacc_p(float& h, float& l, float a, float b) {
    float p = a * b;
    float e = fmaf(a, b, -p);
    float s, er; ts2(h, p, s, er);
    h = s; l += er + e;
}
__device__ __forceinline__ void ffadd(float& h, float& l, float bh2, float bl2) {
    float s, e; ts2(h, bh2, s, e);
    e += l + bl2;
    h = s + e;
    l = e - (h - s);
}

__device__ __forceinline__ float gelu_exact(float v) {
    return 0.5f * v * (1.0f + erff(v * 0.70710678118654752f));
}

// ---------------- LN1 in ff: writes h_hi (main path) + h_lo ----------------
__global__ __launch_bounds__(256)
void ln_ff_kernel(const float* __restrict__ X, const float* __restrict__ w,
                  const float* __restrict__ bia, float* __restrict__ Yh,
                  float* __restrict__ Yl)
{
    __shared__ float sh[8], slo[8], sqh[8], sql[8];
    __shared__ double sm_mean, sm_inv;
    int row = blockIdx.x;
    const float* xr = X + (size_t)row * DIMC;
    int t = threadIdx.x;
    float x0 = xr[t], x1 = xr[t+256], x2 = xr[t+512];
    float sH = 0.f, sL = 0.f, qH = 0.f, qL = 0.f;
    ffacc_f(sH, sL, x0); ffacc_f(sH, sL, x1); ffacc_f(sH, sL, x2);
    ffacc_p(qH, qL, x0, x0); ffacc_p(qH, qL, x1, x1); ffacc_p(qH, qL, x2, x2);
    int lane = t & 31, warp = t >> 5;
    #pragma unroll
    for (int o = 16; o; o >>= 1) {
        float oh = __shfl_xor_sync(0xffffffffu, sH, o);
        float ol = __shfl_xor_sync(0xffffffffu, sL, o);
        ffadd(sH, sL, oh, ol);
        oh = __shfl_xor_sync(0xffffffffu, qH, o);
        ol = __shfl_xor_sync(0xffffffffu, qL, o);
        ffadd(qH, qL, oh, ol);
    }
    if (lane == 0) { sh[warp]=sH; slo[warp]=sL; sqh[warp]=qH; sql[warp]=qL; }
    __syncthreads();
    if (t == 0) {
        double ms = 0.0, mq = 0.0;
        #pragma unroll
        for (int i = 0; i < 8; i++) {
            ms += (double)sh[i] + (double)slo[i];
            mq += (double)sqh[i] + (double)sql[i];
        }
        double mean = ms / 768.0;
        double var  = mq / 768.0 - mean*mean;
        sm_mean = mean;
        sm_inv  = 1.0 / sqrt(var + 1e-5);
    }
    __syncthreads();
    double mean = sm_mean, inv = sm_inv;
    float mh = (float)mean, ml = (float)(mean - (double)mh);
    float ih = (float)inv,  il = (float)(inv  - (double)ih);
    #pragma unroll
    for (int rep = 0; rep < 3; rep++) {
        int c = t + rep*256;
        float xv = (rep==0)?x0:((rep==1)?x1:x2);
        float wv = w[c], bv = bia[c];
        float th, tl; ts2(xv, -mh, th, tl); tl -= ml;
        float ph = th * ih;
        float pl = fmaf(th, ih, -ph);
        pl += th*il + tl*ih;
        float uh = ph * wv;
        float ul = fmaf(ph, wv, -uh);
        ul = fmaf(pl, wv, ul);
        float rh, rl; ts2(uh, bv, rh, rl); rl += ul;
        float oh = rh + rl;
        float ol = rl - (oh - rh);
        Yh[(size_t)row*DIMC + c] = oh;
        Yl[(size_t)row*DIMC + c] = ol;
    }
}

// ---------------- ff GEMM (packed f32x2, Kahan compensation) ----------
#define FFM_K 0
#define FFM_Q 1

template<int MODE>
__global__ __launch_bounds__(256)
void ffgemm_kernel(const float* __restrict__ Ah, const float* __restrict__ Al,
                   const float* __restrict__ W, const float* __restrict__ bias,
                   float* __restrict__ Ch, float* __restrict__ Cl)
{
    __shared__ float Ash[16*68], Asl[16*68], Ws[16*68];
    const int tid = threadIdx.x;
    const int tx = tid & 15, ty = tid >> 4;
    const int m0 = blockIdx.y * 64;
    const int n0 = blockIdx.x * 64;
    const int wrow0 = (MODE == FFM_K) ? 768 : 0;
    const ull NEG1 = dup2(-1.0f);
    ull sS[4][2], cC[4][2];
    #pragma unroll
    for (int i = 0; i < 4; i++)
        #pragma unroll
        for (int j = 0; j < 2; j++) { sS[i][j] = 0ULL; cC[i][j] = 0ULL; }

    const int lrow = tid >> 2;
    const int lc4  = (tid & 3) * 4;
    int arow;
    if (MODE == FFM_Q) { int m = m0 + lrow; arow = (m >> 6)*NTOK + (m & 63); }
    else               arow = m0 + lrow;

    for (int k0 = 0; k0 < DIMC; k0 += 16) {
        float4 vh = *(const float4*)(Ah + (size_t)arow*DIMC + k0 + lc4);
        float4 vl = *(const float4*)(Al + (size_t)arow*DIMC + k0 + lc4);
        float4 vw = *(const float4*)(W + (size_t)(wrow0 + n0 + lrow)*DIMC + k0 + lc4);
        Ash[(lc4+0)*68+lrow]=vh.x; Ash[(lc4+1)*68+lrow]=vh.y; Ash[(lc4+2)*68+lrow]=vh.z; Ash[(lc4+3)*68+lrow]=vh.w;
        Asl[(lc4+0)*68+lrow]=vl.x; Asl[(lc4+1)*68+lrow]=vl.y; Asl[(lc4+2)*68+lrow]=vl.z; Asl[(lc4+3)*68+lrow]=vl.w;
        Ws [(lc4+0)*68+lrow]=vw.x; Ws [(lc4+1)*68+lrow]=vw.y; Ws [(lc4+2)*68+lrow]=vw.z; Ws [(lc4+3)*68+lrow]=vw.w;
        __syncthreads();
        #pragma unroll
        for (int kk = 0; kk < 16; kk++) {
            float4 ah4 = *(const float4*)&Ash[kk*68 + ty*4];
            float4 al4 = *(const float4*)&Asl[kk*68 + ty*4];
            ulonglong2 wq = *(const ulonglong2*)&Ws[kk*68 + tx*4];
            ull wp[2] = {wq.x, wq.y};
            float ahv[4] = {ah4.x, ah4.y, ah4.z, ah4.w};
            float alv[4] = {al4.x, al4.y, al4.z, al4.w};
            #pragma unroll
            for (int i = 0; i < 4; i++) {
                ull ahd = dup2(ahv[i]);
                ull ald = dup2(alv[i]);
                #pragma unroll
                for (int j2 = 0; j2 < 2; j2++) {
                    ull p2 = mul2(ahd, wp[j2]);
                    ull e2 = fma2(ahd, wp[j2], neg2(p2));
                    e2 = fma2(ald, wp[j2], e2);
                    ull y2 = fma2(cC[i][j2], NEG1, p2);
                    ull t2 = add2(sS[i][j2], y2);
                    ull d2 = fma2(sS[i][j2], NEG1, t2);
                    ull cn = fma2(y2, NEG1, d2);
                    cC[i][j2] = fma2(e2, NEG1, cn);
                    sS[i][j2] = t2;
                }
            }
        }
        __syncthreads();
    }

    #pragma unroll
    for (int i = 0; i < 4; i++) {
        float aH[4], aC[4];
        upk2(sS[i][0], aH[0], aH[1]); upk2(sS[i][1], aH[2], aH[3]);
        upk2(cC[i][0], aC[0], aC[1]); upk2(cC[i][1], aC[2], aC[3]);
        int m = m0 + ty*4 + i;
        float4 rh, rl;
        float* ph = &rh.x; float* pl = &rl.x;
        #pragma unroll
        for (int j = 0; j < 4; j++) {
            int col = n0 + tx*4 + j;
            float hi = aH[j], lo = -aC[j];
            float h2 = hi + lo;
            float l2 = lo - (h2 - hi);
            float bv = bias[wrow0 + col];
            float s, e; ts2(h2, bv, s, e); e += l2;
            float oh = s + e;
            float ol = e - (oh - s);
            ph[j] = oh; pl[j] = ol;
        }
        int col0 = n0 + tx*4;
        int head = col0 >> 6, d = col0 & 63;
        size_t off;
        if (MODE == FFM_Q) {
            int b = m >> 6, q = m & 63;
            off = (((size_t)(b*HEADS + head))*LTN + q)*HD + d;
        } else {
            int b = m / NTOK, n = m - (m/NTOK)*NTOK;
            off = (((size_t)(b*HEADS + head))*NTOK + n)*HD + d;
        }
        *(float4*)&Ch[off] = rh;
        *(float4*)&Cl[off] = rl;
    }
}

// ---------------- ff QK^T -> double logits (packed f32x2, Kahan) ----------------
#define SMEM_FFQK (4*64*68*4)

__global__ __launch_bounds__(256)
void ffqk_kernel(const float* __restrict__ Qh, const float* __restrict__ Ql,
                 const float* __restrict__ Kh, const float* __restrict__ Kl,
                 double* __restrict__ Lg)
{
    extern __shared__ float smf[];
    float* sQh = smf;
    float* sQl = smf + 64*68;
    float* sKh = smf + 2*64*68;
    float* sKl = smf + 3*64*68;
    int bh = blockIdx.x, nt = blockIdx.y;
    int tid = threadIdx.x;
    int tx = tid & 15, ty = tid >> 4;
    size_t qbase = (size_t)bh * LTN * HD;
    size_t kbase = ((size_t)bh * NTOK + nt*64) * HD;
    const ull NEG1 = dup2(-1.0f);

    for (int l = tid; l < 1024; l += 256) {
        int row = l >> 4, c4 = (l & 15) * 4;
        float4 a = *(const float4*)&Qh[qbase + (size_t)row*HD + c4];
        float4 b = *(const float4*)&Ql[qbase + (size_t)row*HD + c4];
        float4 c = *(const float4*)&Kh[kbase + (size_t)row*HD + c4];
        float4 d = *(const float4*)&Kl[kbase + (size_t)row*HD + c4];
        sQh[(c4+0)*68+row]=a.x; sQh[(c4+1)*68+row]=a.y; sQh[(c4+2)*68+row]=a.z; sQh[(c4+3)*68+row]=a.w;
        sQl[(c4+0)*68+row]=b.x; sQl[(c4+1)*68+row]=b.y; sQl[(c4+2)*68+row]=b.z; sQl[(c4+3)*68+row]=b.w;
        sKh[(c4+0)*68+row]=c.x; sKh[(c4+1)*68+row]=c.y; sKh[(c4+2)*68+row]=c.z; sKh[(c4+3)*68+row]=c.w;
        sKl[(c4+0)*68+row]=d.x; sKl[(c4+1)*68+row]=d.y; sKl[(c4+2)*68+row]=d.z; sKl[(c4+3)*68+row]=d.w;
    }
    __syncthreads();
    ull sS[4][2], cC[4][2];
    #pragma unroll
    for (int i = 0; i < 4; i++)
        #pragma unroll
        for (int j = 0; j < 2; j++) { sS[i][j]=0ULL; cC[i][j]=0ULL; }
    for (int d = 0; d < 64; d++) {
        float4 qh4 = *(const float4*)&sQh[d*68 + ty*4];
        float4 ql4 = *(const float4*)&sQl[d*68 + ty*4];
        ulonglong2 khq = *(const ulonglong2*)&sKh[d*68 + tx*4];
        ulonglong2 klq = *(const ulonglong2*)&sKl[d*68 + tx*4];
        ull khp[2] = {khq.x, khq.y};
        ull klp[2] = {klq.x, klq.y};
        float qh[4]={qh4.x,qh4.y,qh4.z,qh4.w}, ql[4]={ql4.x,ql4.y,ql4.z,ql4.w};
        #pragma unroll
        for (int i = 0; i < 4; i++) {
            ull qhd = dup2(qh[i]);
            ull qld = dup2(ql[i]);
            #pragma unroll
            for (int j2 = 0; j2 < 2; j2++) {
                ull p2 = mul2(qhd, khp[j2]);
                ull e2 = fma2(qhd, khp[j2], neg2(p2));
                e2 = fma2(qhd, klp[j2], e2);
                e2 = fma2(qld, khp[j2], e2);
                ull y2 = fma2(cC[i][j2], NEG1, p2);
                ull t2 = add2(sS[i][j2], y2);
                ull d2 = fma2(sS[i][j2], NEG1, t2);
                ull cn = fma2(y2, NEG1, d2);
                cC[i][j2] = fma2(e2, NEG1, cn);
                sS[i][j2] = t2;
            }
        }
    }
    #pragma unroll
    for (int i = 0; i < 4; i++) {
        float aH[4], aC[4];
        upk2(sS[i][0], aH[0], aH[1]); upk2(sS[i][1], aH[2], aH[3]);
        upk2(cC[i][0], aC[0], aC[1]); upk2(cC[i][1], aC[2], aC[3]);
        int q = ty*4 + i;
        #pragma unroll
        for (int j = 0; j < 4; j++) {
            int key = nt*64 + tx*4 + j;
            Lg[((size_t)bh*LTN + q)*NTOK + key] =
                ((double)aH[j] - (double)aC[j]) * 0.125;
        }
    }
}

// ---------------- exact double softmax + key sums; also V2 fp32-emulated sums ----------------
__global__ __launch_bounds__(256)
void score_soft_kernel(const double* __restrict__ Lg, double* __restrict__ spartd,
                       float* __restrict__ spartf2)
{
    __shared__ double sl[NTOK];
    __shared__ double sred[16];
    int b = blockIdx.x, h = blockIdx.y;
    int bh = b*HEADS + h;
    const double* L = Lg + (size_t)bh * LTN * NTOK;
    int t = threadIdx.x;
    int lane = t & 31, warp = t >> 5;
    double acc0 = 0.0, acc1 = 0.0;
    float  f0 = 0.f,   f1 = 0.f;

    for (int q = 0; q < LTN; q++) {
        __syncthreads();
        const double* lq = L + (size_t)q * NTOK;
        double m = lq[t];
        m = fmax(m, lq[t+256]);
        if (t < 64) m = fmax(m, lq[t+512]);
        #pragma unroll
        for (int o = 16; o; o >>= 1) m = fmax(m, __shfl_xor_sync(0xffffffffu, m, o));
        if (lane == 0) sred[warp] = m;
        __syncthreads();
        if (t < 32) {
            double mm = (lane < 8) ? sred[lane] : -1e300;
            #pragma unroll
            for (int o = 4; o; o >>= 1) mm = fmax(mm, __shfl_xor_sync(0xffffffffu, mm, o));
            if (lane == 0) sred[0] = mm;
        }
        __syncthreads();
        m = sred[0];
        double sum = 0.0;
        {
            double p = exp(lq[t] - m);       sl[t] = p;       sum += p;
            p = exp(lq[t+256] - m);          sl[t+256] = p;   sum += p;
            if (t < 64) { p = exp(lq[t+512] - m); sl[t+512] = p; sum += p; }
        }
        #pragma unroll
        for (int o = 16; o; o >>= 1) sum += __shfl_xor_sync(0xffffffffu, sum, o);
        if (lane == 0) sred[8+warp] = sum;
        __syncthreads();
        if (t < 32) {
            double ss = (lane < 8) ? sred[8+lane] : 0.0;
            #pragma unroll
            for (int o = 4; o; o >>= 1) ss += __shfl_xor_sync(0xffffffffu, ss, o);
            if (lane == 0) sred[8] = ss;
        }
        __syncthreads();
        double inv = 1.0 / sred[8];
        double a0 = sl[64  + t] * inv;
        double a1 = sl[320 + t] * inv;
        acc0 += a0;
        acc1 += a1;
        f0 += (float)a0;
        f1 += (float)a1;
    }
    spartd[(size_t)bh*512 + t]        = acc0;
    spartd[(size_t)bh*512 + 256 + t]  = acc1;
    spartf2[(size_t)bh*512 + t]       = f0 / 64.0f;
    spartf2[(size_t)bh*512 + 256 + t] = f1 / 64.0f;
}

// ---------------- V1: R4-style fp32-emulated score from main fp32 q/k ----------------
__global__ __launch_bounds__(256)
void score_emul4_kernel(const float* __restrict__ Q, const float* __restrict__ K,
                        float* __restrict__ spartf1)
{
    __shared__ float sq[64];
    __shared__ float sl[NTOK];
    __shared__ float sred[16];
    int b = blockIdx.x, h = blockIdx.y;
    int bh = b*HEADS + h;
    size_t base = (size_t)bh * NTOK * HD;
    int t = threadIdx.x;
    int lane = t & 31, warp = t >> 5;
    float acc0 = 0.f, acc1 = 0.f;

    for (int q = 0; q < LTN; q++) {
        __syncthreads();
        if (t < 16)
            *(float4*)&sq[t*4] = *(const float4*)&Q[base + (size_t)q*HD + t*4];
        __syncthreads();
        #pragma unroll
        for (int rep = 0; rep < 3; rep++) {
            int j = t + rep*256;
            if (j < NTOK) {
                const float* kr = &K[base + (size_t)j*HD];
                float s0=0.f, s1=0.f, s2=0.f, s3=0.f;
                #pragma unroll
                for (int d = 0; d < 64; d += 4) {
                    s0 = fmaf(sq[d+0], kr[d+0], s0);
                    s1 = fmaf(sq[d+1], kr[d+1], s1);
                    s2 = fmaf(sq[d+2], kr[d+2], s2);
                    s3 = fmaf(sq[d+3], kr[d+3], s3);
                }
                sl[j] = ((s0+s1)+(s2+s3)) * 0.125f;
            }
        }
        __syncthreads();
        float m = -3.4e38f;
        m = fmaxf(m, sl[t]);
        m = fmaxf(m, sl[t+256]);
        if (t < 64) m = fmaxf(m, sl[t+512]);
        #pragma unroll
        for (int o = 16; o; o >>= 1) m = fmaxf(m, __shfl_xor_sync(0xffffffffu, m, o));
        if (lane == 0) sred[warp] = m;
        __syncthreads();
        if (t < 32) {
            float mm = (lane < 8) ? sred[lane] : -3.4e38f;
            #pragma unroll
            for (int o = 4; o; o >>= 1) mm = fmaxf(mm, __shfl_xor_sync(0xffffffffu, mm, o));
            if (lane == 0) sred[0] = mm;
        }
        __syncthreads();
        m = sred[0];
        #pragma unroll
        for (int rep = 0; rep < 3; rep++) {
            int j = t + rep*256;
            if (j < NTOK) {
                float d = sl[j] - m;
                sl[j] = (float)exp((double)d);
            }
        }
        __syncthreads();
        float ls = sl[t] + sl[t+256];
        if (t < 64) ls += sl[t+512];
        #pragma unroll
        for (int o = 16; o; o >>= 1) ls += __shfl_xor_sync(0xffffffffu, ls, o);
        if (lane == 0) sred[8+warp] = ls;
        __syncthreads();
        if (t < 32) {
            float ss = (lane < 8) ? sred[8+lane] : 0.f;
            #pragma unroll
            for (int o = 4; o; o >>= 1) ss += __shfl_xor_sync(0xffffffffu, ss, o);
            if (lane == 0) sred[8] = ss;
        }
        __syncthreads();
        float S = sred[8];
        acc0 += sl[64  + t] / S;
        acc1 += sl[320 + t] / S;
    }
    spartf1[(size_t)bh*512 + t]       = acc0 / 64.0f;
    spartf1[(size_t)bh*512 + 256 + t] = acc1 / 64.0f;
}

// ---------------- reductions: exact(double), V1(fp32 seq), V2(fp32 seq) ----------------
__global__ __launch_bounds__(512)
void score_reduce_kernel(const double* __restrict__ spartd,
                         const float* __restrict__ spartf1,
                         const float* __restrict__ spartf2,
                         double* __restrict__ dscore,
                         float* __restrict__ sv1, float* __restrict__ sv2)
{
    int b = blockIdx.x;
    int j = threadIdx.x;
    double s = 0.0;
    float e1 = 0.f, e2 = 0.f;
    #pragma unroll
    for (int h = 0; h < HEADS; h++) {
        size_t o = (size_t)(b*HEADS + h)*512 + j;
        s  += spartd[o] / 64.0;
        e1 += spartf1[o];
        e2 += spartf2[o];
    }
    dscore[b*2*LSN + j] = s / 12.0;
    sv1[b*2*LSN + j] = e1 / 12.0f;
    sv2[b*2*LSN + j] = e2 / 12.0f;
}

// ---------------- main-path fp32 SGEMM (packed f32x2) — QKV only (SACRED) ----
#define EPI_QKV  0

template<int EPI>
__global__ __launch_bounds__(256)
void sgemm_nt(const float* __restrict__ A, const float* __restrict__ Bw,
              const float* __restrict__ bias, const float* __restrict__ res,
              float* __restrict__ Cq, float* __restrict__ Ck, float* __restrict__ Cv,
              float* __restrict__ Cc, int M, int N, int K)
{
    __shared__ float As[16][132];
    __shared__ float Bs[16][132];
    const int tid = threadIdx.x;
    const int tx = tid & 15;
    const int ty = tid >> 4;
    const int m0 = blockIdx.y * 128;
    const int n0 = blockIdx.x * 128;
    ull acc2[8][4];
    #pragma unroll
    for (int i = 0; i < 8; i++)
        #pragma unroll
        for (int j = 0; j < 4; j++) acc2[i][j] = 0ULL;

    const int lrow = tid >> 2;
    const int lc4  = (tid & 3) * 4;

    for (int k0 = 0; k0 < K; k0 += 16) {
        #pragma unroll
        for (int half = 0; half < 2; half++) {
            int row = lrow + half*64;
            float4 va = *(const float4*)(A  + (size_t)(m0+row)*K + k0 + lc4);
            As[lc4+0][row]=va.x; As[lc4+1][row]=va.y; As[lc4+2][row]=va.z; As[lc4+3][row]=va.w;
            float4 vb = *(const float4*)(Bw + (size_t)(n0+row)*K + k0 + lc4);
            Bs[lc4+0][row]=vb.x; Bs[lc4+1][row]=vb.y; Bs[lc4+2][row]=vb.z; Bs[lc4+3][row]=vb.w;
        }
        __syncthreads();
        #pragma unroll
        for (int kk = 0; kk < 16; kk++) {
            float4 a0 = *(const float4*)&As[kk][ty*4];
            float4 a1 = *(const float4*)&As[kk][64 + ty*4];
            ulonglong2 b01 = *(const ulonglong2*)&Bs[kk][tx*4];
            ulonglong2 b23 = *(const ulonglong2*)&Bs[kk][64 + tx*4];
            ull bp0 = b01.x, bp1 = b01.y, bp2 = b23.x, bp3 = b23.y;
            float av[8] = {a0.x,a0.y,a0.z,a0.w,a1.x,a1.y,a1.z,a1.w};
            #pragma unroll
            for (int i = 0; i < 8; i++) {
                ull ad = dup2(av[i]);
                acc2[i][0] = fma2(ad, bp0, acc2[i][0]);
                acc2[i][1] = fma2(ad, bp1, acc2[i][1]);
                acc2[i][2] = fma2(ad, bp2, acc2[i][2]);
                acc2[i][3] = fma2(ad, bp3, acc2[i][3]);
            }
        }
        __syncthreads();
    }

    #pragma unroll
    for (int i = 0; i < 8; i++) {
        float accf[8];
        upk2(acc2[i][0], accf[0], accf[1]);
        upk2(acc2[i][1], accf[2], accf[3]);
        upk2(acc2[i][2], accf[4], accf[5]);
        upk2(acc2[i][3], accf[6], accf[7]);
        int rloc = (i < 4) ? (ty*4 + i) : (64 + ty*4 + i - 4);
        int row = m0 + rloc;
        #pragma unroll
        for (int jq = 0; jq < 2; jq++) {
            int col = n0 + jq*64 + tx*4;
            float4 r;
            r.x = accf[jq*4+0] + bias[col+0];
            r.y = accf[jq*4+1] + bias[col+1];
            r.z = accf[jq*4+2] + bias[col+2];
            r.w = accf[jq*4+3] + bias[col+3];
            int which = col / 768;
            int rem   = col - which*768;
            int head  = rem >> 6;
            int dd    = rem & 63;
            int bb    = row / NTOK;
            int nt    = row - bb*NTOK;
            float* targ = (which == 0) ? Cq : ((which == 1) ? Ck : Cv);
            *(float4*)&targ[(((size_t)(bb*HEADS + head))*NTOK + nt)*HD + dd] = r;
        }
    }
}

// ---------------- tf32 tensor-core GEMM (proj / fc1 / fc2; 1e-3 tolerance path) ----
#define TEPI_PROJ 0
#define TEPI_GELU 1
#define TEPI_OUT  2

template<int EPI>
__global__ __launch_bounds__(256)
void tf32gemm_kernel(const float* __restrict__ A, const float* __restrict__ Bw,
                     const float* __restrict__ bias, const float* __restrict__ res,
                     float* __restrict__ C, int M, int N, int K)
{
    __shared__ unsigned As[128*36];
    __shared__ unsigned Bs[128*36];
    const int tid = threadIdx.x;
    const int warp = tid >> 5, lane = tid & 31;
    const int wr = warp >> 2, wc = warp & 3;
    const int g = lane >> 2, t = lane & 3;
    const int m0 = blockIdx.y * 128, n0 = blockIdx.x * 128;
    const int lr = tid >> 3;
    const int lk = (tid & 7) * 4;

    float acc[4][4][4];
    #pragma unroll
    for (int i = 0; i < 4; i++)
        #pragma unroll
        for (int j = 0; j < 4; j++)
            #pragma unroll
            for (int r = 0; r < 4; r++) acc[i][j][r] = 0.f;

    float4 pa[4], pb[4];
    #pragma unroll
    for (int p = 0; p < 4; p++) {
        pa[p] = *(const float4*)(A  + (size_t)(m0 + p*32 + lr)*K + lk);
        pb[p] = *(const float4*)(Bw + (size_t)(n0 + p*32 + lr)*K + lk);
    }

    for (int k0 = 0; k0 < K; k0 += 32) {
        __syncthreads();
        #pragma unroll
        for (int p = 0; p < 4; p++) {
            int m = p*32 + lr;
            As[m*36+lk+0]=f2tf(pa[p].x); As[m*36+lk+1]=f2tf(pa[p].y);
            As[m*36+lk+2]=f2tf(pa[p].z); As[m*36+lk+3]=f2tf(pa[p].w);
            Bs[m*36+lk+0]=f2tf(pb[p].x); Bs[m*36+lk+1]=f2tf(pb[p].y);
            Bs[m*36+lk+2]=f2tf(pb[p].z); Bs[m*36+lk+3]=f2tf(pb[p].w);
        }
        __syncthreads();
        if (k0 + 32 < K) {
            #pragma unroll
            for (int p = 0; p < 4; p++) {
                pa[p] = *(const float4*)(A  + (size_t)(m0 + p*32 + lr)*K + k0 + 32 + lk);
                pb[p] = *(const float4*)(Bw + (size_t)(n0 + p*32 + lr)*K + k0 + 32 + lk);
            }
        }
        #pragma unroll
        for (int ks = 0; ks < 32; ks += 8) {
            unsigned af[4][4], bf[4][2];
            #pragma unroll
            for (int i = 0; i < 4; i++) {
                int row = wr*64 + i*16 + g;
                af[i][0] = As[row*36 + ks + t];
                af[i][1] = As[(row+8)*36 + ks + t];
                af[i][2] = As[row*36 + ks + t + 4];
                af[i][3] = As[(row+8)*36 + ks + t + 4];
            }
            #pragma unroll
            for (int j = 0; j < 4; j++) {
                int n = wc*32 + j*8 + g;
                bf[j][0] = Bs[n*36 + ks + t];
                bf[j][1] = Bs[n*36 + ks + t + 4];
            }
            #pragma unroll
            for (int i = 0; i < 4; i++)
                #pragma unroll
                for (int j = 0; j < 4; j++)
                    asm volatile(
                        "mma.sync.aligned.m16n8k8.row.col.f32.tf32.tf32.f32 "
                        "{%0,%1,%2,%3}, {%4,%5,%6,%7}, {%8,%9}, {%0,%1,%2,%3};"
                        : "+f"(acc[i][j][0]), "+f"(acc[i][j][1]),
                          "+f"(acc[i][j][2]), "+f"(acc[i][j][3])
                        : "r"(af[i][0]), "r"(af[i][1]), "r"(af[i][2]), "r"(af[i][3]),
                          "r"(bf[j][0]), "r"(bf[j][1]));
        }
    }

    #pragma unroll
    for (int i = 0; i < 4; i++) {
        int r0 = m0 + wr*64 + i*16 + g;
        #pragma unroll
        for (int j = 0; j < 4; j++) {
            int c0 = n0 + wc*32 + j*8 + 2*t;
            float b0v = bias[c0], b1v = bias[c0+1];
            float v00 = acc[i][j][0] + b0v, v01 = acc[i][j][1] + b1v;
            float v10 = acc[i][j][2] + b0v, v11 = acc[i][j][3] + b1v;
            size_t o0 = (size_t)r0*N + c0;
            size_t o1 = (size_t)(r0+8)*N + c0;
            if constexpr (EPI == TEPI_GELU) {
                v00 = gelu_exact(v00); v01 = gelu_exact(v01);
                v10 = gelu_exact(v10); v11 = gelu_exact(v11);
            } else {
                float2 r0v = *(const float2*)&res[o0];
                float2 r1v = *(const float2*)&res[o1];
                v00 += r0v.x; v01 += r0v.y;
                v10 += r1v.x; v11 += r1v.y;
            }
            float2 w0; w0.x = v00; w0.y = v01;
            float2 w1; w1.x = v10; w1.y = v11;
            *(float2*)&C[o0] = w0;
            *(float2*)&C[o1] = w1;
        }
    }
}

// ---------------- attention (fp32 main path, packed f32x2 QK) ----------------
#define SK_PAD 68
#define SMEM_ATTN ((2048 + 64*SK_PAD + 32*577) * 4)

__global__ __launch_bounds__(256)
void attn_softmax_kernel(const float* __restrict__ Q, const float* __restrict__ Km,
                         float* __restrict__ attn_out)
{
    extern __shared__ float sm[];
    float* sQ = sm;
    float* sK = sm + 2048;
    float* sS = sm + 2048 + 64*SK_PAD;
    int bh = blockIdx.x;
    int qt = blockIdx.y;
    int tid = threadIdx.x;
    int tx = tid & 15, ty = tid >> 4;
    int q0 = qt * 32;
    size_t base = (size_t)bh * NTOK * HD;

    for (int l = tid; l < 512; l += 256) {
        int row = l >> 4, c4 = (l & 15) * 4;
        *(float4*)&sQ[row*64 + c4] = *(const float4*)&Q[base + (size_t)(q0+row)*HD + c4];
    }
    for (int kt = 0; kt < 9; kt++) {
        __syncthreads();
        for (int l = tid; l < 1024; l += 256) {
            int row = l >> 4, c4 = (l & 15) * 4;
            float4 v = *(const float4*)&Km[base + (size_t)(kt*64+row)*HD + c4];
            sK[(c4+0)*SK_PAD + row] = v.x;
            sK[(c4+1)*SK_PAD + row] = v.y;
            sK[(c4+2)*SK_PAD + row] = v.z;
            sK[(c4+3)*SK_PAD + row] = v.w;
        }
        __syncthreads();
        ull acc2[2][2] = {{0ULL,0ULL},{0ULL,0ULL}};
        #pragma unroll
        for (int d = 0; d < 64; d++) {
            float qa = sQ[(2*ty)*64 + d];
            float qb = sQ[(2*ty+1)*64 + d];
            ulonglong2 kq = *(const ulonglong2*)&sK[d*SK_PAD + tx*4];
            ull qad = dup2(qa), qbd = dup2(qb);
            acc2[0][0] = fma2(qad, kq.x, acc2[0][0]);
            acc2[0][1] = fma2(qad, kq.y, acc2[0][1]);
            acc2[1][0] = fma2(qbd, kq.x, acc2[1][0]);
            acc2[1][1] = fma2(qbd, kq.y, acc2[1][1]);
        }
        #pragma unroll
        for (int i2 = 0; i2 < 2; i2++) {
            float f0, f1, f2, f3;
            upk2(acc2[i2][0], f0, f1);
            upk2(acc2[i2][1], f2, f3);
            float* dst = &sS[(2*ty+i2)*577 + kt*64 + tx*4];
            dst[0] = f0 * 0.125f;
            dst[1] = f1 * 0.125f;
            dst[2] = f2 * 0.125f;
            dst[3] = f3 * 0.125f;
        }
    }
    __syncthreads();
    int warp = tid >> 5, lane = tid & 31;
    for (int r = warp*4; r < warp*4 + 4; r++) {
        float* srow = &sS[r*577];
        float m = -3.4e38f;
        for (int j = lane; j < NTOK; j += 32) m = fmaxf(m, srow[j]);
        #pragma unroll
        for (int o = 16; o; o >>= 1) m = fmaxf(m, __shfl_xor_sync(0xffffffffu, m, o));
        float s = 0.f;
        for (int j = lane; j < NTOK; j += 32) {
            float p = expf(srow[j] - m);
            srow[j] = p;
            s += p;
        }
        #pragma unroll
        for (int o = 16; o; o >>= 1) s += __shfl_xor_sync(0xffffffffu, s, o);
        size_t obase = ((size_t)bh*NTOK + q0 + r) * NTOK;
        for (int j = lane; j < NTOK; j += 32) attn_out[obase + j] = srow[j] / s;
    }
}

// ---------------- PV -> tf32 tensor cores (x-path only, 1e-3 tol) ----------------
__global__ __launch_bounds__(128)
void pv_tf32_kernel(const float* __restrict__ P, const float* __restrict__ V,
                    float* __restrict__ XA)
{
    __shared__ unsigned sP[64*36];
    __shared__ unsigned sVt[64*36];
    int bh = blockIdx.x, mt = blockIdx.y;
    int b = bh / HEADS, h = bh % HEADS;
    int tid = threadIdx.x;
    int warp = tid >> 5, lane = tid & 31;
    int g = lane >> 2, t = lane & 3;
    int m0 = mt * 64;
    size_t pbase = ((size_t)bh*NTOK + m0) * NTOK;
    size_t vbase = (size_t)bh * NTOK * HD;

    float acc[8][4];
    #pragma unroll
    for (int j = 0; j < 8; j++)
        #pragma unroll
        for (int r = 0; r < 4; r++) acc[j][r] = 0.f;

    for (int k0 = 0; k0 < NTOK; k0 += 32) {
        __syncthreads();
        {
            int prow = tid >> 1;
            int pc0 = (tid & 1) * 16;
            #pragma unroll
            for (int c4 = 0; c4 < 16; c4 += 4) {
                float4 pv4 = *(const float4*)&P[pbase + (size_t)prow*NTOK + k0 + pc0 + c4];
                sP[prow*36 + pc0 + c4 + 0] = f2tf(pv4.x);
                sP[prow*36 + pc0 + c4 + 1] = f2tf(pv4.y);
                sP[prow*36 + pc0 + c4 + 2] = f2tf(pv4.z);
                sP[prow*36 + pc0 + c4 + 3] = f2tf(pv4.w);
            }
        }
        {
            int vrow = tid >> 2;
            int vc0 = (tid & 3) * 16;
            #pragma unroll
            for (int c4 = 0; c4 < 16; c4 += 4) {
                float4 vv4 = *(const float4*)&V[vbase + (size_t)(k0+vrow)*HD + vc0 + c4];
                sVt[(vc0+c4+0)*36 + vrow] = f2tf(vv4.x);
                sVt[(vc0+c4+1)*36 + vrow] = f2tf(vv4.y);
                sVt[(vc0+c4+2)*36 + vrow] = f2tf(vv4.z);
                sVt[(vc0+c4+3)*36 + vrow] = f2tf(vv4.w);
            }
        }
        __syncthreads();
        #pragma unroll
        for (int ks = 0; ks < 32; ks += 8) {
            unsigned af[4];
            int row = warp*16 + g;
            af[0] = sP[row*36 + ks + t];
            af[1] = sP[(row+8)*36 + ks + t];
            af[2] = sP[row*36 + ks + t + 4];
            af[3] = sP[(row+8)*36 + ks + t + 4];
            #pragma unroll
            for (int j = 0; j < 8; j++) {
                unsigned bf0 = sVt[(j*8+g)*36 + ks + t];
                unsigned bf1 = sVt[(j*8+g)*36 + ks + t + 4];
                asm volatile(
                    "mma.sync.aligned.m16n8k8.row.col.f32.tf32.tf32.f32 "
                    "{%0,%1,%2,%3}, {%4,%5,%6,%7}, {%8,%9}, {%0,%1,%2,%3};"
                    : "+f"(acc[j][0]), "+f"(acc[j][1]), "+f"(acc[j][2]), "+f"(acc[j][3])
                    : "r"(af[0]), "r"(af[1]), "r"(af[2]), "r"(af[3]),
                      "r"(bf0), "r"(bf1));
            }
        }
    }
    int q0r = m0 + warp*16 + g;
    #pragma unroll
    for (int j = 0; j < 8; j++) {
        int c0 = j*8 + 2*t;
        float2 w0; w0.x = acc[j][0]; w0.y = acc[j][1];
        float2 w1; w1.x = acc[j][2]; w1.y = acc[j][3];
        *(float2*)&XA[((size_t)b*NTOK + q0r)*DIMC + h*HD + c0] = w0;
        *(float2*)&XA[((size_t)b*NTOK + q0r + 8)*DIMC + h*HD + c0] = w1;
    }
}

// ---------------- sort (exact) + intersection-flag swap -> final order ----------------
__global__ __launch_bounds__(256)
void sort_flag_kernel(const double* __restrict__ dscore,
                      const float* __restrict__ sv1, const float* __restrict__ sv2,
                      int* __restrict__ order)
{
    __shared__ double sv[256];
    __shared__ int    si[256];
    __shared__ int    flg[256];
    int b = blockIdx.x, grp = blockIdx.y, tid = threadIdx.x;
    int group = b*2 + grp;
    int gbase = b*2*LSN + grp*LSN;
    sv[tid] = dscore[gbase + tid];
    si[tid] = tid;
    __syncthreads();
    for (int k = 2; k <= 256; k <<= 1) {
        for (int j = k >> 1; j > 0; j >>= 1) {
            int ixj = tid ^ j;
            if (ixj > tid) {
                double va = sv[tid], vb = sv[ixj];
                int    ia = si[tid], ib = si[ixj];
                bool a_first = (va > vb) || (va == vb && ia < ib);
                bool desc = ((tid & k) == 0);
                bool doswap = desc ? (!a_first) : a_first;
                if (doswap) { sv[tid]=vb; sv[ixj]=va; si[tid]=ib; si[ixj]=ia; }
            }
            __syncthreads();
        }
    }
    int f = 0;
    if (tid < 255) {
        int u = si[tid], v = si[tid+1];
        float a1 = sv1[gbase + u], b1 = sv1[gbase + v];
        float a2 = sv2[gbase + u], b2 = sv2[gbase + v];
        bool inv1 = (b1 > a1) || (b1 == a1 && v < u);
        bool inv2 = (b2 > a2) || (b2 == a2 && v < u);
        f = (inv1 && inv2) ? 1 : 0;
    }
    flg[tid] = f;
    __syncthreads();
    int fprev = (tid > 0) ? flg[tid-1] : 0;
    int src = flg[tid] ? tid+1 : (fprev ? tid-1 : tid);
    order[group*LSN + tid] = si[src];
}

__global__ __launch_bounds__(256)
void emit_kernel(const int* __restrict__ order,
                 const int* __restrict__ gi_ps, const int* __restrict__ gi_s,
                 float* __restrict__ out, int* __restrict__ top_ps,
                 int* __restrict__ top_s)
{
    int b = blockIdx.x, grp = blockIdx.y, tid = threadIdx.x;
    int group = b*2 + grp;
    int idx = order[group*LSN + tid];
    const int* gi = grp ? gi_s : gi_ps;
    float gval = (float)gi[b*LSN + idx];
    if (tid < KEEPN) {
        out[(grp ? KEEP_S_OFF : KEEP_PS_OFF) + b*KEEPN + tid] = gval;
        (grp ? top_s : top_ps)[b*LSN + tid] = idx;
    } else {
        out[(grp ? REM_S_OFF : REM_PS_OFF) + b*REMN + (tid - KEEPN)] = gval;
    }
}

__global__ void idx_copy_kernel(const int* __restrict__ git, float* __restrict__ out)
{
    int i = blockIdx.x*256 + threadIdx.x;
    if (i < BATCH*LTN) out[GIT_OFF + i] = (float)git[i];
}

// ---------------- gather kept tokens + LN2 ----------------
__global__ __launch_bounds__(256)
void gather_ln2_kernel(const float* __restrict__ X1, const int* __restrict__ topps,
                       const int* __restrict__ tops, const float* __restrict__ w,
                       const float* __restrict__ bia, float* __restrict__ XN,
                       float* __restrict__ HN)
{
    __shared__ float sb[16];
    int i = blockIdx.x;
    int b = blockIdx.y;
    int src;
    if (i < LTN)              src = i;
    else if (i < LTN + KEEPN) src = LTN + topps[b*LSN + (i - LTN)];
    else                      src = LTN + LSN + tops[b*LSN + (i - LTN - KEEPN)];
    const float* xr = X1 + ((size_t)b*NTOK + src) * DIMC;
    size_t ob = ((size_t)b*NKEEP + i) * DIMC;
    int t = threadIdx.x;
    float v0 = xr[t], v1 = xr[t+256], v2 = xr[t+512];
    XN[ob+t] = v0; XN[ob+t+256] = v1; XN[ob+t+512] = v2;
    float s = v0+v1+v2;
    float q = v0*v0 + v1*v1 + v2*v2;
    int lane = t & 31, warp = t >> 5;
    #pragma unroll
    for (int o = 16; o; o >>= 1) {
        s += __shfl_xor_sync(0xffffffffu, s, o);
        q += __shfl_xor_sync(0xffffffffu, q, o);
    }
    if (lane == 0) { sb[warp] = s; sb[8+warp] = q; }
    __syncthreads();
    if (t < 32) {
        float s2 = (lane < 8) ? sb[lane] : 0.f;
        float q2 = (lane < 8) ? sb[8+lane] : 0.f;
        #pragma unroll
        for (int o = 4; o; o >>= 1) {
            s2 += __shfl_xor_sync(0xffffffffu, s2, o);
            q2 += __shfl_xor_sync(0xffffffffu, q2, o);
        }
        if (lane == 0) { sb[0] = s2; sb[1] = q2; }
    }
    __syncthreads();
    float mean = sb[0] * (1.f/768.f);
    float var  = sb[1] * (1.f/768.f) - mean*mean;
    float inv  = rsqrtf(var + 1e-5f);
    HN[ob+t]     = (v0-mean)*inv*w[t]     + bia[t];
    HN[ob+t+256] = (v1-mean)*inv*w[t+256] + bia[t+256];
    HN[ob+t+512] = (v2-mean)*inv*w[t+512] + bia[t+512];
}

// ---------------- stream/event resources (created once; per-call work identical) ----
struct OverlapRes {
    cudaStream_t s1, s2;
    cudaEvent_t evLn, evQkv, evEmul, evEmit;
    OverlapRes() {
        cudaStreamCreateWithFlags(&s1, cudaStreamNonBlocking);
        cudaStreamCreateWithFlags(&s2, cudaStreamNonBlocking);
        cudaEventCreateWithFlags(&evLn,   cudaEventDisableTiming);
        cudaEventCreateWithFlags(&evQkv,  cudaEventDisableTiming);
        cudaEventCreateWithFlags(&evEmul, cudaEventDisableTiming);
        cudaEventCreateWithFlags(&evEmit, cudaEventDisableTiming);
    }
};
static OverlapRes& ores() { static OverlapRes r; return r; }

// ---------------- launch ----------------
extern "C" void kernel_launch(void* const* d_in, const int* in_sizes, int n_in,
                              void* d_out, int out_size)
{
    const float* x     = (const float*)d_in[0];
    const int*   git   = (const int*)  d_in[1];
    const int*   gips  = (const int*)  d_in[2];
    const int*   gis   = (const int*)  d_in[3];
    const float* ln1w  = (const float*)d_in[4];
    const float* ln1b  = (const float*)d_in[5];
    const float* qkvw  = (const float*)d_in[6];
    const float* qkvb  = (const float*)d_in[7];
    const float* projw = (const float*)d_in[8];
    const float* projb = (const float*)d_in[9];
    const float* ln2w  = (const float*)d_in[10];
    const float* ln2b  = (const float*)d_in[11];
    const float* fc1w  = (const float*)d_in[12];
    const float* fc1b  = (const float*)d_in[13];
    const float* fc2w  = (const float*)d_in[14];
    const float* fc2b  = (const float*)d_in[15];
    float* out = (float*)d_out;

    float *ph, *phlo, *pq, *pk, *pv, *pxa, *px1, *pxn, *phn, *pact;
    float *pkffh, *pkffl, *pqffh, *pqffl, *pspartf1, *pspartf2, *psv1, *psv2;
    double *pL, *pspartd, *pdscore;
    int *porder, *ptopps, *ptops;
    cudaGetSymbolAddress((void**)&ph,      g_h);
    cudaGetSymbolAddress((void**)&phlo,    g_hlo);
    cudaGetSymbolAddress((void**)&pq,      g_q);
    cudaGetSymbolAddress((void**)&pk,      g_k);
    cudaGetSymbolAddress((void**)&pv,      g_v);
    cudaGetSymbolAddress((void**)&pxa,     g_xa);
    cudaGetSymbolAddress((void**)&px1,     g_x1);
    cudaGetSymbolAddress((void**)&pxn,     g_xn);
    cudaGetSymbolAddress((void**)&phn,     g_hn);
    cudaGetSymbolAddress((void**)&pact,    g_act);
    cudaGetSymbolAddress((void**)&pkffh,   g_kffh);
    cudaGetSymbolAddress((void**)&pkffl,   g_kffl);
    cudaGetSymbolAddress((void**)&pqffh,   g_qffh);
    cudaGetSymbolAddress((void**)&pqffl,   g_qffl);
    cudaGetSymbolAddress((void**)&pL,      g_L);
    cudaGetSymbolAddress((void**)&pspartd, g_spartd);
    cudaGetSymbolAddress((void**)&pspartf1,g_spartf1);
    cudaGetSymbolAddress((void**)&pspartf2,g_spartf2);
    cudaGetSymbolAddress((void**)&pdscore, g_dscore);
    cudaGetSymbolAddress((void**)&psv1,    g_sv1);
    cudaGetSymbolAddress((void**)&psv2,    g_sv2);
    cudaGetSymbolAddress((void**)&porder,  g_order);
    cudaGetSymbolAddress((void**)&ptopps,  g_top_ps);
    cudaGetSymbolAddress((void**)&ptops,   g_top_s);

    float* attn_out = out + ATTN_OFF;

    cudaFuncSetAttribute(attn_softmax_kernel,
                         cudaFuncAttributeMaxDynamicSharedMemorySize, SMEM_ATTN);
    cudaFuncSetAttribute(ffqk_kernel,
                         cudaFuncAttributeMaxDynamicSharedMemorySize, SMEM_FFQK);

    OverlapRes& R = ores();

    // 1. LN1 (s0)
    ln_ff_kernel<<<M1, 256>>>(x, ln1w, ln1b, ph, phlo);
    cudaEventRecord(R.evLn, 0);

    // --- s1: score branch (ff path), depends only on LN1 ---
    cudaStreamWaitEvent(R.s1, R.evLn, 0);
    ffgemm_kernel<FFM_K><<<dim3(DIMC/64, M1/64), 256, 0, R.s1>>>(
        ph, phlo, qkvw, qkvb, pkffh, pkffl);
    ffgemm_kernel<FFM_Q><<<dim3(DIMC/64, (BATCH*LTN)/64), 256, 0, R.s1>>>(
        ph, phlo, qkvw, qkvb, pqffh, pqffl);
    ffqk_kernel<<<dim3(BATCH*HEADS, NTOK/64), 256, SMEM_FFQK, R.s1>>>(
        pqffh, pqffl, pkffh, pkffl, pL);
    score_soft_kernel<<<dim3(BATCH, HEADS), 256, 0, R.s1>>>(pL, pspartd, pspartf2);

    // --- s0: main branch ---
    sgemm_nt<EPI_QKV><<<dim3(3*DIMC/128, M1/128), 256>>>(
        ph, qkvw, qkvb, nullptr, pq, pk, pv, nullptr, M1, 3*DIMC, DIMC);
    cudaEventRecord(R.evQkv, 0);

    // --- s2: V1 emulation (needs q/k only) ---
    cudaStreamWaitEvent(R.s2, R.evQkv, 0);
    score_emul4_kernel<<<dim3(BATCH, HEADS), 256, 0, R.s2>>>(pq, pk, pspartf1);
    cudaEventRecord(R.evEmul, R.s2);

    // s0 continues main branch
    attn_softmax_kernel<<<dim3(BATCH*HEADS, NTOK/32), 256, SMEM_ATTN>>>(pq, pk, attn_out);
    pv_tf32_kernel<<<dim3(BATCH*HEADS, NTOK/64), 128>>>(attn_out, pv, pxa);
    tf32gemm_kernel<TEPI_PROJ><<<dim3(DIMC/128, M1/128), 256>>>(
        pxa, projw, projb, x, px1, M1, DIMC, DIMC);

    // s1: reductions + sort + emit (joins s2's emul result)
    cudaStreamWaitEvent(R.s1, R.evEmul, 0);
    score_reduce_kernel<<<BATCH, 512, 0, R.s1>>>(pspartd, pspartf1, pspartf2,
                                                 pdscore, psv1, psv2);
    sort_flag_kernel<<<dim3(BATCH, 2), 256, 0, R.s1>>>(pdscore, psv1, psv2, porder);
    emit_kernel<<<dim3(BATCH, 2), 256, 0, R.s1>>>(porder, gips, gis, out, ptopps, ptops);
    idx_copy_kernel<<<(BATCH*LTN + 255)/256, 256, 0, R.s1>>>(git, out);
    cudaEventRecord(R.evEmit, R.s1);

    // s0: join with emit, then tail
    cudaStreamWaitEvent(0, R.evEmit, 0);
    gather_ln2_kernel<<<dim3(NKEEP, BATCH), 256>>>(px1, ptopps, ptops, ln2w, ln2b, pxn, phn);
    tf32gemm_kernel<TEPI_GELU><<<dim3(HID/128, M2/128), 256>>>(
        phn, fc1w, fc1b, nullptr, pact, M2, HID, DIMC);
    tf32gemm_kernel<TEPI_OUT><<<dim3(DIMC/128, M2/128), 256>>>(
        pact, fc2w, fc2b, pxn, out, M2, DIMC, HID);
}

// round 15
// speedup vs baseline: 1.5363x; 1.0372x over previous
#include <cuda_runtime.h>

// ---------------- problem constants ----------------
#define BATCH  32
#define NTOK   576
#define DIMC   768
#define HEADS  12
#define HD     64
#define LTN    64
#define LSN    256
#define KEEPN  180
#define REMN   76
#define NKEEP  424
#define HID    3072

#define M1     (BATCH*NTOK)   // 18432
#define M2     (BATCH*NKEEP)  // 13568
#define QCH    8              // q-chunks in score_soft

// output layout (flattened tuple, float32, reference order)
#define GIT_OFF      10420224
#define KEEP_PS_OFF  10422272
#define KEEP_S_OFF   10428032
#define REM_PS_OFF   10433792
#define REM_S_OFF    10436224
#define ATTN_OFF     10438656

// ---------------- device scratch ----------------
__device__ __align__(16) float g_h  [M1*DIMC];
__device__ __align__(16) float g_hlo[M1*DIMC];
__device__ __align__(16) float g_q  [M1*DIMC];
__device__ __align__(16) float g_k  [M1*DIMC];
__device__ __align__(16) float g_v  [M1*DIMC];
__device__ __align__(16) float g_xa [M1*DIMC];
__device__ __align__(16) float g_x1 [M1*DIMC];
__device__ __align__(16) float g_xn [M2*DIMC];
__device__ __align__(16) float g_hn [M2*DIMC];
__device__ __align__(16) float g_act[(size_t)M2*HID];
__device__ __align__(16) float g_kffh[M1*DIMC];
__device__ __align__(16) float g_kffl[M1*DIMC];
__device__ __align__(16) float g_qffh[BATCH*HEADS*LTN*HD];
__device__ __align__(16) float g_qffl[BATCH*HEADS*LTN*HD];
__device__ __align__(16) double g_L[(size_t)BATCH*HEADS*LTN*NTOK];
__device__ __align__(16) float  g_pqf[(size_t)BATCH*HEADS*LTN*512];   // per-q fp32 attn vals
__device__ __align__(16) double g_pdd[(size_t)BATCH*HEADS*QCH*512];   // per-chunk double partials
__device__ __align__(16) double g_spartd [(size_t)BATCH*HEADS*512];
__device__ __align__(16) float  g_spartf2[(size_t)BATCH*HEADS*512];
__device__ __align__(16) float  g_spartf1[(size_t)BATCH*HEADS*512];
__device__ __align__(16) double g_dscore[BATCH*2*LSN];
__device__ __align__(16) float  g_sv1[BATCH*2*LSN];
__device__ __align__(16) float  g_sv2[BATCH*2*LSN];
__device__ __align__(16) int    g_order[64*LSN];
__device__ __align__(16) int    g_top_ps[BATCH*LSN];
__device__ __align__(16) int    g_top_s [BATCH*LSN];

// ---------------- packed f32x2 helpers (per-lane IEEE rn) ----
typedef unsigned long long ull;
__device__ __forceinline__ ull pk2(float lo, float hi) {
    ull r;
    asm("mov.b64 %0, {%1, %2};" : "=l"(r)
        : "r"(__float_as_uint(lo)), "r"(__float_as_uint(hi)));
    return r;
}
__device__ __forceinline__ ull dup2(float v) { return pk2(v, v); }
__device__ __forceinline__ void upk2(ull v, float& lo, float& hi) {
    unsigned a, b;
    asm("mov.b64 {%0, %1}, %2;" : "=r"(a), "=r"(b) : "l"(v));
    lo = __uint_as_float(a); hi = __uint_as_float(b);
}
__device__ __forceinline__ ull fma2(ull a, ull b, ull c) {
    ull d; asm("fma.rn.f32x2 %0, %1, %2, %3;" : "=l"(d) : "l"(a), "l"(b), "l"(c));
    return d;
}
__device__ __forceinline__ ull add2(ull a, ull b) {
    ull d; asm("add.rn.f32x2 %0, %1, %2;" : "=l"(d) : "l"(a), "l"(b));
    return d;
}
__device__ __forceinline__ ull mul2(ull a, ull b) {
    ull d; asm("mul.rn.f32x2 %0, %1, %2;" : "=l"(d) : "l"(a), "l"(b));
    return d;
}
__device__ __forceinline__ ull neg2(ull a) {
    const ull m = 0x8000000080000000ULL;
    ull d; asm("xor.b64 %0, %1, %2;" : "=l"(d) : "l"(a), "l"(m));
    return d;
}
__device__ __forceinline__ unsigned f2tf(float f) {
    unsigned r; asm("cvt.rna.tf32.f32 %0, %1;" : "=r"(r) : "f"(f));
    return r;
}

// ---------------- ff (double-single) helpers ----------------
__device__ __forceinline__ void ts2(float a, float b, float& s, float& e) {
    s = a + b;
    float z = s - a;
    e = (a - (s - z)) + (b - z);
}
__device__ __forceinline__ void ffacc_f(float& h, float& l, float v) {
    float s, e; ts2(h, v, s, e); h = s; l += e;
}
__device__ __forceinline__ void ffacc_p(float& h, float& l, float a, float b) {
    float p = a * b;
    float e = fmaf(a, b, -p);
    float s, er; ts2(h, p, s, er);
    h = s; l += er + e;
}
__device__ __forceinline__ void ffadd(float& h, float& l, float bh2, float bl2) {
    float s, e; ts2(h, bh2, s, e);
    e += l + bl2;
    h = s + e;
    l = e - (h - s);
}

__device__ __forceinline__ float gelu_exact(float v) {
    return 0.5f * v * (1.0f + erff(v * 0.70710678118654752f));
}

// ---------------- LN1 in ff ----------------
__global__ __launch_bounds__(256)
void ln_ff_kernel(const float* __restrict__ X, const float* __restrict__ w,
                  const float* __restrict__ bia, float* __restrict__ Yh,
                  float* __restrict__ Yl)
{
    __shared__ float sh[8], slo[8], sqh[8], sql[8];
    __shared__ double sm_mean, sm_inv;
    int row = blockIdx.x;
    const float* xr = X + (size_t)row * DIMC;
    int t = threadIdx.x;
    float x0 = xr[t], x1 = xr[t+256], x2 = xr[t+512];
    float sH = 0.f, sL = 0.f, qH = 0.f, qL = 0.f;
    ffacc_f(sH, sL, x0); ffacc_f(sH, sL, x1); ffacc_f(sH, sL, x2);
    ffacc_p(qH, qL, x0, x0); ffacc_p(qH, qL, x1, x1); ffacc_p(qH, qL, x2, x2);
    int lane = t & 31, warp = t >> 5;
    #pragma unroll
    for (int o = 16; o; o >>= 1) {
        float oh = __shfl_xor_sync(0xffffffffu, sH, o);
        float ol = __shfl_xor_sync(0xffffffffu, sL, o);
        ffadd(sH, sL, oh, ol);
        oh = __shfl_xor_sync(0xffffffffu, qH, o);
        ol = __shfl_xor_sync(0xffffffffu, qL, o);
        ffadd(qH, qL, oh, ol);
    }
    if (lane == 0) { sh[warp]=sH; slo[warp]=sL; sqh[warp]=qH; sql[warp]=qL; }
    __syncthreads();
    if (t == 0) {
        double ms = 0.0, mq = 0.0;
        #pragma unroll
        for (int i = 0; i < 8; i++) {
            ms += (double)sh[i] + (double)slo[i];
            mq += (double)sqh[i] + (double)sql[i];
        }
        double mean = ms / 768.0;
        double var  = mq / 768.0 - mean*mean;
        sm_mean = mean;
        sm_inv  = 1.0 / sqrt(var + 1e-5);
    }
    __syncthreads();
    double mean = sm_mean, inv = sm_inv;
    float mh = (float)mean, ml = (float)(mean - (double)mh);
    float ih = (float)inv,  il = (float)(inv  - (double)ih);
    #pragma unroll
    for (int rep = 0; rep < 3; rep++) {
        int c = t + rep*256;
        float xv = (rep==0)?x0:((rep==1)?x1:x2);
        float wv = w[c], bv = bia[c];
        float th, tl; ts2(xv, -mh, th, tl); tl -= ml;
        float ph = th * ih;
        float pl = fmaf(th, ih, -ph);
        pl += th*il + tl*ih;
        float uh = ph * wv;
        float ul = fmaf(ph, wv, -uh);
        ul = fmaf(pl, wv, ul);
        float rh, rl; ts2(uh, bv, rh, rl); rl += ul;
        float oh = rh + rl;
        float ol = rl - (oh - rh);
        Yh[(size_t)row*DIMC + c] = oh;
        Yl[(size_t)row*DIMC + c] = ol;
    }
}

// ---------------- ff GEMM (packed f32x2, Kahan) ----------
#define FFM_K 0
#define FFM_Q 1

template<int MODE>
__global__ __launch_bounds__(256)
void ffgemm_kernel(const float* __restrict__ Ah, const float* __restrict__ Al,
                   const float* __restrict__ W, const float* __restrict__ bias,
                   float* __restrict__ Ch, float* __restrict__ Cl)
{
    __shared__ float Ash[16*68], Asl[16*68], Ws[16*68];
    const int tid = threadIdx.x;
    const int tx = tid & 15, ty = tid >> 4;
    const int m0 = blockIdx.y * 64;
    const int n0 = blockIdx.x * 64;
    const int wrow0 = (MODE == FFM_K) ? 768 : 0;
    const ull NEG1 = dup2(-1.0f);
    ull sS[4][2], cC[4][2];
    #pragma unroll
    for (int i = 0; i < 4; i++)
        #pragma unroll
        for (int j = 0; j < 2; j++) { sS[i][j] = 0ULL; cC[i][j] = 0ULL; }

    const int lrow = tid >> 2;
    const int lc4  = (tid & 3) * 4;
    int arow;
    if (MODE == FFM_Q) { int m = m0 + lrow; arow = (m >> 6)*NTOK + (m & 63); }
    else               arow = m0 + lrow;

    for (int k0 = 0; k0 < DIMC; k0 += 16) {
        float4 vh = *(const float4*)(Ah + (size_t)arow*DIMC + k0 + lc4);
        float4 vl = *(const float4*)(Al + (size_t)arow*DIMC + k0 + lc4);
        float4 vw = *(const float4*)(W + (size_t)(wrow0 + n0 + lrow)*DIMC + k0 + lc4);
        Ash[(lc4+0)*68+lrow]=vh.x; Ash[(lc4+1)*68+lrow]=vh.y; Ash[(lc4+2)*68+lrow]=vh.z; Ash[(lc4+3)*68+lrow]=vh.w;
        Asl[(lc4+0)*68+lrow]=vl.x; Asl[(lc4+1)*68+lrow]=vl.y; Asl[(lc4+2)*68+lrow]=vl.z; Asl[(lc4+3)*68+lrow]=vl.w;
        Ws [(lc4+0)*68+lrow]=vw.x; Ws [(lc4+1)*68+lrow]=vw.y; Ws [(lc4+2)*68+lrow]=vw.z; Ws [(lc4+3)*68+lrow]=vw.w;
        __syncthreads();
        #pragma unroll
        for (int kk = 0; kk < 16; kk++) {
            float4 ah4 = *(const float4*)&Ash[kk*68 + ty*4];
            float4 al4 = *(const float4*)&Asl[kk*68 + ty*4];
            ulonglong2 wq = *(const ulonglong2*)&Ws[kk*68 + tx*4];
            ull wp[2] = {wq.x, wq.y};
            float ahv[4] = {ah4.x, ah4.y, ah4.z, ah4.w};
            float alv[4] = {al4.x, al4.y, al4.z, al4.w};
            #pragma unroll
            for (int i = 0; i < 4; i++) {
                ull ahd = dup2(ahv[i]);
                ull ald = dup2(alv[i]);
                #pragma unroll
                for (int j2 = 0; j2 < 2; j2++) {
                    ull p2 = mul2(ahd, wp[j2]);
                    ull e2 = fma2(ahd, wp[j2], neg2(p2));
                    e2 = fma2(ald, wp[j2], e2);
                    ull y2 = fma2(cC[i][j2], NEG1, p2);
                    ull t2 = add2(sS[i][j2], y2);
                    ull d2 = fma2(sS[i][j2], NEG1, t2);
                    ull cn = fma2(y2, NEG1, d2);
                    cC[i][j2] = fma2(e2, NEG1, cn);
                    sS[i][j2] = t2;
                }
            }
        }
        __syncthreads();
    }

    #pragma unroll
    for (int i = 0; i < 4; i++) {
        float aH[4], aC[4];
        upk2(sS[i][0], aH[0], aH[1]); upk2(sS[i][1], aH[2], aH[3]);
        upk2(cC[i][0], aC[0], aC[1]); upk2(cC[i][1], aC[2], aC[3]);
        int m = m0 + ty*4 + i;
        float4 rh, rl;
        float* ph = &rh.x; float* pl = &rl.x;
        #pragma unroll
        for (int j = 0; j < 4; j++) {
            int col = n0 + tx*4 + j;
            float hi = aH[j], lo = -aC[j];
            float h2 = hi + lo;
            float l2 = lo - (h2 - hi);
            float bv = bias[wrow0 + col];
            float s, e; ts2(h2, bv, s, e); e += l2;
            float oh = s + e;
            float ol = e - (oh - s);
            ph[j] = oh; pl[j] = ol;
        }
        int col0 = n0 + tx*4;
        int head = col0 >> 6, d = col0 & 63;
        size_t off;
        if (MODE == FFM_Q) {
            int b = m >> 6, q = m & 63;
            off = (((size_t)(b*HEADS + head))*LTN + q)*HD + d;
        } else {
            int b = m / NTOK, n = m - (m/NTOK)*NTOK;
            off = (((size_t)(b*HEADS + head))*NTOK + n)*HD + d;
        }
        *(float4*)&Ch[off] = rh;
        *(float4*)&Cl[off] = rl;
    }
}

// ---------------- ff QK^T -> double logits (packed f32x2, Kahan) ----------------
#define SMEM_FFQK (4*64*68*4)

__global__ __launch_bounds__(256)
void ffqk_kernel(const float* __restrict__ Qh, const float* __restrict__ Ql,
                 const float* __restrict__ Kh, const float* __restrict__ Kl,
                 double* __restrict__ Lg)
{
    extern __shared__ float smf[];
    float* sQh = smf;
    float* sQl = smf + 64*68;
    float* sKh = smf + 2*64*68;
    float* sKl = smf + 3*64*68;
    int bh = blockIdx.x, nt = blockIdx.y;
    int tid = threadIdx.x;
    int tx = tid & 15, ty = tid >> 4;
    size_t qbase = (size_t)bh * LTN * HD;
    size_t kbase = ((size_t)bh * NTOK + nt*64) * HD;
    const ull NEG1 = dup2(-1.0f);

    for (int l = tid; l < 1024; l += 256) {
        int row = l >> 4, c4 = (l & 15) * 4;
        float4 a = *(const float4*)&Qh[qbase + (size_t)row*HD + c4];
        float4 b = *(const float4*)&Ql[qbase + (size_t)row*HD + c4];
        float4 c = *(const float4*)&Kh[kbase + (size_t)row*HD + c4];
        float4 d = *(const float4*)&Kl[kbase + (size_t)row*HD + c4];
        sQh[(c4+0)*68+row]=a.x; sQh[(c4+1)*68+row]=a.y; sQh[(c4+2)*68+row]=a.z; sQh[(c4+3)*68+row]=a.w;
        sQl[(c4+0)*68+row]=b.x; sQl[(c4+1)*68+row]=b.y; sQl[(c4+2)*68+row]=b.z; sQl[(c4+3)*68+row]=b.w;
        sKh[(c4+0)*68+row]=c.x; sKh[(c4+1)*68+row]=c.y; sKh[(c4+2)*68+row]=c.z; sKh[(c4+3)*68+row]=c.w;
        sKl[(c4+0)*68+row]=d.x; sKl[(c4+1)*68+row]=d.y; sKl[(c4+2)*68+row]=d.z; sKl[(c4+3)*68+row]=d.w;
    }
    __syncthreads();
    ull sS[4][2], cC[4][2];
    #pragma unroll
    for (int i = 0; i < 4; i++)
        #pragma unroll
        for (int j = 0; j < 2; j++) { sS[i][j]=0ULL; cC[i][j]=0ULL; }
    for (int d = 0; d < 64; d++) {
        float4 qh4 = *(const float4*)&sQh[d*68 + ty*4];
        float4 ql4 = *(const float4*)&sQl[d*68 + ty*4];
        ulonglong2 khq = *(const ulonglong2*)&sKh[d*68 + tx*4];
        ulonglong2 klq = *(const ulonglong2*)&sKl[d*68 + tx*4];
        ull khp[2] = {khq.x, khq.y};
        ull klp[2] = {klq.x, klq.y};
        float qh[4]={qh4.x,qh4.y,qh4.z,qh4.w}, ql[4]={ql4.x,ql4.y,ql4.z,ql4.w};
        #pragma unroll
        for (int i = 0; i < 4; i++) {
            ull qhd = dup2(qh[i]);
            ull qld = dup2(ql[i]);
            #pragma unroll
            for (int j2 = 0; j2 < 2; j2++) {
                ull p2 = mul2(qhd, khp[j2]);
                ull e2 = fma2(qhd, khp[j2], neg2(p2));
                e2 = fma2(qhd, klp[j2], e2);
                e2 = fma2(qld, khp[j2], e2);
                ull y2 = fma2(cC[i][j2], NEG1, p2);
                ull t2 = add2(sS[i][j2], y2);
                ull d2 = fma2(sS[i][j2], NEG1, t2);
                ull cn = fma2(y2, NEG1, d2);
                cC[i][j2] = fma2(e2, NEG1, cn);
                sS[i][j2] = t2;
            }
        }
    }
    #pragma unroll
    for (int i = 0; i < 4; i++) {
        float aH[4], aC[4];
        upk2(sS[i][0], aH[0], aH[1]); upk2(sS[i][1], aH[2], aH[3]);
        upk2(cC[i][0], aC[0], aC[1]); upk2(cC[i][1], aC[2], aC[3]);
        int q = ty*4 + i;
        #pragma unroll
        for (int j = 0; j < 4; j++) {
            int key = nt*64 + tx*4 + j;
            Lg[((size_t)bh*LTN + q)*NTOK + key] =
                ((double)aH[j] - (double)aC[j]) * 0.125;
        }
    }
}

// ---------------- exact double softmax per q-chunk (8 q per block) ----------------
// Writes per-q fp32 attn values (for bit-identical sequential V2 sum) and
// per-chunk sequential double partials.
__global__ __launch_bounds__(256)
void score_soft_kernel(const double* __restrict__ Lg, float* __restrict__ pqf,
                       double* __restrict__ pdd)
{
    __shared__ double sl[NTOK];
    __shared__ double sred[16];
    int b = blockIdx.x, h = blockIdx.y, qc = blockIdx.z;
    int bh = b*HEADS + h;
    const double* L = Lg + (size_t)bh * LTN * NTOK;
    int t = threadIdx.x;
    int lane = t & 31, warp = t >> 5;
    double acc0 = 0.0, acc1 = 0.0;

    for (int qi = 0; qi < 8; qi++) {
        int q = qc*8 + qi;
        __syncthreads();
        const double* lq = L + (size_t)q * NTOK;
        double m = lq[t];
        m = fmax(m, lq[t+256]);
        if (t < 64) m = fmax(m, lq[t+512]);
        #pragma unroll
        for (int o = 16; o; o >>= 1) m = fmax(m, __shfl_xor_sync(0xffffffffu, m, o));
        if (lane == 0) sred[warp] = m;
        __syncthreads();
        if (t < 32) {
            double mm = (lane < 8) ? sred[lane] : -1e300;
            #pragma unroll
            for (int o = 4; o; o >>= 1) mm = fmax(mm, __shfl_xor_sync(0xffffffffu, mm, o));
            if (lane == 0) sred[0] = mm;
        }
        __syncthreads();
        m = sred[0];
        double sum = 0.0;
        {
            double p = exp(lq[t] - m);       sl[t] = p;       sum += p;
            p = exp(lq[t+256] - m);          sl[t+256] = p;   sum += p;
            if (t < 64) { p = exp(lq[t+512] - m); sl[t+512] = p; sum += p; }
        }
        #pragma unroll
        for (int o = 16; o; o >>= 1) sum += __shfl_xor_sync(0xffffffffu, sum, o);
        if (lane == 0) sred[8+warp] = sum;
        __syncthreads();
        if (t < 32) {
            double ss = (lane < 8) ? sred[8+lane] : 0.0;
            #pragma unroll
            for (int o = 4; o; o >>= 1) ss += __shfl_xor_sync(0xffffffffu, ss, o);
            if (lane == 0) sred[8] = ss;
        }
        __syncthreads();
        double inv = 1.0 / sred[8];
        double a0 = sl[64  + t] * inv;
        double a1 = sl[320 + t] * inv;
        acc0 += a0;
        acc1 += a1;
        size_t qoff = ((size_t)bh*LTN + q) * 512;
        pqf[qoff + t]       = (float)a0;   // exact same value as R14's (float)a0
        pqf[qoff + 256 + t] = (float)a1;
    }
    size_t coff = ((size_t)bh*QCH + qc) * 512;
    pdd[coff + t]       = acc0;
    pdd[coff + 256 + t] = acc1;
}

// per-bh reduce: double chunk partials (sequential over chunks) and
// bit-identical sequential fp32 q-sum for V2.
__global__ __launch_bounds__(512)
void score_qreduce_kernel(const float* __restrict__ pqf, const double* __restrict__ pdd,
                          double* __restrict__ spartd, float* __restrict__ spartf2)
{
    int bh = blockIdx.x;
    int t = threadIdx.x;   // 0..511
    double d = 0.0;
    #pragma unroll
    for (int qc = 0; qc < QCH; qc++)
        d += pdd[((size_t)bh*QCH + qc)*512 + t];
    float f = 0.f;
    for (int q = 0; q < LTN; q++)
        f += pqf[((size_t)bh*LTN + q)*512 + t];
    spartd[(size_t)bh*512 + t]  = d;
    spartf2[(size_t)bh*512 + t] = f / 64.0f;
}

// ---------------- V1: R4-style fp32-emulated score (SACRED) ----------------
__global__ __launch_bounds__(256)
void score_emul4_kernel(const float* __restrict__ Q, const float* __restrict__ K,
                        float* __restrict__ spartf1)
{
    __shared__ float sq[64];
    __shared__ float sl[NTOK];
    __shared__ float sred[16];
    int b = blockIdx.x, h = blockIdx.y;
    int bh = b*HEADS + h;
    size_t base = (size_t)bh * NTOK * HD;
    int t = threadIdx.x;
    int lane = t & 31, warp = t >> 5;
    float acc0 = 0.f, acc1 = 0.f;

    for (int q = 0; q < LTN; q++) {
        __syncthreads();
        if (t < 16)
            *(float4*)&sq[t*4] = *(const float4*)&Q[base + (size_t)q*HD + t*4];
        __syncthreads();
        #pragma unroll
        for (int rep = 0; rep < 3; rep++) {
            int j = t + rep*256;
            if (j < NTOK) {
                const float* kr = &K[base + (size_t)j*HD];
                float s0=0.f, s1=0.f, s2=0.f, s3=0.f;
                #pragma unroll
                for (int d = 0; d < 64; d += 4) {
                    s0 = fmaf(sq[d+0], kr[d+0], s0);
                    s1 = fmaf(sq[d+1], kr[d+1], s1);
                    s2 = fmaf(sq[d+2], kr[d+2], s2);
                    s3 = fmaf(sq[d+3], kr[d+3], s3);
                }
                sl[j] = ((s0+s1)+(s2+s3)) * 0.125f;
            }
        }
        __syncthreads();
        float m = -3.4e38f;
        m = fmaxf(m, sl[t]);
        m = fmaxf(m, sl[t+256]);
        if (t < 64) m = fmaxf(m, sl[t+512]);
        #pragma unroll
        for (int o = 16; o; o >>= 1) m = fmaxf(m, __shfl_xor_sync(0xffffffffu, m, o));
        if (lane == 0) sred[warp] = m;
        __syncthreads();
        if (t < 32) {
            float mm = (lane < 8) ? sred[lane] : -3.4e38f;
            #pragma unroll
            for (int o = 4; o; o >>= 1) mm = fmaxf(mm, __shfl_xor_sync(0xffffffffu, mm, o));
            if (lane == 0) sred[0] = mm;
        }
        __syncthreads();
        m = sred[0];
        #pragma unroll
        for (int rep = 0; rep < 3; rep++) {
            int j = t + rep*256;
            if (j < NTOK) {
                float d = sl[j] - m;
                sl[j] = (float)exp((double)d);
            }
        }
        __syncthreads();
        float ls = sl[t] + sl[t+256];
        if (t < 64) ls += sl[t+512];
        #pragma unroll
        for (int o = 16; o; o >>= 1) ls += __shfl_xor_sync(0xffffffffu, ls, o);
        if (lane == 0) sred[8+warp] = ls;
        __syncthreads();
        if (t < 32) {
            float ss = (lane < 8) ? sred[8+lane] : 0.f;
            #pragma unroll
            for (int o = 4; o; o >>= 1) ss += __shfl_xor_sync(0xffffffffu, ss, o);
            if (lane == 0) sred[8] = ss;
        }
        __syncthreads();
        float S = sred[8];
        acc0 += sl[64  + t] / S;
        acc1 += sl[320 + t] / S;
    }
    spartf1[(size_t)bh*512 + t]       = acc0 / 64.0f;
    spartf1[(size_t)bh*512 + 256 + t] = acc1 / 64.0f;
}

// ---------------- reductions: exact(double), V1, V2 ----------------
__global__ __launch_bounds__(512)
void score_reduce_kernel(const double* __restrict__ spartd,
                         const float* __restrict__ spartf1,
                         const float* __restrict__ spartf2,
                         double* __restrict__ dscore,
                         float* __restrict__ sv1, float* __restrict__ sv2)
{
    int b = blockIdx.x;
    int j = threadIdx.x;
    double s = 0.0;
    float e1 = 0.f, e2 = 0.f;
    #pragma unroll
    for (int h = 0; h < HEADS; h++) {
        size_t o = (size_t)(b*HEADS + h)*512 + j;
        s  += spartd[o] / 64.0;
        e1 += spartf1[o];
        e2 += spartf2[o];
    }
    dscore[b*2*LSN + j] = s / 12.0;
    sv1[b*2*LSN + j] = e1 / 12.0f;
    sv2[b*2*LSN + j] = e2 / 12.0f;
}

// ---------------- sacred fp32 QK GEMM (packed f32x2, N=1536) ----
#define EPI_QKV  0

template<int EPI>
__global__ __launch_bounds__(256)
void sgemm_nt(const float* __restrict__ A, const float* __restrict__ Bw,
              const float* __restrict__ bias, const float* __restrict__ res,
              float* __restrict__ Cq, float* __restrict__ Ck, float* __restrict__ Cv,
              float* __restrict__ Cc, int M, int N, int K)
{
    __shared__ float As[16][132];
    __shared__ float Bs[16][132];
    const int tid = threadIdx.x;
    const int tx = tid & 15;
    const int ty = tid >> 4;
    const int m0 = blockIdx.y * 128;
    const int n0 = blockIdx.x * 128;
    ull acc2[8][4];
    #pragma unroll
    for (int i = 0; i < 8; i++)
        #pragma unroll
        for (int j = 0; j < 4; j++) acc2[i][j] = 0ULL;

    const int lrow = tid >> 2;
    const int lc4  = (tid & 3) * 4;

    for (int k0 = 0; k0 < K; k0 += 16) {
        #pragma unroll
        for (int half = 0; half < 2; half++) {
            int row = lrow + half*64;
            float4 va = *(const float4*)(A  + (size_t)(m0+row)*K + k0 + lc4);
            As[lc4+0][row]=va.x; As[lc4+1][row]=va.y; As[lc4+2][row]=va.z; As[lc4+3][row]=va.w;
            float4 vb = *(const float4*)(Bw + (size_t)(n0+row)*K + k0 + lc4);
            Bs[lc4+0][row]=vb.x; Bs[lc4+1][row]=vb.y; Bs[lc4+2][row]=vb.z; Bs[lc4+3][row]=vb.w;
        }
        __syncthreads();
        #pragma unroll
        for (int kk = 0; kk < 16; kk++) {
            float4 a0 = *(const float4*)&As[kk][ty*4];
            float4 a1 = *(const float4*)&As[kk][64 + ty*4];
            ulonglong2 b01 = *(const ulonglong2*)&Bs[kk][tx*4];
            ulonglong2 b23 = *(const ulonglong2*)&Bs[kk][64 + tx*4];
            ull bp0 = b01.x, bp1 = b01.y, bp2 = b23.x, bp3 = b23.y;
            float av[8] = {a0.x,a0.y,a0.z,a0.w,a1.x,a1.y,a1.z,a1.w};
            #pragma unroll
            for (int i = 0; i < 8; i++) {
                ull ad = dup2(av[i]);
                acc2[i][0] = fma2(ad, bp0, acc2[i][0]);
                acc2[i][1] = fma2(ad, bp1, acc2[i][1]);
                acc2[i][2] = fma2(ad, bp2, acc2[i][2]);
                acc2[i][3] = fma2(ad, bp3, acc2[i][3]);
            }
        }
        __syncthreads();
    }

    #pragma unroll
    for (int i = 0; i < 8; i++) {
        float accf[8];
        upk2(acc2[i][0], accf[0], accf[1]);
        upk2(acc2[i][1], accf[2], accf[3]);
        upk2(acc2[i][2], accf[4], accf[5]);
        upk2(acc2[i][3], accf[6], accf[7]);
        int rloc = (i < 4) ? (ty*4 + i) : (64 + ty*4 + i - 4);
        int row = m0 + rloc;
        #pragma unroll
        for (int jq = 0; jq < 2; jq++) {
            int col = n0 + jq*64 + tx*4;
            float4 r;
            r.x = accf[jq*4+0] + bias[col+0];
            r.y = accf[jq*4+1] + bias[col+1];
            r.z = accf[jq*4+2] + bias[col+2];
            r.w = accf[jq*4+3] + bias[col+3];
            int which = col / 768;
            int rem   = col - which*768;
            int head  = rem >> 6;
            int dd    = rem & 63;
            int bb    = row / NTOK;
            int nt    = row - bb*NTOK;
            float* targ = (which == 0) ? Cq : ((which == 1) ? Ck : Cv);
            *(float4*)&targ[(((size_t)(bb*HEADS + head))*NTOK + nt)*HD + dd] = r;
        }
    }
}

// ---------------- tf32 tensor-core GEMM ----
#define TEPI_PROJ 0
#define TEPI_GELU 1
#define TEPI_OUT  2
#define TEPI_V    3

template<int EPI>
__global__ __launch_bounds__(256)
void tf32gemm_kernel(const float* __restrict__ A, const float* __restrict__ Bw,
                     const float* __restrict__ bias, const float* __restrict__ res,
                     float* __restrict__ C, int M, int N, int K)
{
    __shared__ unsigned As[128*36];
    __shared__ unsigned Bs[128*36];
    const int tid = threadIdx.x;
    const int warp = tid >> 5, lane = tid & 31;
    const int wr = warp >> 2, wc = warp & 3;
    const int g = lane >> 2, t = lane & 3;
    const int m0 = blockIdx.y * 128, n0 = blockIdx.x * 128;
    const int lr = tid >> 3;
    const int lk = (tid & 7) * 4;

    float acc[4][4][4];
    #pragma unroll
    for (int i = 0; i < 4; i++)
        #pragma unroll
        for (int j = 0; j < 4; j++)
            #pragma unroll
            for (int r = 0; r < 4; r++) acc[i][j][r] = 0.f;

    float4 pa[4], pb[4];
    #pragma unroll
    for (int p = 0; p < 4; p++) {
        pa[p] = *(const float4*)(A  + (size_t)(m0 + p*32 + lr)*K + lk);
        pb[p] = *(const float4*)(Bw + (size_t)(n0 + p*32 + lr)*K + lk);
    }

    for (int k0 = 0; k0 < K; k0 += 32) {
        __syncthreads();
        #pragma unroll
        for (int p = 0; p < 4; p++) {
            int m = p*32 + lr;
            As[m*36+lk+0]=f2tf(pa[p].x); As[m*36+lk+1]=f2tf(pa[p].y);
            As[m*36+lk+2]=f2tf(pa[p].z); As[m*36+lk+3]=f2tf(pa[p].w);
            Bs[m*36+lk+0]=f2tf(pb[p].x); Bs[m*36+lk+1]=f2tf(pb[p].y);
            Bs[m*36+lk+2]=f2tf(pb[p].z); Bs[m*36+lk+3]=f2tf(pb[p].w);
        }
        __syncthreads();
        if (k0 + 32 < K) {
            #pragma unroll
            for (int p = 0; p < 4; p++) {
                pa[p] = *(const float4*)(A  + (size_t)(m0 + p*32 + lr)*K + k0 + 32 + lk);
                pb[p] = *(const float4*)(Bw + (size_t)(n0 + p*32 + lr)*K + k0 + 32 + lk);
            }
        }
        #pragma unroll
        for (int ks = 0; ks < 32; ks += 8) {
            unsigned af[4][4], bf[4][2];
            #pragma unroll
            for (int i = 0; i < 4; i++) {
                int row = wr*64 + i*16 + g;
                af[i][0] = As[row*36 + ks + t];
                af[i][1] = As[(row+8)*36 + ks + t];
                af[i][2] = As[row*36 + ks + t + 4];
                af[i][3] = As[(row+8)*36 + ks + t + 4];
            }
            #pragma unroll
            for (int j = 0; j < 4; j++) {
                int n = wc*32 + j*8 + g;
                bf[j][0] = Bs[n*36 + ks + t];
                bf[j][1] = Bs[n*36 + ks + t + 4];
            }
            #pragma unroll
            for (int i = 0; i < 4; i++)
                #pragma unroll
                for (int j = 0; j < 4; j++)
                    asm volatile(
                        "mma.sync.aligned.m16n8k8.row.col.f32.tf32.tf32.f32 "
                        "{%0,%1,%2,%3}, {%4,%5,%6,%7}, {%8,%9}, {%0,%1,%2,%3};"
                        : "+f"(acc[i][j][0]), "+f"(acc[i][j][1]),
                          "+f"(acc[i][j][2]), "+f"(acc[i][j][3])
                        : "r"(af[i][0]), "r"(af[i][1]), "r"(af[i][2]), "r"(af[i][3]),
                          "r"(bf[j][0]), "r"(bf[j][1]));
        }
    }

    #pragma unroll
    for (int i = 0; i < 4; i++) {
        int r0 = m0 + wr*64 + i*16 + g;
        #pragma unroll
        for (int j = 0; j < 4; j++) {
            int c0 = n0 + wc*32 + j*8 + 2*t;
            float b0v = bias[c0], b1v = bias[c0+1];
            float v00 = acc[i][j][0] + b0v, v01 = acc[i][j][1] + b1v;
            float v10 = acc[i][j][2] + b0v, v11 = acc[i][j][3] + b1v;
            if constexpr (EPI == TEPI_V) {
                // scatter to (b, head, n, d)
                int head = c0 >> 6, d = c0 & 63;
                int b0r = r0 / NTOK, n0r = r0 - b0r*NTOK;
                int b1r = (r0+8) / NTOK, n1r = (r0+8) - b1r*NTOK;
                float2 w0; w0.x = v00; w0.y = v01;
                float2 w1; w1.x = v10; w1.y = v11;
                *(float2*)&C[(((size_t)(b0r*HEADS + head))*NTOK + n0r)*HD + d] = w0;
                *(float2*)&C[(((size_t)(b1r*HEADS + head))*NTOK + n1r)*HD + d] = w1;
            } else {
                size_t o0 = (size_t)r0*N + c0;
                size_t o1 = (size_t)(r0+8)*N + c0;
                if constexpr (EPI == TEPI_GELU) {
                    v00 = gelu_exact(v00); v01 = gelu_exact(v01);
                    v10 = gelu_exact(v10); v11 = gelu_exact(v11);
                } else {
                    float2 r0v = *(const float2*)&res[o0];
                    float2 r1v = *(const float2*)&res[o1];
                    v00 += r0v.x; v01 += r0v.y;
                    v10 += r1v.x; v11 += r1v.y;
                }
                float2 w0; w0.x = v00; w0.y = v01;
                float2 w1; w1.x = v10; w1.y = v11;
                *(float2*)&C[o0] = w0;
                *(float2*)&C[o1] = w1;
            }
        }
    }
}

// ---------------- attention (fp32 main path, fast exp, 1e-3 tol) ----------------
#define SK_PAD 68
#define SMEM_ATTN ((2048 + 64*SK_PAD + 32*577) * 4)

__global__ __launch_bounds__(256)
void attn_softmax_kernel(const float* __restrict__ Q, const float* __restrict__ Km,
                         float* __restrict__ attn_out)
{
    extern __shared__ float sm[];
    float* sQ = sm;
    float* sK = sm + 2048;
    float* sS = sm + 2048 + 64*SK_PAD;
    int bh = blockIdx.x;
    int qt = blockIdx.y;
    int tid = threadIdx.x;
    int tx = tid & 15, ty = tid >> 4;
    int q0 = qt * 32;
    size_t base = (size_t)bh * NTOK * HD;

    for (int l = tid; l < 512; l += 256) {
        int row = l >> 4, c4 = (l & 15) * 4;
        *(float4*)&sQ[row*64 + c4] = *(const float4*)&Q[base + (size_t)(q0+row)*HD + c4];
    }
    for (int kt = 0; kt < 9; kt++) {
        __syncthreads();
        for (int l = tid; l < 1024; l += 256) {
            int row = l >> 4, c4 = (l & 15) * 4;
            float4 v = *(const float4*)&Km[base + (size_t)(kt*64+row)*HD + c4];
            sK[(c4+0)*SK_PAD + row] = v.x;
            sK[(c4+1)*SK_PAD + row] = v.y;
            sK[(c4+2)*SK_PAD + row] = v.z;
            sK[(c4+3)*SK_PAD + row] = v.w;
        }
        __syncthreads();
        ull acc2[2][2] = {{0ULL,0ULL},{0ULL,0ULL}};
        #pragma unroll
        for (int d = 0; d < 64; d++) {
            float qa = sQ[(2*ty)*64 + d];
            float qb = sQ[(2*ty+1)*64 + d];
            ulonglong2 kq = *(const ulonglong2*)&sK[d*SK_PAD + tx*4];
            ull qad = dup2(qa), qbd = dup2(qb);
            acc2[0][0] = fma2(qad, kq.x, acc2[0][0]);
            acc2[0][1] = fma2(qad, kq.y, acc2[0][1]);
            acc2[1][0] = fma2(qbd, kq.x, acc2[1][0]);
            acc2[1][1] = fma2(qbd, kq.y, acc2[1][1]);
        }
        #pragma unroll
        for (int i2 = 0; i2 < 2; i2++) {
            float f0, f1, f2, f3;
            upk2(acc2[i2][0], f0, f1);
            upk2(acc2[i2][1], f2, f3);
            float* dst = &sS[(2*ty+i2)*577 + kt*64 + tx*4];
            dst[0] = f0 * 0.125f;
            dst[1] = f1 * 0.125f;
            dst[2] = f2 * 0.125f;
            dst[3] = f3 * 0.125f;
        }
    }
    __syncthreads();
    int warp = tid >> 5, lane = tid & 31;
    for (int r = warp*4; r < warp*4 + 4; r++) {
        float* srow = &sS[r*577];
        float m = -3.4e38f;
        for (int j = lane; j < NTOK; j += 32) m = fmaxf(m, srow[j]);
        #pragma unroll
        for (int o = 16; o; o >>= 1) m = fmaxf(m, __shfl_xor_sync(0xffffffffu, m, o));
        float s = 0.f;
        for (int j = lane; j < NTOK; j += 32) {
            float p = __expf(srow[j] - m);   // fast exp: attn output tol 1e-3
            srow[j] = p;
            s += p;
        }
        #pragma unroll
        for (int o = 16; o; o >>= 1) s += __shfl_xor_sync(0xffffffffu, s, o);
        float invs = 1.0f / s;
        size_t obase = ((size_t)bh*NTOK + q0 + r) * NTOK;
        for (int j = lane; j < NTOK; j += 32) attn_out[obase + j] = srow[j] * invs;
    }
}

// ---------------- PV -> tf32 tensor cores ----------------
__global__ __launch_bounds__(128)
void pv_tf32_kernel(const float* __restrict__ P, const float* __restrict__ V,
                    float* __restrict__ XA)
{
    __shared__ unsigned sP[64*36];
    __shared__ unsigned sVt[64*36];
    int bh = blockIdx.x, mt = blockIdx.y;
    int b = bh / HEADS, h = bh % HEADS;
    int tid = threadIdx.x;
    int warp = tid >> 5, lane = tid & 31;
    int g = lane >> 2, t = lane & 3;
    int m0 = mt * 64;
    size_t pbase = ((size_t)bh*NTOK + m0) * NTOK;
    size_t vbase = (size_t)bh * NTOK * HD;

    float acc[8][4];
    #pragma unroll
    for (int j = 0; j < 8; j++)
        #pragma unroll
        for (int r = 0; r < 4; r++) acc[j][r] = 0.f;

    for (int k0 = 0; k0 < NTOK; k0 += 32) {
        __syncthreads();
        {
            int prow = tid >> 1;
            int pc0 = (tid & 1) * 16;
            #pragma unroll
            for (int c4 = 0; c4 < 16; c4 += 4) {
                float4 pv4 = *(const float4*)&P[pbase + (size_t)prow*NTOK + k0 + pc0 + c4];
                sP[prow*36 + pc0 + c4 + 0] = f2tf(pv4.x);
                sP[prow*36 + pc0 + c4 + 1] = f2tf(pv4.y);
                sP[prow*36 + pc0 + c4 + 2] = f2tf(pv4.z);
                sP[prow*36 + pc0 + c4 + 3] = f2tf(pv4.w);
            }
        }
        {
            int vrow = tid >> 2;
            int vc0 = (tid & 3) * 16;
            #pragma unroll
            for (int c4 = 0; c4 < 16; c4 += 4) {
                float4 vv4 = *(const float4*)&V[vbase + (size_t)(k0+vrow)*HD + vc0 + c4];
                sVt[(vc0+c4+0)*36 + vrow] = f2tf(vv4.x);
                sVt[(vc0+c4+1)*36 + vrow] = f2tf(vv4.y);
                sVt[(vc0+c4+2)*36 + vrow] = f2tf(vv4.z);
                sVt[(vc0+c4+3)*36 + vrow] = f2tf(vv4.w);
            }
        }
        __syncthreads();
        #pragma unroll
        for (int ks = 0; ks < 32; ks += 8) {
            unsigned af[4];
            int row = warp*16 + g;
            af[0] = sP[row*36 + ks + t];
            af[1] = sP[(row+8)*36 + ks + t];
            af[2] = sP[row*36 + ks + t + 4];
            af[3] = sP[(row+8)*36 + ks + t + 4];
            #pragma unroll
            for (int j = 0; j < 8; j++) {
                unsigned bf0 = sVt[(j*8+g)*36 + ks + t];
                unsigned bf1 = sVt[(j*8+g)*36 + ks + t + 4];
                asm volatile(
                    "mma.sync.aligned.m16n8k8.row.col.f32.tf32.tf32.f32 "
                    "{%0,%1,%2,%3}, {%4,%5,%6,%7}, {%8,%9}, {%0,%1,%2,%3};"
                    : "+f"(acc[j][0]), "+f"(acc[j][1]), "+f"(acc[j][2]), "+f"(acc[j][3])
                    : "r"(af[0]), "r"(af[1]), "r"(af[2]), "r"(af[3]),
                      "r"(bf0), "r"(bf1));
            }
        }
    }
    int q0r = m0 + warp*16 + g;
    #pragma unroll
    for (int j = 0; j < 8; j++) {
        int c0 = j*8 + 2*t;
        float2 w0; w0.x = acc[j][0]; w0.y = acc[j][1];
        float2 w1; w1.x = acc[j][2]; w1.y = acc[j][3];
        *(float2*)&XA[((size_t)b*NTOK + q0r)*DIMC + h*HD + c0] = w0;
        *(float2*)&XA[((size_t)b*NTOK + q0r + 8)*DIMC + h*HD + c0] = w1;
    }
}

// ---------------- sort (exact) + intersection-flag swap -> final order ----------------
__global__ __launch_bounds__(256)
void sort_flag_kernel(const double* __restrict__ dscore,
                      const float* __restrict__ sv1, const float* __restrict__ sv2,
                      int* __restrict__ order)
{
    __shared__ double sv[256];
    __shared__ int    si[256];
    __shared__ int    flg[256];
    int b = blockIdx.x, grp = blockIdx.y, tid = threadIdx.x;
    int group = b*2 + grp;
    int gbase = b*2*LSN + grp*LSN;
    sv[tid] = dscore[gbase + tid];
    si[tid] = tid;
    __syncthreads();
    for (int k = 2; k <= 256; k <<= 1) {
        for (int j = k >> 1; j > 0; j >>= 1) {
            int ixj = tid ^ j;
            if (ixj > tid) {
                double va = sv[tid], vb = sv[ixj];
                int    ia = si[tid], ib = si[ixj];
                bool a_first = (va > vb) || (va == vb && ia < ib);
                bool desc = ((tid & k) == 0);
                bool doswap = desc ? (!a_first) : a_first;
                if (doswap) { sv[tid]=vb; sv[ixj]=va; si[tid]=ib; si[ixj]=ia; }
            }
            __syncthreads();
        }
    }
    int f = 0;
    if (tid < 255) {
        int u = si[tid], v = si[tid+1];
        float a1 = sv1[gbase + u], b1 = sv1[gbase + v];
        float a2 = sv2[gbase + u], b2 = sv2[gbase + v];
        bool inv1 = (b1 > a1) || (b1 == a1 && v < u);
        bool inv2 = (b2 > a2) || (b2 == a2 && v < u);
        f = (inv1 && inv2) ? 1 : 0;
    }
    flg[tid] = f;
    __syncthreads();
    int fprev = (tid > 0) ? flg[tid-1] : 0;
    int src = flg[tid] ? tid+1 : (fprev ? tid-1 : tid);
    order[group*LSN + tid] = si[src];
}

__global__ __launch_bounds__(256)
void emit_kernel(const int* __restrict__ order,
                 const int* __restrict__ gi_ps, const int* __restrict__ gi_s,
                 float* __restrict__ out, int* __restrict__ top_ps,
                 int* __restrict__ top_s)
{
    int b = blockIdx.x, grp = blockIdx.y, tid = threadIdx.x;
    int group = b*2 + grp;
    int idx = order[group*LSN + tid];
    const int* gi = grp ? gi_s : gi_ps;
    float gval = (float)gi[b*LSN + idx];
    if (tid < KEEPN) {
        out[(grp ? KEEP_S_OFF : KEEP_PS_OFF) + b*KEEPN + tid] = gval;
        (grp ? top_s : top_ps)[b*LSN + tid] = idx;
    } else {
        out[(grp ? REM_S_OFF : REM_PS_OFF) + b*REMN + (tid - KEEPN)] = gval;
    }
}

__global__ void idx_copy_kernel(const int* __restrict__ git, float* __restrict__ out)
{
    int i = blockIdx.x*256 + threadIdx.x;
    if (i < BATCH*LTN) out[GIT_OFF + i] = (float)git[i];
}

// ---------------- gather kept tokens + LN2 ----------------
__global__ __launch_bounds__(256)
void gather_ln2_kernel(const float* __restrict__ X1, const int* __restrict__ topps,
                       const int* __restrict__ tops, const float* __restrict__ w,
                       const float* __restrict__ bia, float* __restrict__ XN,
                       float* __restrict__ HN)
{
    __shared__ float sb[16];
    int i = blockIdx.x;
    int b = blockIdx.y;
    int src;
    if (i < LTN)              src = i;
    else if (i < LTN + KEEPN) src = LTN + topps[b*LSN + (i - LTN)];
    else                      src = LTN + LSN + tops[b*LSN + (i - LTN - KEEPN)];
    const float* xr = X1 + ((size_t)b*NTOK + src) * DIMC;
    size_t ob = ((size_t)b*NKEEP + i) * DIMC;
    int t = threadIdx.x;
    float v0 = xr[t], v1 = xr[t+256], v2 = xr[t+512];
    XN[ob+t] = v0; XN[ob+t+256] = v1; XN[ob+t+512] = v2;
    float s = v0+v1+v2;
    float q = v0*v0 + v1*v1 + v2*v2;
    int lane = t & 31, warp = t >> 5;
    #pragma unroll
    for (int o = 16; o; o >>= 1) {
        s += __shfl_xor_sync(0xffffffffu, s, o);
        q += __shfl_xor_sync(0xffffffffu, q, o);
    }
    if (lane == 0) { sb[warp] = s; sb[8+warp] = q; }
    __syncthreads();
    if (t < 32) {
        float s2 = (lane < 8) ? sb[lane] : 0.f;
        float q2 = (lane < 8) ? sb[8+lane] : 0.f;
        #pragma unroll
        for (int o = 4; o; o >>= 1) {
            s2 += __shfl_xor_sync(0xffffffffu, s2, o);
            q2 += __shfl_xor_sync(0xffffffffu, q2, o);
        }
        if (lane == 0) { sb[0] = s2; sb[1] = q2; }
    }
    __syncthreads();
    float mean = sb[0] * (1.f/768.f);
    float var  = sb[1] * (1.f/768.f) - mean*mean;
    float inv  = rsqrtf(var + 1e-5f);
    HN[ob+t]     = (v0-mean)*inv*w[t]     + bia[t];
    HN[ob+t+256] = (v1-mean)*inv*w[t+256] + bia[t+256];
    HN[ob+t+512] = (v2-mean)*inv*w[t+512] + bia[t+512];
}

// ---------------- stream/event resources (created once) ----
struct OverlapRes {
    cudaStream_t s1, s2;
    cudaEvent_t evLn, evQkv, evEmul, evEmit;
    OverlapRes() {
        cudaStreamCreateWithFlags(&s1, cudaStreamNonBlocking);
        cudaStreamCreateWithFlags(&s2, cudaStreamNonBlocking);
        cudaEventCreateWithFlags(&evLn,   cudaEventDisableTiming);
        cudaEventCreateWithFlags(&evQkv,  cudaEventDisableTiming);
        cudaEventCreateWithFlags(&evEmul, cudaEventDisableTiming);
        cudaEventCreateWithFlags(&evEmit, cudaEventDisableTiming);
    }
};
static OverlapRes& ores() { static OverlapRes r; return r; }

// ---------------- launch ----------------
extern "C" void kernel_launch(void* const* d_in, const int* in_sizes, int n_in,
                              void* d_out, int out_size)
{
    const float* x     = (const float*)d_in[0];
    const int*   git   = (const int*)  d_in[1];
    const int*   gips  = (const int*)  d_in[2];
    const int*   gis   = (const int*)  d_in[3];
    const float* ln1w  = (const float*)d_in[4];
    const float* ln1b  = (const float*)d_in[5];
    const float* qkvw  = (const float*)d_in[6];
    const float* qkvb  = (const float*)d_in[7];
    const float* projw = (const float*)d_in[8];
    const float* projb = (const float*)d_in[9];
    const float* ln2w  = (const float*)d_in[10];
    const float* ln2b  = (const float*)d_in[11];
    const float* fc1w  = (const float*)d_in[12];
    const float* fc1b  = (const float*)d_in[13];
    const float* fc2w  = (const float*)d_in[14];
    const float* fc2b  = (const float*)d_in[15];
    float* out = (float*)d_out;

    float *ph, *phlo, *pq, *pk, *pv, *pxa, *px1, *pxn, *phn, *pact;
    float *pkffh, *pkffl, *pqffh, *pqffl, *pspartf1, *pspartf2, *psv1, *psv2, *ppqf;
    double *pL, *pspartd, *pdscore, *ppdd;
    int *porder, *ptopps, *ptops;
    cudaGetSymbolAddress((void**)&ph,      g_h);
    cudaGetSymbolAddress((void**)&phlo,    g_hlo);
    cudaGetSymbolAddress((void**)&pq,      g_q);
    cudaGetSymbolAddress((void**)&pk,      g_k);
    cudaGetSymbolAddress((void**)&pv,      g_v);
    cudaGetSymbolAddress((void**)&pxa,     g_xa);
    cudaGetSymbolAddress((void**)&px1,     g_x1);
    cudaGetSymbolAddress((void**)&pxn,     g_xn);
    cudaGetSymbolAddress((void**)&phn,     g_hn);
    cudaGetSymbolAddress((void**)&pact,    g_act);
    cudaGetSymbolAddress((void**)&pkffh,   g_kffh);
    cudaGetSymbolAddress((void**)&pkffl,   g_kffl);
    cudaGetSymbolAddress((void**)&pqffh,   g_qffh);
    cudaGetSymbolAddress((void**)&pqffl,   g_qffl);
    cudaGetSymbolAddress((void**)&pL,      g_L);
    cudaGetSymbolAddress((void**)&ppqf,    g_pqf);
    cudaGetSymbolAddress((void**)&ppdd,    g_pdd);
    cudaGetSymbolAddress((void**)&pspartd, g_spartd);
    cudaGetSymbolAddress((void**)&pspartf1,g_spartf1);
    cudaGetSymbolAddress((void**)&pspartf2,g_spartf2);
    cudaGetSymbolAddress((void**)&pdscore, g_dscore);
    cudaGetSymbolAddress((void**)&psv1,    g_sv1);
    cudaGetSymbolAddress((void**)&psv2,    g_sv2);
    cudaGetSymbolAddress((void**)&porder,  g_order);
    cudaGetSymbolAddress((void**)&ptopps,  g_top_ps);
    cudaGetSymbolAddress((void**)&ptops,   g_top_s);

    float* attn_out = out + ATTN_OFF;

    cudaFuncSetAttribute(attn_softmax_kernel,
                         cudaFuncAttributeMaxDynamicSharedMemorySize, SMEM_ATTN);
    cudaFuncSetAttribute(ffqk_kernel,
                         cudaFuncAttributeMaxDynamicSharedMemorySize, SMEM_FFQK);

    OverlapRes& R = ores();

    // 1. LN1 (s0)
    ln_ff_kernel<<<M1, 256>>>(x, ln1w, ln1b, ph, phlo);
    cudaEventRecord(R.evLn, 0);

    // --- s1: score branch (ff path), depends only on LN1 ---
    cudaStreamWaitEvent(R.s1, R.evLn, 0);
    ffgemm_kernel<FFM_K><<<dim3(DIMC/64, M1/64), 256, 0, R.s1>>>(
        ph, phlo, qkvw, qkvb, pkffh, pkffl);
    ffgemm_kernel<FFM_Q><<<dim3(DIMC/64, (BATCH*LTN)/64), 256, 0, R.s1>>>(
        ph, phlo, qkvw, qkvb, pqffh, pqffl);
    ffqk_kernel<<<dim3(BATCH*HEADS, NTOK/64), 256, SMEM_FFQK, R.s1>>>(
        pqffh, pqffl, pkffh, pkffl, pL);
    score_soft_kernel<<<dim3(BATCH, HEADS, QCH), 256, 0, R.s1>>>(pL, ppqf, ppdd);
    score_qreduce_kernel<<<BATCH*HEADS, 512, 0, R.s1>>>(ppqf, ppdd, pspartd, pspartf2);

    // --- s0: sacred QK GEMM (N=1536; per-element bit-identical to R14) ---
    sgemm_nt<EPI_QKV><<<dim3(2*DIMC/128, M1/128), 256>>>(
        ph, qkvw, qkvb, nullptr, pq, pk, pv, nullptr, M1, 2*DIMC, DIMC);
    cudaEventRecord(R.evQkv, 0);

    // --- s2: V1 emulation (needs q/k only) ---
    cudaStreamWaitEvent(R.s2, R.evQkv, 0);
    score_emul4_kernel<<<dim3(BATCH, HEADS), 256, 0, R.s2>>>(pq, pk, pspartf1);
    cudaEventRecord(R.evEmul, R.s2);

    // s0: V via tf32 tensor cores (x-path only), then attention
    tf32gemm_kernel<TEPI_V><<<dim3(DIMC/128, M1/128), 256>>>(
        ph, qkvw + (size_t)(2*DIMC)*DIMC, qkvb + 2*DIMC, nullptr, pv, M1, DIMC, DIMC);
    attn_softmax_kernel<<<dim3(BATCH*HEADS, NTOK/32), 256, SMEM_ATTN>>>(pq, pk, attn_out);
    pv_tf32_kernel<<<dim3(BATCH*HEADS, NTOK/64), 128>>>(attn_out, pv, pxa);
    tf32gemm_kernel<TEPI_PROJ><<<dim3(DIMC/128, M1/128), 256>>>(
        pxa, projw, projb, x, px1, M1, DIMC, DIMC);

    // s1: reductions + sort + emit (joins s2's emul result)
    cudaStreamWaitEvent(R.s1, R.evEmul, 0);
    score_reduce_kernel<<<BATCH, 512, 0, R.s1>>>(pspartd, pspartf1, pspartf2,
                                                 pdscore, psv1, psv2);
    sort_flag_kernel<<<dim3(BATCH, 2), 256, 0, R.s1>>>(pdscore, psv1, psv2, porder);
    emit_kernel<<<dim3(BATCH, 2), 256, 0, R.s1>>>(porder, gips, gis, out, ptopps, ptops);
    idx_copy_kernel<<<(BATCH*LTN + 255)/256, 256, 0, R.s1>>>(git, out);
    cudaEventRecord(R.evEmit, R.s1);

    // s0: join with emit, then tail
    cudaStreamWaitEvent(0, R.evEmit, 0);
    gather_ln2_kernel<<<dim3(NKEEP, BATCH), 256>>>(px1, ptopps, ptops, ln2w, ln2b, pxn, phn);
    tf32gemm_kernel<TEPI_GELU><<<dim3(HID/128, M2/128), 256>>>(
        phn, fc1w, fc1b, nullptr, pact, M2, HID, DIMC);
    tf32gemm_kernel<TEPI_OUT><<<dim3(DIMC/128, M2/128), 256>>>(
        pact, fc2w, fc2b, pxn, out, M2, DIMC, HID);
}

// round 16
// speedup vs baseline: 1.6131x; 1.0500x over previous
#include <cuda_runtime.h>

// ---------------- problem constants ----------------
#define BATCH  32
#define NTOK   576
#define DIMC   768
#define HEADS  12
#define HD     64
#define LTN    64
#define LSN    256
#define KEEPN  180
#define REMN   76
#define NKEEP  424
#define HID    3072

#define M1     (BATCH*NTOK)   // 18432
#define M2     (BATCH*NKEEP)  // 13568
#define QCH    8              // q-chunks in score_soft / emul4

// output layout (flattened tuple, float32, reference order)
#define GIT_OFF      10420224
#define KEEP_PS_OFF  10422272
#define KEEP_S_OFF   10428032
#define REM_PS_OFF   10433792
#define REM_S_OFF    10436224
#define ATTN_OFF     10438656

// ---------------- device scratch ----------------
__device__ __align__(16) float g_h  [M1*DIMC];
__device__ __align__(16) float g_hlo[M1*DIMC];
__device__ __align__(16) float g_q  [M1*DIMC];
__device__ __align__(16) float g_k  [M1*DIMC];
__device__ __align__(16) float g_v  [M1*DIMC];
__device__ __align__(16) float g_xa [M1*DIMC];
__device__ __align__(16) float g_x1 [M1*DIMC];
__device__ __align__(16) float g_xn [M2*DIMC];
__device__ __align__(16) float g_hn [M2*DIMC];
__device__ __align__(16) float g_act[(size_t)M2*HID];
__device__ __align__(16) float g_kffh[M1*DIMC];
__device__ __align__(16) float g_kffl[M1*DIMC];
__device__ __align__(16) float g_qffh[BATCH*HEADS*LTN*HD];
__device__ __align__(16) float g_qffl[BATCH*HEADS*LTN*HD];
__device__ __align__(16) double g_L[(size_t)BATCH*HEADS*LTN*NTOK];
__device__ __align__(16) float  g_pqf [(size_t)BATCH*HEADS*LTN*512];  // per-q fp32 attn vals (V2)
__device__ __align__(16) float  g_pqf1[(size_t)BATCH*HEADS*LTN*512];  // per-q fp32 vals (V1)
__device__ __align__(16) double g_pdd[(size_t)BATCH*HEADS*QCH*512];   // per-chunk double partials
__device__ __align__(16) double g_spartd [(size_t)BATCH*HEADS*512];
__device__ __align__(16) float  g_spartf2[(size_t)BATCH*HEADS*512];
__device__ __align__(16) float  g_spartf1[(size_t)BATCH*HEADS*512];
__device__ __align__(16) double g_dscore[BATCH*2*LSN];
__device__ __align__(16) float  g_sv1[BATCH*2*LSN];
__device__ __align__(16) float  g_sv2[BATCH*2*LSN];
__device__ __align__(16) int    g_order[64*LSN];
__device__ __align__(16) int    g_top_ps[BATCH*LSN];
__device__ __align__(16) int    g_top_s [BATCH*LSN];

// ---------------- packed f32x2 helpers (per-lane IEEE rn) ----
typedef unsigned long long ull;
__device__ __forceinline__ ull pk2(float lo, float hi) {
    ull r;
    asm("mov.b64 %0, {%1, %2};" : "=l"(r)
        : "r"(__float_as_uint(lo)), "r"(__float_as_uint(hi)));
    return r;
}
__device__ __forceinline__ ull dup2(float v) { return pk2(v, v); }
__device__ __forceinline__ void upk2(ull v, float& lo, float& hi) {
    unsigned a, b;
    asm("mov.b64 {%0, %1}, %2;" : "=r"(a), "=r"(b) : "l"(v));
    lo = __uint_as_float(a); hi = __uint_as_float(b);
}
__device__ __forceinline__ ull fma2(ull a, ull b, ull c) {
    ull d; asm("fma.rn.f32x2 %0, %1, %2, %3;" : "=l"(d) : "l"(a), "l"(b), "l"(c));
    return d;
}
__device__ __forceinline__ ull add2(ull a, ull b) {
    ull d; asm("add.rn.f32x2 %0, %1, %2;" : "=l"(d) : "l"(a), "l"(b));
    return d;
}
__device__ __forceinline__ ull mul2(ull a, ull b) {
    ull d; asm("mul.rn.f32x2 %0, %1, %2;" : "=l"(d) : "l"(a), "l"(b));
    return d;
}
__device__ __forceinline__ ull neg2(ull a) {
    const ull m = 0x8000000080000000ULL;
    ull d; asm("xor.b64 %0, %1, %2;" : "=l"(d) : "l"(a), "l"(m));
    return d;
}
__device__ __forceinline__ unsigned f2tf(float f) {
    unsigned r; asm("cvt.rna.tf32.f32 %0, %1;" : "=r"(r) : "f"(f));
    return r;
}

// ---------------- ff (double-single) helpers ----------------
__device__ __forceinline__ void ts2(float a, float b, float& s, float& e) {
    s = a + b;
    float z = s - a;
    e = (a - (s - z)) + (b - z);
}
__device__ __forceinline__ void ffacc_f(float& h, float& l, float v) {
    float s, e; ts2(h, v, s, e); h = s; l += e;
}
__device__ __forceinline__ void ffacc_p(float& h, float& l, float a, float b) {
    float p = a * b;
    float e = fmaf(a, b, -p);
    float s, er; ts2(h, p, s, er);
    h = s; l += er + e;
}
__device__ __forceinline__ void ffadd(float& h, float& l, float bh2, float bl2) {
    float s, e; ts2(h, bh2, s, e);
    e += l + bl2;
    h = s + e;
    l = e - (h - s);
}

__device__ __forceinline__ float gelu_exact(float v) {
    return 0.5f * v * (1.0f + erff(v * 0.70710678118654752f));
}

// ---------------- LN1 in ff ----------------
__global__ __launch_bounds__(256)
void ln_ff_kernel(const float* __restrict__ X, const float* __restrict__ w,
                  const float* __restrict__ bia, float* __restrict__ Yh,
                  float* __restrict__ Yl)
{
    __shared__ float sh[8], slo[8], sqh[8], sql[8];
    __shared__ double sm_mean, sm_inv;
    int row = blockIdx.x;
    const float* xr = X + (size_t)row * DIMC;
    int t = threadIdx.x;
    float x0 = xr[t], x1 = xr[t+256], x2 = xr[t+512];
    float sH = 0.f, sL = 0.f, qH = 0.f, qL = 0.f;
    ffacc_f(sH, sL, x0); ffacc_f(sH, sL, x1); ffacc_f(sH, sL, x2);
    ffacc_p(qH, qL, x0, x0); ffacc_p(qH, qL, x1, x1); ffacc_p(qH, qL, x2, x2);
    int lane = t & 31, warp = t >> 5;
    #pragma unroll
    for (int o = 16; o; o >>= 1) {
        float oh = __shfl_xor_sync(0xffffffffu, sH, o);
        float ol = __shfl_xor_sync(0xffffffffu, sL, o);
        ffadd(sH, sL, oh, ol);
        oh = __shfl_xor_sync(0xffffffffu, qH, o);
        ol = __shfl_xor_sync(0xffffffffu, qL, o);
        ffadd(qH, qL, oh, ol);
    }
    if (lane == 0) { sh[warp]=sH; slo[warp]=sL; sqh[warp]=qH; sql[warp]=qL; }
    __syncthreads();
    if (t == 0) {
        double ms = 0.0, mq = 0.0;
        #pragma unroll
        for (int i = 0; i < 8; i++) {
            ms += (double)sh[i] + (double)slo[i];
            mq += (double)sqh[i] + (double)sql[i];
        }
        double mean = ms / 768.0;
        double var  = mq / 768.0 - mean*mean;
        sm_mean = mean;
        sm_inv  = 1.0 / sqrt(var + 1e-5);
    }
    __syncthreads();
    double mean = sm_mean, inv = sm_inv;
    float mh = (float)mean, ml = (float)(mean - (double)mh);
    float ih = (float)inv,  il = (float)(inv  - (double)ih);
    #pragma unroll
    for (int rep = 0; rep < 3; rep++) {
        int c = t + rep*256;
        float xv = (rep==0)?x0:((rep==1)?x1:x2);
        float wv = w[c], bv = bia[c];
        float th, tl; ts2(xv, -mh, th, tl); tl -= ml;
        float ph = th * ih;
        float pl = fmaf(th, ih, -ph);
        pl += th*il + tl*ih;
        float uh = ph * wv;
        float ul = fmaf(ph, wv, -uh);
        ul = fmaf(pl, wv, ul);
        float rh, rl; ts2(uh, bv, rh, rl); rl += ul;
        float oh = rh + rl;
        float ol = rl - (oh - rh);
        Yh[(size_t)row*DIMC + c] = oh;
        Yl[(size_t)row*DIMC + c] = ol;
    }
}

// ---------------- ff GEMM (packed f32x2, Kahan) ----------
#define FFM_K 0
#define FFM_Q 1

template<int MODE>
__global__ __launch_bounds__(256)
void ffgemm_kernel(const float* __restrict__ Ah, const float* __restrict__ Al,
                   const float* __restrict__ W, const float* __restrict__ bias,
                   float* __restrict__ Ch, float* __restrict__ Cl)
{
    __shared__ float Ash[16*68], Asl[16*68], Ws[16*68];
    const int tid = threadIdx.x;
    const int tx = tid & 15, ty = tid >> 4;
    const int m0 = blockIdx.y * 64;
    const int n0 = blockIdx.x * 64;
    const int wrow0 = (MODE == FFM_K) ? 768 : 0;
    const ull NEG1 = dup2(-1.0f);
    ull sS[4][2], cC[4][2];
    #pragma unroll
    for (int i = 0; i < 4; i++)
        #pragma unroll
        for (int j = 0; j < 2; j++) { sS[i][j] = 0ULL; cC[i][j] = 0ULL; }

    const int lrow = tid >> 2;
    const int lc4  = (tid & 3) * 4;
    int arow;
    if (MODE == FFM_Q) { int m = m0 + lrow; arow = (m >> 6)*NTOK + (m & 63); }
    else               arow = m0 + lrow;

    for (int k0 = 0; k0 < DIMC; k0 += 16) {
        float4 vh = *(const float4*)(Ah + (size_t)arow*DIMC + k0 + lc4);
        float4 vl = *(const float4*)(Al + (size_t)arow*DIMC + k0 + lc4);
        float4 vw = *(const float4*)(W + (size_t)(wrow0 + n0 + lrow)*DIMC + k0 + lc4);
        Ash[(lc4+0)*68+lrow]=vh.x; Ash[(lc4+1)*68+lrow]=vh.y; Ash[(lc4+2)*68+lrow]=vh.z; Ash[(lc4+3)*68+lrow]=vh.w;
        Asl[(lc4+0)*68+lrow]=vl.x; Asl[(lc4+1)*68+lrow]=vl.y; Asl[(lc4+2)*68+lrow]=vl.z; Asl[(lc4+3)*68+lrow]=vl.w;
        Ws [(lc4+0)*68+lrow]=vw.x; Ws [(lc4+1)*68+lrow]=vw.y; Ws [(lc4+2)*68+lrow]=vw.z; Ws [(lc4+3)*68+lrow]=vw.w;
        __syncthreads();
        #pragma unroll
        for (int kk = 0; kk < 16; kk++) {
            float4 ah4 = *(const float4*)&Ash[kk*68 + ty*4];
            float4 al4 = *(const float4*)&Asl[kk*68 + ty*4];
            ulonglong2 wq = *(const ulonglong2*)&Ws[kk*68 + tx*4];
            ull wp[2] = {wq.x, wq.y};
            float ahv[4] = {ah4.x, ah4.y, ah4.z, ah4.w};
            float alv[4] = {al4.x, al4.y, al4.z, al4.w};
            #pragma unroll
            for (int i = 0; i < 4; i++) {
                ull ahd = dup2(ahv[i]);
                ull ald = dup2(alv[i]);
                #pragma unroll
                for (int j2 = 0; j2 < 2; j2++) {
                    ull p2 = mul2(ahd, wp[j2]);
                    ull e2 = fma2(ahd, wp[j2], neg2(p2));
                    e2 = fma2(ald, wp[j2], e2);
                    ull y2 = fma2(cC[i][j2], NEG1, p2);
                    ull t2 = add2(sS[i][j2], y2);
                    ull d2 = fma2(sS[i][j2], NEG1, t2);
                    ull cn = fma2(y2, NEG1, d2);
                    cC[i][j2] = fma2(e2, NEG1, cn);
                    sS[i][j2] = t2;
                }
            }
        }
        __syncthreads();
    }

    #pragma unroll
    for (int i = 0; i < 4; i++) {
        float aH[4], aC[4];
        upk2(sS[i][0], aH[0], aH[1]); upk2(sS[i][1], aH[2], aH[3]);
        upk2(cC[i][0], aC[0], aC[1]); upk2(cC[i][1], aC[2], aC[3]);
        int m = m0 + ty*4 + i;
        float4 rh, rl;
        float* ph = &rh.x; float* pl = &rl.x;
        #pragma unroll
        for (int j = 0; j < 4; j++) {
            int col = n0 + tx*4 + j;
            float hi = aH[j], lo = -aC[j];
            float h2 = hi + lo;
            float l2 = lo - (h2 - hi);
            float bv = bias[wrow0 + col];
            float s, e; ts2(h2, bv, s, e); e += l2;
            float oh = s + e;
            float ol = e - (oh - s);
            ph[j] = oh; pl[j] = ol;
        }
        int col0 = n0 + tx*4;
        int head = col0 >> 6, d = col0 & 63;
        size_t off;
        if (MODE == FFM_Q) {
            int b = m >> 6, q = m & 63;
            off = (((size_t)(b*HEADS + head))*LTN + q)*HD + d;
        } else {
            int b = m / NTOK, n = m - (m/NTOK)*NTOK;
            off = (((size_t)(b*HEADS + head))*NTOK + n)*HD + d;
        }
        *(float4*)&Ch[off] = rh;
        *(float4*)&Cl[off] = rl;
    }
}

// ---------------- ff QK^T -> double logits (packed f32x2, Kahan) ----------------
#define SMEM_FFQK (4*64*68*4)

__global__ __launch_bounds__(256)
void ffqk_kernel(const float* __restrict__ Qh, const float* __restrict__ Ql,
                 const float* __restrict__ Kh, const float* __restrict__ Kl,
                 double* __restrict__ Lg)
{
    extern __shared__ float smf[];
    float* sQh = smf;
    float* sQl = smf + 64*68;
    float* sKh = smf + 2*64*68;
    float* sKl = smf + 3*64*68;
    int bh = blockIdx.x, nt = blockIdx.y;
    int tid = threadIdx.x;
    int tx = tid & 15, ty = tid >> 4;
    size_t qbase = (size_t)bh * LTN * HD;
    size_t kbase = ((size_t)bh * NTOK + nt*64) * HD;
    const ull NEG1 = dup2(-1.0f);

    for (int l = tid; l < 1024; l += 256) {
        int row = l >> 4, c4 = (l & 15) * 4;
        float4 a = *(const float4*)&Qh[qbase + (size_t)row*HD + c4];
        float4 b = *(const float4*)&Ql[qbase + (size_t)row*HD + c4];
        float4 c = *(const float4*)&Kh[kbase + (size_t)row*HD + c4];
        float4 d = *(const float4*)&Kl[kbase + (size_t)row*HD + c4];
        sQh[(c4+0)*68+row]=a.x; sQh[(c4+1)*68+row]=a.y; sQh[(c4+2)*68+row]=a.z; sQh[(c4+3)*68+row]=a.w;
        sQl[(c4+0)*68+row]=b.x; sQl[(c4+1)*68+row]=b.y; sQl[(c4+2)*68+row]=b.z; sQl[(c4+3)*68+row]=b.w;
        sKh[(c4+0)*68+row]=c.x; sKh[(c4+1)*68+row]=c.y; sKh[(c4+2)*68+row]=c.z; sKh[(c4+3)*68+row]=c.w;
        sKl[(c4+0)*68+row]=d.x; sKl[(c4+1)*68+row]=d.y; sKl[(c4+2)*68+row]=d.z; sKl[(c4+3)*68+row]=d.w;
    }
    __syncthreads();
    ull sS[4][2], cC[4][2];
    #pragma unroll
    for (int i = 0; i < 4; i++)
        #pragma unroll
        for (int j = 0; j < 2; j++) { sS[i][j]=0ULL; cC[i][j]=0ULL; }
    for (int d = 0; d < 64; d++) {
        float4 qh4 = *(const float4*)&sQh[d*68 + ty*4];
        float4 ql4 = *(const float4*)&sQl[d*68 + ty*4];
        ulonglong2 khq = *(const ulonglong2*)&sKh[d*68 + tx*4];
        ulonglong2 klq = *(const ulonglong2*)&sKl[d*68 + tx*4];
        ull khp[2] = {khq.x, khq.y};
        ull klp[2] = {klq.x, klq.y};
        float qh[4]={qh4.x,qh4.y,qh4.z,qh4.w}, ql[4]={ql4.x,ql4.y,ql4.z,ql4.w};
        #pragma unroll
        for (int i = 0; i < 4; i++) {
            ull qhd = dup2(qh[i]);
            ull qld = dup2(ql[i]);
            #pragma unroll
            for (int j2 = 0; j2 < 2; j2++) {
                ull p2 = mul2(qhd, khp[j2]);
                ull e2 = fma2(qhd, khp[j2], neg2(p2));
                e2 = fma2(qhd, klp[j2], e2);
                e2 = fma2(qld, khp[j2], e2);
                ull y2 = fma2(cC[i][j2], NEG1, p2);
                ull t2 = add2(sS[i][j2], y2);
                ull d2 = fma2(sS[i][j2], NEG1, t2);
                ull cn = fma2(y2, NEG1, d2);
                cC[i][j2] = fma2(e2, NEG1, cn);
                sS[i][j2] = t2;
            }
        }
    }
    #pragma unroll
    for (int i = 0; i < 4; i++) {
        float aH[4], aC[4];
        upk2(sS[i][0], aH[0], aH[1]); upk2(sS[i][1], aH[2], aH[3]);
        upk2(cC[i][0], aC[0], aC[1]); upk2(cC[i][1], aC[2], aC[3]);
        int q = ty*4 + i;
        #pragma unroll
        for (int j = 0; j < 4; j++) {
            int key = nt*64 + tx*4 + j;
            Lg[((size_t)bh*LTN + q)*NTOK + key] =
                ((double)aH[j] - (double)aC[j]) * 0.125;
        }
    }
}

// ---------------- exact double softmax per q-chunk ----------------
__global__ __launch_bounds__(256)
void score_soft_kernel(const double* __restrict__ Lg, float* __restrict__ pqf,
                       double* __restrict__ pdd)
{
    __shared__ double sl[NTOK];
    __shared__ double sred[16];
    int b = blockIdx.x, h = blockIdx.y, qc = blockIdx.z;
    int bh = b*HEADS + h;
    const double* L = Lg + (size_t)bh * LTN * NTOK;
    int t = threadIdx.x;
    int lane = t & 31, warp = t >> 5;
    double acc0 = 0.0, acc1 = 0.0;

    for (int qi = 0; qi < 8; qi++) {
        int q = qc*8 + qi;
        __syncthreads();
        const double* lq = L + (size_t)q * NTOK;
        double m = lq[t];
        m = fmax(m, lq[t+256]);
        if (t < 64) m = fmax(m, lq[t+512]);
        #pragma unroll
        for (int o = 16; o; o >>= 1) m = fmax(m, __shfl_xor_sync(0xffffffffu, m, o));
        if (lane == 0) sred[warp] = m;
        __syncthreads();
        if (t < 32) {
            double mm = (lane < 8) ? sred[lane] : -1e300;
            #pragma unroll
            for (int o = 4; o; o >>= 1) mm = fmax(mm, __shfl_xor_sync(0xffffffffu, mm, o));
            if (lane == 0) sred[0] = mm;
        }
        __syncthreads();
        m = sred[0];
        double sum = 0.0;
        {
            double p = exp(lq[t] - m);       sl[t] = p;       sum += p;
            p = exp(lq[t+256] - m);          sl[t+256] = p;   sum += p;
            if (t < 64) { p = exp(lq[t+512] - m); sl[t+512] = p; sum += p; }
        }
        #pragma unroll
        for (int o = 16; o; o >>= 1) sum += __shfl_xor_sync(0xffffffffu, sum, o);
        if (lane == 0) sred[8+warp] = sum;
        __syncthreads();
        if (t < 32) {
            double ss = (lane < 8) ? sred[8+lane] : 0.0;
            #pragma unroll
            for (int o = 4; o; o >>= 1) ss += __shfl_xor_sync(0xffffffffu, ss, o);
            if (lane == 0) sred[8] = ss;
        }
        __syncthreads();
        double inv = 1.0 / sred[8];
        double a0 = sl[64  + t] * inv;
        double a1 = sl[320 + t] * inv;
        acc0 += a0;
        acc1 += a1;
        size_t qoff = ((size_t)bh*LTN + q) * 512;
        pqf[qoff + t]       = (float)a0;
        pqf[qoff + 256 + t] = (float)a1;
    }
    size_t coff = ((size_t)bh*QCH + qc) * 512;
    pdd[coff + t]       = acc0;
    pdd[coff + 256 + t] = acc1;
}

// per-bh reduce: exact chunk partials + bit-identical sequential fp32 q-sums (V1, V2)
__global__ __launch_bounds__(512)
void score_qreduce_kernel(const float* __restrict__ pqf, const float* __restrict__ pqf1,
                          const double* __restrict__ pdd,
                          double* __restrict__ spartd, float* __restrict__ spartf1,
                          float* __restrict__ spartf2)
{
    int bh = blockIdx.x;
    int t = threadIdx.x;   // 0..511
    double d = 0.0;
    #pragma unroll
    for (int qc = 0; qc < QCH; qc++)
        d += pdd[((size_t)bh*QCH + qc)*512 + t];
    float f = 0.f, f1 = 0.f;
    for (int q = 0; q < LTN; q++) {
        f  += pqf [((size_t)bh*LTN + q)*512 + t];
        f1 += pqf1[((size_t)bh*LTN + q)*512 + t];
    }
    spartd[(size_t)bh*512 + t]  = d;
    spartf2[(size_t)bh*512 + t] = f / 64.0f;
    spartf1[(size_t)bh*512 + t] = f1 / 64.0f;
}

// ---------------- V1: fp32-emulated summands, q-chunked (values bit-identical) ----
__global__ __launch_bounds__(256)
void score_emul4_kernel(const float* __restrict__ Q, const float* __restrict__ K,
                        float* __restrict__ pqf1)
{
    __shared__ float sq[64];
    __shared__ float sl[NTOK];
    __shared__ float sred[16];
    int b = blockIdx.x, h = blockIdx.y, qc = blockIdx.z;
    int bh = b*HEADS + h;
    size_t base = (size_t)bh * NTOK * HD;
    int t = threadIdx.x;
    int lane = t & 31, warp = t >> 5;

    for (int qi = 0; qi < 8; qi++) {
        int q = qc*8 + qi;
        __syncthreads();
        if (t < 16)
            *(float4*)&sq[t*4] = *(const float4*)&Q[base + (size_t)q*HD + t*4];
        __syncthreads();
        #pragma unroll
        for (int rep = 0; rep < 3; rep++) {
            int j = t + rep*256;
            if (j < NTOK) {
                const float* kr = &K[base + (size_t)j*HD];
                float s0=0.f, s1=0.f, s2=0.f, s3=0.f;
                #pragma unroll
                for (int d = 0; d < 64; d += 4) {
                    s0 = fmaf(sq[d+0], kr[d+0], s0);
                    s1 = fmaf(sq[d+1], kr[d+1], s1);
                    s2 = fmaf(sq[d+2], kr[d+2], s2);
                    s3 = fmaf(sq[d+3], kr[d+3], s3);
                }
                sl[j] = ((s0+s1)+(s2+s3)) * 0.125f;
            }
        }
        __syncthreads();
        float m = -3.4e38f;
        m = fmaxf(m, sl[t]);
        m = fmaxf(m, sl[t+256]);
        if (t < 64) m = fmaxf(m, sl[t+512]);
        #pragma unroll
        for (int o = 16; o; o >>= 1) m = fmaxf(m, __shfl_xor_sync(0xffffffffu, m, o));
        if (lane == 0) sred[warp] = m;
        __syncthreads();
        if (t < 32) {
            float mm = (lane < 8) ? sred[lane] : -3.4e38f;
            #pragma unroll
            for (int o = 4; o; o >>= 1) mm = fmaxf(mm, __shfl_xor_sync(0xffffffffu, mm, o));
            if (lane == 0) sred[0] = mm;
        }
        __syncthreads();
        m = sred[0];
        #pragma unroll
        for (int rep = 0; rep < 3; rep++) {
            int j = t + rep*256;
            if (j < NTOK) {
                float d = sl[j] - m;
                sl[j] = (float)exp((double)d);
            }
        }
        __syncthreads();
        float ls = sl[t] + sl[t+256];
        if (t < 64) ls += sl[t+512];
        #pragma unroll
        for (int o = 16; o; o >>= 1) ls += __shfl_xor_sync(0xffffffffu, ls, o);
        if (lane == 0) sred[8+warp] = ls;
        __syncthreads();
        if (t < 32) {
            float ss = (lane < 8) ? sred[8+lane] : 0.f;
            #pragma unroll
            for (int o = 4; o; o >>= 1) ss += __shfl_xor_sync(0xffffffffu, ss, o);
            if (lane == 0) sred[8] = ss;
        }
        __syncthreads();
        float S = sred[8];
        size_t qoff = ((size_t)bh*LTN + q) * 512;
        pqf1[qoff + t]       = sl[64  + t] / S;   // identical value to R15's summand
        pqf1[qoff + 256 + t] = sl[320 + t] / S;
    }
}

// ---------------- reductions: exact(double), V1, V2 ----------------
__global__ __launch_bounds__(512)
void score_reduce_kernel(const double* __restrict__ spartd,
                         const float* __restrict__ spartf1,
                         const float* __restrict__ spartf2,
                         double* __restrict__ dscore,
                         float* __restrict__ sv1, float* __restrict__ sv2)
{
    int b = blockIdx.x;
    int j = threadIdx.x;
    double s = 0.0;
    float e1 = 0.f, e2 = 0.f;
    #pragma unroll
    for (int h = 0; h < HEADS; h++) {
        size_t o = (size_t)(b*HEADS + h)*512 + j;
        s  += spartd[o] / 64.0;
        e1 += spartf1[o];
        e2 += spartf2[o];
    }
    dscore[b*2*LSN + j] = s / 12.0;
    sv1[b*2*LSN + j] = e1 / 12.0f;
    sv2[b*2*LSN + j] = e2 / 12.0f;
}

// ---------------- sacred fp32 QK GEMM (packed f32x2, N=1536) ----
#define EPI_QKV  0

template<int EPI>
__global__ __launch_bounds__(256)
void sgemm_nt(const float* __restrict__ A, const float* __restrict__ Bw,
              const float* __restrict__ bias, const float* __restrict__ res,
              float* __restrict__ Cq, float* __restrict__ Ck, float* __restrict__ Cv,
              float* __restrict__ Cc, int M, int N, int K)
{
    __shared__ float As[16][132];
    __shared__ float Bs[16][132];
    const int tid = threadIdx.x;
    const int tx = tid & 15;
    const int ty = tid >> 4;
    const int m0 = blockIdx.y * 128;
    const int n0 = blockIdx.x * 128;
    ull acc2[8][4];
    #pragma unroll
    for (int i = 0; i < 8; i++)
        #pragma unroll
        for (int j = 0; j < 4; j++) acc2[i][j] = 0ULL;

    const int lrow = tid >> 2;
    const int lc4  = (tid & 3) * 4;

    for (int k0 = 0; k0 < K; k0 += 16) {
        #pragma unroll
        for (int half = 0; half < 2; half++) {
            int row = lrow + half*64;
            float4 va = *(const float4*)(A  + (size_t)(m0+row)*K + k0 + lc4);
            As[lc4+0][row]=va.x; As[lc4+1][row]=va.y; As[lc4+2][row]=va.z; As[lc4+3][row]=va.w;
            float4 vb = *(const float4*)(Bw + (size_t)(n0+row)*K + k0 + lc4);
            Bs[lc4+0][row]=vb.x; Bs[lc4+1][row]=vb.y; Bs[lc4+2][row]=vb.z; Bs[lc4+3][row]=vb.w;
        }
        __syncthreads();
        #pragma unroll
        for (int kk = 0; kk < 16; kk++) {
            float4 a0 = *(const float4*)&As[kk][ty*4];
            float4 a1 = *(const float4*)&As[kk][64 + ty*4];
            ulonglong2 b01 = *(const ulonglong2*)&Bs[kk][tx*4];
            ulonglong2 b23 = *(const ulonglong2*)&Bs[kk][64 + tx*4];
            ull bp0 = b01.x, bp1 = b01.y, bp2 = b23.x, bp3 = b23.y;
            float av[8] = {a0.x,a0.y,a0.z,a0.w,a1.x,a1.y,a1.z,a1.w};
            #pragma unroll
            for (int i = 0; i < 8; i++) {
                ull ad = dup2(av[i]);
                acc2[i][0] = fma2(ad, bp0, acc2[i][0]);
                acc2[i][1] = fma2(ad, bp1, acc2[i][1]);
                acc2[i][2] = fma2(ad, bp2, acc2[i][2]);
                acc2[i][3] = fma2(ad, bp3, acc2[i][3]);
            }
        }
        __syncthreads();
    }

    #pragma unroll
    for (int i = 0; i < 8; i++) {
        float accf[8];
        upk2(acc2[i][0], accf[0], accf[1]);
        upk2(acc2[i][1], accf[2], accf[3]);
        upk2(acc2[i][2], accf[4], accf[5]);
        upk2(acc2[i][3], accf[6], accf[7]);
        int rloc = (i < 4) ? (ty*4 + i) : (64 + ty*4 + i - 4);
        int row = m0 + rloc;
        #pragma unroll
        for (int jq = 0; jq < 2; jq++) {
            int col = n0 + jq*64 + tx*4;
            float4 r;
            r.x = accf[jq*4+0] + bias[col+0];
            r.y = accf[jq*4+1] + bias[col+1];
            r.z = accf[jq*4+2] + bias[col+2];
            r.w = accf[jq*4+3] + bias[col+3];
            int which = col / 768;
            int rem   = col - which*768;
            int head  = rem >> 6;
            int dd    = rem & 63;
            int bb    = row / NTOK;
            int nt    = row - bb*NTOK;
            float* targ = (which == 0) ? Cq : ((which == 1) ? Ck : Cv);
            *(float4*)&targ[(((size_t)(bb*HEADS + head))*NTOK + nt)*HD + dd] = r;
        }
    }
}

// ---------------- tf32 tensor-core GEMM ----
#define TEPI_PROJ 0
#define TEPI_GELU 1
#define TEPI_OUT  2
#define TEPI_V    3

template<int EPI>
__global__ __launch_bounds__(256)
void tf32gemm_kernel(const float* __restrict__ A, const float* __restrict__ Bw,
                     const float* __restrict__ bias, const float* __restrict__ res,
                     float* __restrict__ C, int M, int N, int K)
{
    __shared__ unsigned As[128*36];
    __shared__ unsigned Bs[128*36];
    const int tid = threadIdx.x;
    const int warp = tid >> 5, lane = tid & 31;
    const int wr = warp >> 2, wc = warp & 3;
    const int g = lane >> 2, t = lane & 3;
    const int m0 = blockIdx.y * 128, n0 = blockIdx.x * 128;
    const int lr = tid >> 3;
    const int lk = (tid & 7) * 4;

    float acc[4][4][4];
    #pragma unroll
    for (int i = 0; i < 4; i++)
        #pragma unroll
        for (int j = 0; j < 4; j++)
            #pragma unroll
            for (int r = 0; r < 4; r++) acc[i][j][r] = 0.f;

    float4 pa[4], pb[4];
    #pragma unroll
    for (int p = 0; p < 4; p++) {
        pa[p] = *(const float4*)(A  + (size_t)(m0 + p*32 + lr)*K + lk);
        pb[p] = *(const float4*)(Bw + (size_t)(n0 + p*32 + lr)*K + lk);
    }

    for (int k0 = 0; k0 < K; k0 += 32) {
        __syncthreads();
        #pragma unroll
        for (int p = 0; p < 4; p++) {
            int m = p*32 + lr;
            As[m*36+lk+0]=f2tf(pa[p].x); As[m*36+lk+1]=f2tf(pa[p].y);
            As[m*36+lk+2]=f2tf(pa[p].z); As[m*36+lk+3]=f2tf(pa[p].w);
            Bs[m*36+lk+0]=f2tf(pb[p].x); Bs[m*36+lk+1]=f2tf(pb[p].y);
            Bs[m*36+lk+2]=f2tf(pb[p].z); Bs[m*36+lk+3]=f2tf(pb[p].w);
        }
        __syncthreads();
        if (k0 + 32 < K) {
            #pragma unroll
            for (int p = 0; p < 4; p++) {
                pa[p] = *(const float4*)(A  + (size_t)(m0 + p*32 + lr)*K + k0 + 32 + lk);
                pb[p] = *(const float4*)(Bw + (size_t)(n0 + p*32 + lr)*K + k0 + 32 + lk);
            }
        }
        #pragma unroll
        for (int ks = 0; ks < 32; ks += 8) {
            unsigned af[4][4], bf[4][2];
            #pragma unroll
            for (int i = 0; i < 4; i++) {
                int row = wr*64 + i*16 + g;
                af[i][0] = As[row*36 + ks + t];
                af[i][1] = As[(row+8)*36 + ks + t];
                af[i][2] = As[row*36 + ks + t + 4];
                af[i][3] = As[(row+8)*36 + ks + t + 4];
            }
            #pragma unroll
            for (int j = 0; j < 4; j++) {
                int n = wc*32 + j*8 + g;
                bf[j][0] = Bs[n*36 + ks + t];
                bf[j][1] = Bs[n*36 + ks + t + 4];
            }
            #pragma unroll
            for (int i = 0; i < 4; i++)
                #pragma unroll
                for (int j = 0; j < 4; j++)
                    asm volatile(
                        "mma.sync.aligned.m16n8k8.row.col.f32.tf32.tf32.f32 "
                        "{%0,%1,%2,%3}, {%4,%5,%6,%7}, {%8,%9}, {%0,%1,%2,%3};"
                        : "+f"(acc[i][j][0]), "+f"(acc[i][j][1]),
                          "+f"(acc[i][j][2]), "+f"(acc[i][j][3])
                        : "r"(af[i][0]), "r"(af[i][1]), "r"(af[i][2]), "r"(af[i][3]),
                          "r"(bf[j][0]), "r"(bf[j][1]));
        }
    }

    #pragma unroll
    for (int i = 0; i < 4; i++) {
        int r0 = m0 + wr*64 + i*16 + g;
        #pragma unroll
        for (int j = 0; j < 4; j++) {
            int c0 = n0 + wc*32 + j*8 + 2*t;
            float b0v = bias[c0], b1v = bias[c0+1];
            float v00 = acc[i][j][0] + b0v, v01 = acc[i][j][1] + b1v;
            float v10 = acc[i][j][2] + b0v, v11 = acc[i][j][3] + b1v;
            if constexpr (EPI == TEPI_V) {
                int head = c0 >> 6, d = c0 & 63;
                int b0r = r0 / NTOK, n0r = r0 - b0r*NTOK;
                int b1r = (r0+8) / NTOK, n1r = (r0+8) - b1r*NTOK;
                float2 w0; w0.x = v00; w0.y = v01;
                float2 w1; w1.x = v10; w1.y = v11;
                *(float2*)&C[(((size_t)(b0r*HEADS + head))*NTOK + n0r)*HD + d] = w0;
                *(float2*)&C[(((size_t)(b1r*HEADS + head))*NTOK + n1r)*HD + d] = w1;
            } else {
                size_t o0 = (size_t)r0*N + c0;
                size_t o1 = (size_t)(r0+8)*N + c0;
                if constexpr (EPI == TEPI_GELU) {
                    v00 = gelu_exact(v00); v01 = gelu_exact(v01);
                    v10 = gelu_exact(v10); v11 = gelu_exact(v11);
                } else {
                    float2 r0v = *(const float2*)&res[o0];
                    float2 r1v = *(const float2*)&res[o1];
                    v00 += r0v.x; v01 += r0v.y;
                    v10 += r1v.x; v11 += r1v.y;
                }
                float2 w0; w0.x = v00; w0.y = v01;
                float2 w1; w1.x = v10; w1.y = v11;
                *(float2*)&C[o0] = w0;
                *(float2*)&C[o1] = w1;
            }
        }
    }
}

// ---------------- attention: tf32 MMA QK^T + fp32 softmax (1e-3 tol path) ----------
#define SMEM_ATTN2 ((32*68 + 64*68 + 32*577) * 4)

__global__ __launch_bounds__(256)
void attn_tf32_kernel(const float* __restrict__ Q, const float* __restrict__ Km,
                      float* __restrict__ attn_out)
{
    extern __shared__ unsigned smu[];
    unsigned* sQ = smu;                      // 32*68
    unsigned* sK = smu + 32*68;              // 64*68
    float* sS = (float*)(smu + 32*68 + 64*68);   // 32*577
    int bh = blockIdx.x, qt = blockIdx.y;
    int tid = threadIdx.x;
    int warp = tid >> 5, lane = tid & 31;
    int g = lane >> 2, t = lane & 3;
    int q0 = qt * 32;
    size_t base = (size_t)bh * NTOK * HD;

    for (int l = tid; l < 2048; l += 256) {
        int row = l >> 6, col = l & 63;
        sQ[row*68 + col] = f2tf(Q[base + (size_t)(q0+row)*HD + col]);
    }
    int qb = (warp & 1) * 16;
    int kb = (warp >> 1) * 16;
    for (int kt = 0; kt < 9; kt++) {
        __syncthreads();
        for (int l = tid; l < 4096; l += 256) {
            int row = l >> 6, col = l & 63;
            sK[row*68 + col] = f2tf(Km[base + (size_t)(kt*64+row)*HD + col]);
        }
        __syncthreads();
        unsigned af[8][4];
        #pragma unroll
        for (int ks = 0; ks < 8; ks++) {
            af[ks][0] = sQ[(qb+g)*68 + ks*8 + t];
            af[ks][1] = sQ[(qb+g+8)*68 + ks*8 + t];
            af[ks][2] = sQ[(qb+g)*68 + ks*8 + t + 4];
            af[ks][3] = sQ[(qb+g+8)*68 + ks*8 + t + 4];
        }
        #pragma unroll
        for (int jt = 0; jt < 2; jt++) {
            int kn = kb + jt*8;
            float acc[4] = {0.f, 0.f, 0.f, 0.f};
            #pragma unroll
            for (int ks = 0; ks < 8; ks++) {
                unsigned bf0 = sK[(kn+g)*68 + ks*8 + t];
                unsigned bf1 = sK[(kn+g)*68 + ks*8 + t + 4];
                asm volatile(
                    "mma.sync.aligned.m16n8k8.row.col.f32.tf32.tf32.f32 "
                    "{%0,%1,%2,%3}, {%4,%5,%6,%7}, {%8,%9}, {%0,%1,%2,%3};"
                    : "+f"(acc[0]), "+f"(acc[1]), "+f"(acc[2]), "+f"(acc[3])
                    : "r"(af[ks][0]), "r"(af[ks][1]), "r"(af[ks][2]), "r"(af[ks][3]),
                      "r"(bf0), "r"(bf1));
            }
            int col = kt*64 + kn + 2*t;
            sS[(qb+g)*577 + col]     = acc[0] * 0.125f;
            sS[(qb+g)*577 + col+1]   = acc[1] * 0.125f;
            sS[(qb+g+8)*577 + col]   = acc[2] * 0.125f;
            sS[(qb+g+8)*577 + col+1] = acc[3] * 0.125f;
        }
    }
    __syncthreads();
    for (int r = warp*4; r < warp*4 + 4; r++) {
        float* srow = &sS[r*577];
        float m = -3.4e38f;
        for (int j = lane; j < NTOK; j += 32) m = fmaxf(m, srow[j]);
        #pragma unroll
        for (int o = 16; o; o >>= 1) m = fmaxf(m, __shfl_xor_sync(0xffffffffu, m, o));
        float s = 0.f;
        for (int j = lane; j < NTOK; j += 32) {
            float p = __expf(srow[j] - m);
            srow[j] = p;
            s += p;
        }
        #pragma unroll
        for (int o = 16; o; o >>= 1) s += __shfl_xor_sync(0xffffffffu, s, o);
        float invs = 1.0f / s;
        size_t obase = ((size_t)bh*NTOK + q0 + r) * NTOK;
        for (int j = lane; j < NTOK; j += 32) attn_out[obase + j] = srow[j] * invs;
    }
}

// ---------------- PV -> tf32 tensor cores ----------------
__global__ __launch_bounds__(128)
void pv_tf32_kernel(const float* __restrict__ P, const float* __restrict__ V,
                    float* __restrict__ XA)
{
    __shared__ unsigned sP[64*36];
    __shared__ unsigned sVt[64*36];
    int bh = blockIdx.x, mt = blockIdx.y;
    int b = bh / HEADS, h = bh % HEADS;
    int tid = threadIdx.x;
    int warp = tid >> 5, lane = tid & 31;
    int g = lane >> 2, t = lane & 3;
    int m0 = mt * 64;
    size_t pbase = ((size_t)bh*NTOK + m0) * NTOK;
    size_t vbase = (size_t)bh * NTOK * HD;

    float acc[8][4];
    #pragma unroll
    for (int j = 0; j < 8; j++)
        #pragma unroll
        for (int r = 0; r < 4; r++) acc[j][r] = 0.f;

    for (int k0 = 0; k0 < NTOK; k0 += 32) {
        __syncthreads();
        {
            int prow = tid >> 1;
            int pc0 = (tid & 1) * 16;
            #pragma unroll
            for (int c4 = 0; c4 < 16; c4 += 4) {
                float4 pv4 = *(const float4*)&P[pbase + (size_t)prow*NTOK + k0 + pc0 + c4];
                sP[prow*36 + pc0 + c4 + 0] = f2tf(pv4.x);
                sP[prow*36 + pc0 + c4 + 1] = f2tf(pv4.y);
                sP[prow*36 + pc0 + c4 + 2] = f2tf(pv4.z);
                sP[prow*36 + pc0 + c4 + 3] = f2tf(pv4.w);
            }
        }
        {
            int vrow = tid >> 2;
            int vc0 = (tid & 3) * 16;
            #pragma unroll
            for (int c4 = 0; c4 < 16; c4 += 4) {
                float4 vv4 = *(const float4*)&V[vbase + (size_t)(k0+vrow)*HD + vc0 + c4];
                sVt[(vc0+c4+0)*36 + vrow] = f2tf(vv4.x);
                sVt[(vc0+c4+1)*36 + vrow] = f2tf(vv4.y);
                sVt[(vc0+c4+2)*36 + vrow] = f2tf(vv4.z);
                sVt[(vc0+c4+3)*36 + vrow] = f2tf(vv4.w);
            }
        }
        __syncthreads();
        #pragma unroll
        for (int ks = 0; ks < 32; ks += 8) {
            unsigned af[4];
            int row = warp*16 + g;
            af[0] = sP[row*36 + ks + t];
            af[1] = sP[(row+8)*36 + ks + t];
            af[2] = sP[row*36 + ks + t + 4];
            af[3] = sP[(row+8)*36 + ks + t + 4];
            #pragma unroll
            for (int j = 0; j < 8; j++) {
                unsigned bf0 = sVt[(j*8+g)*36 + ks + t];
                unsigned bf1 = sVt[(j*8+g)*36 + ks + t + 4];
                asm volatile(
                    "mma.sync.aligned.m16n8k8.row.col.f32.tf32.tf32.f32 "
                    "{%0,%1,%2,%3}, {%4,%5,%6,%7}, {%8,%9}, {%0,%1,%2,%3};"
                    : "+f"(acc[j][0]), "+f"(acc[j][1]), "+f"(acc[j][2]), "+f"(acc[j][3])
                    : "r"(af[0]), "r"(af[1]), "r"(af[2]), "r"(af[3]),
                      "r"(bf0), "r"(bf1));
            }
        }
    }
    int q0r = m0 + warp*16 + g;
    #pragma unroll
    for (int j = 0; j < 8; j++) {
        int c0 = j*8 + 2*t;
        float2 w0; w0.x = acc[j][0]; w0.y = acc[j][1];
        float2 w1; w1.x = acc[j][2]; w1.y = acc[j][3];
        *(float2*)&XA[((size_t)b*NTOK + q0r)*DIMC + h*HD + c0] = w0;
        *(float2*)&XA[((size_t)b*NTOK + q0r + 8)*DIMC + h*HD + c0] = w1;
    }
}

// ---------------- sort (exact) + intersection-flag swap -> final order ----------------
__global__ __launch_bounds__(256)
void sort_flag_kernel(const double* __restrict__ dscore,
                      const float* __restrict__ sv1, const float* __restrict__ sv2,
                      int* __restrict__ order)
{
    __shared__ double sv[256];
    __shared__ int    si[256];
    __shared__ int    flg[256];
    int b = blockIdx.x, grp = blockIdx.y, tid = threadIdx.x;
    int group = b*2 + grp;
    int gbase = b*2*LSN + grp*LSN;
    sv[tid] = dscore[gbase + tid];
    si[tid] = tid;
    __syncthreads();
    for (int k = 2; k <= 256; k <<= 1) {
        for (int j = k >> 1; j > 0; j >>= 1) {
            int ixj = tid ^ j;
            if (ixj > tid) {
                double va = sv[tid], vb = sv[ixj];
                int    ia = si[tid], ib = si[ixj];
                bool a_first = (va > vb) || (va == vb && ia < ib);
                bool desc = ((tid & k) == 0);
                bool doswap = desc ? (!a_first) : a_first;
                if (doswap) { sv[tid]=vb; sv[ixj]=va; si[tid]=ib; si[ixj]=ia; }
            }
            __syncthreads();
        }
    }
    int f = 0;
    if (tid < 255) {
        int u = si[tid], v = si[tid+1];
        float a1 = sv1[gbase + u], b1 = sv1[gbase + v];
        float a2 = sv2[gbase + u], b2 = sv2[gbase + v];
        bool inv1 = (b1 > a1) || (b1 == a1 && v < u);
        bool inv2 = (b2 > a2) || (b2 == a2 && v < u);
        f = (inv1 && inv2) ? 1 : 0;
    }
    flg[tid] = f;
    __syncthreads();
    int fprev = (tid > 0) ? flg[tid-1] : 0;
    int src = flg[tid] ? tid+1 : (fprev ? tid-1 : tid);
    order[group*LSN + tid] = si[src];
}

__global__ __launch_bounds__(256)
void emit_kernel(const int* __restrict__ order,
                 const int* __restrict__ gi_ps, const int* __restrict__ gi_s,
                 float* __restrict__ out, int* __restrict__ top_ps,
                 int* __restrict__ top_s)
{
    int b = blockIdx.x, grp = blockIdx.y, tid = threadIdx.x;
    int group = b*2 + grp;
    int idx = order[group*LSN + tid];
    const int* gi = grp ? gi_s : gi_ps;
    float gval = (float)gi[b*LSN + idx];
    if (tid < KEEPN) {
        out[(grp ? KEEP_S_OFF : KEEP_PS_OFF) + b*KEEPN + tid] = gval;
        (grp ? top_s : top_ps)[b*LSN + tid] = idx;
    } else {
        out[(grp ? REM_S_OFF : REM_PS_OFF) + b*REMN + (tid - KEEPN)] = gval;
    }
}

__global__ void idx_copy_kernel(const int* __restrict__ git, float* __restrict__ out)
{
    int i = blockIdx.x*256 + threadIdx.x;
    if (i < BATCH*LTN) out[GIT_OFF + i] = (float)git[i];
}

// ---------------- gather kept tokens + LN2 ----------------
__global__ __launch_bounds__(256)
void gather_ln2_kernel(const float* __restrict__ X1, const int* __restrict__ topps,
                       const int* __restrict__ tops, const float* __restrict__ w,
                       const float* __restrict__ bia, float* __restrict__ XN,
                       float* __restrict__ HN)
{
    __shared__ float sb[16];
    int i = blockIdx.x;
    int b = blockIdx.y;
    int src;
    if (i < LTN)              src = i;
    else if (i < LTN + KEEPN) src = LTN + topps[b*LSN + (i - LTN)];
    else                      src = LTN + LSN + tops[b*LSN + (i - LTN - KEEPN)];
    const float* xr = X1 + ((size_t)b*NTOK + src) * DIMC;
    size_t ob = ((size_t)b*NKEEP + i) * DIMC;
    int t = threadIdx.x;
    float v0 = xr[t], v1 = xr[t+256], v2 = xr[t+512];
    XN[ob+t] = v0; XN[ob+t+256] = v1; XN[ob+t+512] = v2;
    float s = v0+v1+v2;
    float q = v0*v0 + v1*v1 + v2*v2;
    int lane = t & 31, warp = t >> 5;
    #pragma unroll
    for (int o = 16; o; o >>= 1) {
        s += __shfl_xor_sync(0xffffffffu, s, o);
        q += __shfl_xor_sync(0xffffffffu, q, o);
    }
    if (lane == 0) { sb[warp] = s; sb[8+warp] = q; }
    __syncthreads();
    if (t < 32) {
        float s2 = (lane < 8) ? sb[lane] : 0.f;
        float q2 = (lane < 8) ? sb[8+lane] : 0.f;
        #pragma unroll
        for (int o = 4; o; o >>= 1) {
            s2 += __shfl_xor_sync(0xffffffffu, s2, o);
            q2 += __shfl_xor_sync(0xffffffffu, q2, o);
        }
        if (lane == 0) { sb[0] = s2; sb[1] = q2; }
    }
    __syncthreads();
    float mean = sb[0] * (1.f/768.f);
    float var  = sb[1] * (1.f/768.f) - mean*mean;
    float inv  = rsqrtf(var + 1e-5f);
    HN[ob+t]     = (v0-mean)*inv*w[t]     + bia[t];
    HN[ob+t+256] = (v1-mean)*inv*w[t+256] + bia[t+256];
    HN[ob+t+512] = (v2-mean)*inv*w[t+512] + bia[t+512];
}

// ---------------- stream/event resources (created once) ----
struct OverlapRes {
    cudaStream_t s1, s2;
    cudaEvent_t evLn, evQkv, evEmul, evEmit;
    OverlapRes() {
        cudaStreamCreateWithFlags(&s1, cudaStreamNonBlocking);
        cudaStreamCreateWithFlags(&s2, cudaStreamNonBlocking);
        cudaEventCreateWithFlags(&evLn,   cudaEventDisableTiming);
        cudaEventCreateWithFlags(&evQkv,  cudaEventDisableTiming);
        cudaEventCreateWithFlags(&evEmul, cudaEventDisableTiming);
        cudaEventCreateWithFlags(&evEmit, cudaEventDisableTiming);
    }
};
static OverlapRes& ores() { static OverlapRes r; return r; }

// ---------------- launch ----------------
extern "C" void kernel_launch(void* const* d_in, const int* in_sizes, int n_in,
                              void* d_out, int out_size)
{
    const float* x     = (const float*)d_in[0];
    const int*   git   = (const int*)  d_in[1];
    const int*   gips  = (const int*)  d_in[2];
    const int*   gis   = (const int*)  d_in[3];
    const float* ln1w  = (const float*)d_in[4];
    const float* ln1b  = (const float*)d_in[5];
    const float* qkvw  = (const float*)d_in[6];
    const float* qkvb  = (const float*)d_in[7];
    const float* projw = (const float*)d_in[8];
    const float* projb = (const float*)d_in[9];
    const float* ln2w  = (const float*)d_in[10];
    const float* ln2b  = (const float*)d_in[11];
    const float* fc1w  = (const float*)d_in[12];
    const float* fc1b  = (const float*)d_in[13];
    const float* fc2w  = (const float*)d_in[14];
    const float* fc2b  = (const float*)d_in[15];
    float* out = (float*)d_out;

    float *ph, *phlo, *pq, *pk, *pv, *pxa, *px1, *pxn, *phn, *pact;
    float *pkffh, *pkffl, *pqffh, *pqffl, *pspartf1, *pspartf2, *psv1, *psv2;
    float *ppqf, *ppqf1;
    double *pL, *pspartd, *pdscore, *ppdd;
    int *porder, *ptopps, *ptops;
    cudaGetSymbolAddress((void**)&ph,      g_h);
    cudaGetSymbolAddress((void**)&phlo,    g_hlo);
    cudaGetSymbolAddress((void**)&pq,      g_q);
    cudaGetSymbolAddress((void**)&pk,      g_k);
    cudaGetSymbolAddress((void**)&pv,      g_v);
    cudaGetSymbolAddress((void**)&pxa,     g_xa);
    cudaGetSymbolAddress((void**)&px1,     g_x1);
    cudaGetSymbolAddress((void**)&pxn,     g_xn);
    cudaGetSymbolAddress((void**)&phn,     g_hn);
    cudaGetSymbolAddress((void**)&pact,    g_act);
    cudaGetSymbolAddress((void**)&pkffh,   g_kffh);
    cudaGetSymbolAddress((void**)&pkffl,   g_kffl);
    cudaGetSymbolAddress((void**)&pqffh,   g_qffh);
    cudaGetSymbolAddress((void**)&pqffl,   g_qffl);
    cudaGetSymbolAddress((void**)&pL,      g_L);
    cudaGetSymbolAddress((void**)&ppqf,    g_pqf);
    cudaGetSymbolAddress((void**)&ppqf1,   g_pqf1);
    cudaGetSymbolAddress((void**)&ppdd,    g_pdd);
    cudaGetSymbolAddress((void**)&pspartd, g_spartd);
    cudaGetSymbolAddress((void**)&pspartf1,g_spartf1);
    cudaGetSymbolAddress((void**)&pspartf2,g_spartf2);
    cudaGetSymbolAddress((void**)&pdscore, g_dscore);
    cudaGetSymbolAddress((void**)&psv1,    g_sv1);
    cudaGetSymbolAddress((void**)&psv2,    g_sv2);
    cudaGetSymbolAddress((void**)&porder,  g_order);
    cudaGetSymbolAddress((void**)&ptopps,  g_top_ps);
    cudaGetSymbolAddress((void**)&ptops,   g_top_s);

    float* attn_out = out + ATTN_OFF;

    cudaFuncSetAttribute(attn_tf32_kernel,
                         cudaFuncAttributeMaxDynamicSharedMemorySize, SMEM_ATTN2);
    cudaFuncSetAttribute(ffqk_kernel,
                         cudaFuncAttributeMaxDynamicSharedMemorySize, SMEM_FFQK);

    OverlapRes& R = ores();

    // 1. LN1 (s0)
    ln_ff_kernel<<<M1, 256>>>(x, ln1w, ln1b, ph, phlo);
    cudaEventRecord(R.evLn, 0);

    // --- s1: score branch (ff path), depends only on LN1 ---
    cudaStreamWaitEvent(R.s1, R.evLn, 0);
    ffgemm_kernel<FFM_K><<<dim3(DIMC/64, M1/64), 256, 0, R.s1>>>(
        ph, phlo, qkvw, qkvb, pkffh, pkffl);
    ffgemm_kernel<FFM_Q><<<dim3(DIMC/64, (BATCH*LTN)/64), 256, 0, R.s1>>>(
        ph, phlo, qkvw, qkvb, pqffh, pqffl);
    ffqk_kernel<<<dim3(BATCH*HEADS, NTOK/64), 256, SMEM_FFQK, R.s1>>>(
        pqffh, pqffl, pkffh, pkffl, pL);
    score_soft_kernel<<<dim3(BATCH, HEADS, QCH), 256, 0, R.s1>>>(pL, ppqf, ppdd);

    // --- s0: sacred QK GEMM (N=1536; per-element bit-identical) ---
    sgemm_nt<EPI_QKV><<<dim3(2*DIMC/128, M1/128), 256>>>(
        ph, qkvw, qkvb, nullptr, pq, pk, pv, nullptr, M1, 2*DIMC, DIMC);
    cudaEventRecord(R.evQkv, 0);

    // --- s2: V1 emulation, q-chunked (values bit-identical) ---
    cudaStreamWaitEvent(R.s2, R.evQkv, 0);
    score_emul4_kernel<<<dim3(BATCH, HEADS, QCH), 256, 0, R.s2>>>(pq, pk, ppqf1);
    cudaEventRecord(R.evEmul, R.s2);

    // s0: V via tf32 tensor cores, then attention (tf32 QK^T)
    tf32gemm_kernel<TEPI_V><<<dim3(DIMC/128, M1/128), 256>>>(
        ph, qkvw + (size_t)(2*DIMC)*DIMC, qkvb + 2*DIMC, nullptr, pv, M1, DIMC, DIMC);
    attn_tf32_kernel<<<dim3(BATCH*HEADS, NTOK/32), 256, SMEM_ATTN2>>>(pq, pk, attn_out);
    pv_tf32_kernel<<<dim3(BATCH*HEADS, NTOK/64), 128>>>(attn_out, pv, pxa);
    tf32gemm_kernel<TEPI_PROJ><<<dim3(DIMC/128, M1/128), 256>>>(
        pxa, projw, projb, x, px1, M1, DIMC, DIMC);

    // s1: q-reduce (needs V1 summands from s2), reductions, sort, emit
    cudaStreamWaitEvent(R.s1, R.evEmul, 0);
    score_qreduce_kernel<<<BATCH*HEADS, 512, 0, R.s1>>>(
        ppqf, ppqf1, ppdd, pspartd, pspartf1, pspartf2);
    score_reduce_kernel<<<BATCH, 512, 0, R.s1>>>(pspartd, pspartf1, pspartf2,
                                                 pdscore, psv1, psv2);
    sort_flag_kernel<<<dim3(BATCH, 2), 256, 0, R.s1>>>(pdscore, psv1, psv2, porder);
    emit_kernel<<<dim3(BATCH, 2), 256, 0, R.s1>>>(porder, gips, gis, out, ptopps, ptops);
    idx_copy_kernel<<<(BATCH*LTN + 255)/256, 256, 0, R.s1>>>(git, out);
    cudaEventRecord(R.evEmit, R.s1);

    // s0: join with emit, then tail
    cudaStreamWaitEvent(0, R.evEmit, 0);
    gather_ln2_kernel<<<dim3(NKEEP, BATCH), 256>>>(px1, ptopps, ptops, ln2w, ln2b, pxn, phn);
    tf32gemm_kernel<TEPI_GELU><<<dim3(HID/128, M2/128), 256>>>(
        phn, fc1w, fc1b, nullptr, pact, M2, HID, DIMC);
    tf32gemm_kernel<TEPI_OUT><<<dim3(DIMC/128, M2/128), 256>>>(
        pact, fc2w, fc2b, pxn, out, M2, DIMC, HID);
}